// round 3
// baseline (speedup 1.0000x reference)
#include <cuda_runtime.h>
#include <math.h>

#define Bn 16
#define Tn 1024
#define Dn 512
#define Hn 8
#define HDn 64
#define COUTn 7
#define PREDn 96
#define Kn 8
#define LATENTn 2048
#define TP (Tn + PREDn)   /* 1120 */
#define T1 (Tn + 1)       /* 1025 */

#define OFF_RES3   0
#define OFF_LEVEL  (Bn*Tn*Dn)
#define OFF_GROWTH (OFF_LEVEL + Bn*Tn*COUTn)
#define OFF_SEASON (OFF_GROWTH + Bn*T1*Dn)

#define GSEG 16
#define GSEGLEN 64

// GEMM tiling
#define KTILE 32
#define APAD 36
#define BPAD 136
#define SM_A_WORDS (2*128*APAD)
#define SM_B_WORDS (2*KTILE*BPAD)
#define GEMM_SMEM ((SM_A_WORDS + SM_B_WORDS) * 4)

// ---------------- scratch ----------------
__device__ float RES1[Bn*Tn*Dn];
__device__ float VBUF[Bn*Tn*Dn];
__device__ float GBUF[Bn*T1*Dn];
__device__ float R2B [Bn*Tn*Dn];
__device__ float FBUF[Bn*Tn*LATENTn];
__device__ float FOUT[Bn*Tn*Dn];
__device__ float TK_RE[Bn*Kn*Dn];
__device__ float TK_IM[Bn*Kn*Dn];
__device__ int   TK_M [Bn*Kn*Dn];
__device__ float GS_G[Bn*Tn*COUTn];
__device__ float GS_S[Bn*Tn*COUTn];
__device__ float GZ    [Bn*Dn*GSEG];
__device__ float GCARRY[Bn*Dn*GSEG];
__device__ float LZ    [Bn*COUTn*GSEG];
__device__ float LCARRY[Bn*COUTn*GSEG];

// ---------------- FFT (radix-2 DIF, 1024-pt) + top-8 per series ----------------
__global__ __launch_bounds__(256) void fft_topk_kernel(const float* __restrict__ x) {
    __shared__ float2 data[4][1024];
    __shared__ float2 tw[512];
    int tid = threadIdx.x;
    int b   = blockIdx.x >> 7;
    int d0  = (blockIdx.x & 127) << 2;

    for (int k = tid; k < 512; k += 256) {
        float s, c;
        sincosf(-6.283185307179586f * (float)k / 1024.0f, &s, &c);
        tw[k] = make_float2(c, s);
    }
    const float* xb = x + (size_t)b * Tn * Dn;
    for (int i = tid; i < 4096; i += 256) {
        int t = i >> 2, j = i & 3;
        data[j][t] = make_float2(xb[(size_t)t*Dn + d0 + j], 0.f);
    }
    __syncthreads();

    int tmul = 1;
    for (int half = 512; half >= 1; half >>= 1, tmul <<= 1) {
        for (int i = tid; i < 2048; i += 256) {
            int s  = i >> 9;
            int bf = i & 511;
            int k  = bf & (half - 1);
            int pos = 2*bf - k;
            float2 u = data[s][pos], v = data[s][pos + half];
            data[s][pos] = make_float2(u.x + v.x, u.y + v.y);
            float2 t2 = make_float2(u.x - v.x, u.y - v.y);
            float2 w  = tw[k * tmul];
            data[s][pos + half] = make_float2(t2.x*w.x - t2.y*w.y,
                                              t2.x*w.y + t2.y*w.x);
        }
        __syncthreads();
    }

    int wid = tid >> 5, lane = tid & 31;
    if (wid < 4) {
        int s = wid;
        int chosen[8];
#pragma unroll
        for (int q = 0; q < 8; q++) chosen[q] = -1;
#pragma unroll
        for (int it = 0; it < 8; it++) {
            float bestm = -1.f; int bestf = 1 << 20;
            for (int f = 1 + lane; f <= 511; f += 32) {
                bool used = false;
#pragma unroll
                for (int q = 0; q < 8; q++) used |= (chosen[q] == f);
                if (used) continue;
                int j = (int)(__brev((unsigned)f) >> 22);
                float2 v = data[s][j];
                float m2 = v.x*v.x + v.y*v.y;
                if (m2 > bestm || (m2 == bestm && f < bestf)) { bestm = m2; bestf = f; }
            }
            for (int off = 16; off; off >>= 1) {
                float om = __shfl_xor_sync(0xffffffffu, bestm, off);
                int   of = __shfl_xor_sync(0xffffffffu, bestf, off);
                if (om > bestm || (om == bestm && of < bestf)) { bestm = om; bestf = of; }
            }
            chosen[it] = bestf;
        }
        if (lane == 0) {
            int d = d0 + s;
#pragma unroll
            for (int it = 0; it < 8; it++) {
                int f = chosen[it];
                int j = (int)(__brev((unsigned)f) >> 22);
                float2 v = data[s][j];
                size_t o = ((size_t)b * Kn + it) * Dn + d;
                TK_M[o] = f; TK_RE[o] = v.x; TK_IM[o] = v.y;
            }
        }
    }
}

// ---------------- season reconstruction + res1 ----------------
__global__ __launch_bounds__(256) void season_kernel(const float* __restrict__ res,
                                                     float* __restrict__ out) {
    __shared__ float ctab[1024];
    for (int j = threadIdx.x; j < 1024; j += 256)
        ctab[j] = cosf(6.283185307179586f / 1024.0f * (float)j);
    __syncthreads();

    int d  = blockIdx.x * 256 + threadIdx.x;
    int b  = blockIdx.y;
    int t0 = blockIdx.z * 112;

    int ms[8]; float re[8], im[8];
#pragma unroll
    for (int k = 0; k < 8; k++) {
        size_t o = ((size_t)b*Kn + k)*Dn + d;
        ms[k] = TK_M[o];
        re[k] = TK_RE[o] * (2.0f / (float)Tn);
        im[k] = TK_IM[o] * (2.0f / (float)Tn);
    }
    float*       seas = out + OFF_SEASON + (size_t)b*TP*Dn;
    const float* rb   = res + (size_t)b*Tn*Dn;
    float*       r1   = RES1 + (size_t)b*Tn*Dn;

    for (int t = t0; t < t0 + 112; t++) {
        float acc = 0.f;
#pragma unroll
        for (int k = 0; k < 8; k++) {
            int idx = (ms[k]*t) & 1023;
            acc += re[k]*ctab[idx] - im[k]*ctab[(idx + 768) & 1023];
        }
        seas[(size_t)t*Dn + d] = acc;
        if (t < Tn) r1[(size_t)t*Dn + d] = rb[(size_t)t*Dn + d] - acc;
    }
}

// ---------------- TF32 tensor-core GEMM, double-buffered ----------------
__device__ __forceinline__ unsigned f2tf32(float f) {
    unsigned u;
    asm("cvt.rna.tf32.f32 %0, %1;" : "=r"(u) : "f"(f));
    return u;
}

__global__ __launch_bounds__(256) void tf32gemm_kernel(const float* __restrict__ A,
                                                       const float* __restrict__ Bm,
                                                       float* __restrict__ C,
                                                       int M, int N, int K, int dogelu) {
    extern __shared__ unsigned smemraw[];
    unsigned (*As)[128][APAD]  = (unsigned(*)[128][APAD])smemraw;
    unsigned (*Bs)[KTILE][BPAD] = (unsigned(*)[KTILE][BPAD])(smemraw + SM_A_WORDS);

    int tid = threadIdx.x;
    int row0 = blockIdx.y * 128, col0 = blockIdx.x * 128;
    int wid = tid >> 5, lane = tid & 31;
    int wm = (wid & 1) * 64, wn = (wid >> 1) * 32;
    int g = lane >> 2, tg = lane & 3;
    int arow = tid >> 1, akq = (tid & 1) * 16;
    int bkrow = tid >> 3, bnq = (tid & 7) * 16;

    float acc[4][4][4];
#pragma unroll
    for (int i = 0; i < 4; i++)
#pragma unroll
        for (int j = 0; j < 4; j++)
#pragma unroll
            for (int q = 0; q < 4; q++) acc[i][j][q] = 0.f;

    const int NT = K / KTILE;
    float4 pa[4], pb[4];

    // prologue: load tile 0
    {
        int gr = row0 + arow;
        if (gr < M) {
            const float* ap = A + (size_t)gr*K + akq;
#pragma unroll
            for (int q = 0; q < 4; q++) pa[q] = *(const float4*)(ap + q*4);
        } else {
#pragma unroll
            for (int q = 0; q < 4; q++) pa[q] = make_float4(0.f,0.f,0.f,0.f);
        }
        const float* bp = Bm + (size_t)bkrow*N + col0 + bnq;
#pragma unroll
        for (int q = 0; q < 4; q++) pb[q] = *(const float4*)(bp + q*4);
    }
    {
        uint4* ar = (uint4*)&As[0][arow][akq];
        uint4* br = (uint4*)&Bs[0][bkrow][bnq];
#pragma unroll
        for (int q = 0; q < 4; q++) {
            ar[q] = make_uint4(f2tf32(pa[q].x), f2tf32(pa[q].y), f2tf32(pa[q].z), f2tf32(pa[q].w));
            br[q] = make_uint4(f2tf32(pb[q].x), f2tf32(pb[q].y), f2tf32(pb[q].z), f2tf32(pb[q].w));
        }
    }
    __syncthreads();

    for (int it = 0; it < NT; it++) {
        int buf = it & 1;
        if (it + 1 < NT) {
            int k0 = (it + 1) * KTILE;
            int gr = row0 + arow;
            if (gr < M) {
                const float* ap = A + (size_t)gr*K + k0 + akq;
#pragma unroll
                for (int q = 0; q < 4; q++) pa[q] = *(const float4*)(ap + q*4);
            } else {
#pragma unroll
                for (int q = 0; q < 4; q++) pa[q] = make_float4(0.f,0.f,0.f,0.f);
            }
            const float* bp = Bm + (size_t)(k0 + bkrow)*N + col0 + bnq;
#pragma unroll
            for (int q = 0; q < 4; q++) pb[q] = *(const float4*)(bp + q*4);
        }

#pragma unroll
        for (int kk = 0; kk < KTILE; kk += 8) {
            unsigned af[4][4], bf[4][2];
#pragma unroll
            for (int mt = 0; mt < 4; mt++) {
                int m = wm + mt*16 + g;
                af[mt][0] = As[buf][m  ][kk+tg];
                af[mt][1] = As[buf][m+8][kk+tg];
                af[mt][2] = As[buf][m  ][kk+tg+4];
                af[mt][3] = As[buf][m+8][kk+tg+4];
            }
#pragma unroll
            for (int nt = 0; nt < 4; nt++) {
                int n = wn + nt*8 + g;
                bf[nt][0] = Bs[buf][kk+tg  ][n];
                bf[nt][1] = Bs[buf][kk+tg+4][n];
            }
#pragma unroll
            for (int mt = 0; mt < 4; mt++)
#pragma unroll
                for (int nt = 0; nt < 4; nt++)
                    asm volatile(
                        "mma.sync.aligned.m16n8k8.row.col.f32.tf32.tf32.f32 "
                        "{%0,%1,%2,%3}, {%4,%5,%6,%7}, {%8,%9}, {%0,%1,%2,%3};"
                        : "+f"(acc[mt][nt][0]), "+f"(acc[mt][nt][1]),
                          "+f"(acc[mt][nt][2]), "+f"(acc[mt][nt][3])
                        : "r"(af[mt][0]), "r"(af[mt][1]), "r"(af[mt][2]), "r"(af[mt][3]),
                          "r"(bf[nt][0]), "r"(bf[nt][1]));
        }

        if (it + 1 < NT) {
            int nbuf = buf ^ 1;
            uint4* ar = (uint4*)&As[nbuf][arow][akq];
            uint4* br = (uint4*)&Bs[nbuf][bkrow][bnq];
#pragma unroll
            for (int q = 0; q < 4; q++) {
                ar[q] = make_uint4(f2tf32(pa[q].x), f2tf32(pa[q].y), f2tf32(pa[q].z), f2tf32(pa[q].w));
                br[q] = make_uint4(f2tf32(pb[q].x), f2tf32(pb[q].y), f2tf32(pb[q].z), f2tf32(pb[q].w));
            }
        }
        __syncthreads();
    }

#pragma unroll
    for (int mt = 0; mt < 4; mt++) {
#pragma unroll
        for (int nt = 0; nt < 4; nt++) {
            int r0 = row0 + wm + mt*16 + g;
            int c  = col0 + wn + nt*8 + 2*tg;
            float v[4];
#pragma unroll
            for (int q = 0; q < 4; q++) {
                float u = acc[mt][nt][q];
                if (dogelu) u = 0.5f*u*(1.0f + erff(u*0.70710678118654752f));
                v[q] = u;
            }
            if (r0 < M)     *(float2*)(C + (size_t)r0*N + c)     = make_float2(v[0], v[1]);
            if (r0 + 8 < M) *(float2*)(C + (size_t)(r0+8)*N + c) = make_float2(v[2], v[3]);
        }
    }
}

// ---------------- growth EMA: blocked parallel scan ----------------
__global__ __launch_bounds__(256) void growth_passA(const float* __restrict__ sw,
                                                    const float* __restrict__ z0) {
    int gid = blockIdx.x*256 + threadIdx.x;
    int c = gid & 511;
    int r = gid >> 9;
    int b = r & 15, seg = r >> 4;
    float w = 1.f/(1.f + expf(-sw[c >> 6]));
    int t0 = seg * GSEGLEN;
    const float* vp = VBUF + (size_t)b*Tn*Dn + c;
    float prev = (t0 == 0) ? z0[c] : vp[(size_t)(t0-1)*Dn];
    float z = 0.f;
#pragma unroll 4
    for (int l = 0; l < GSEGLEN; l++) {
        float v = vp[(size_t)(t0+l)*Dn];
        z = w*z + (v - prev);
        prev = v;
    }
    GZ[(size_t)((b<<9)+c)*GSEG + seg] = z;
}

__global__ __launch_bounds__(256) void growth_carry(const float* __restrict__ sw,
                                                    const float* __restrict__ v0) {
    int ch = blockIdx.x*256 + threadIdx.x;
    int c = ch & 511;
    float w = 1.f/(1.f + expf(-sw[c >> 6]));
    float w64 = 1.f;
    { float p = w; int e = GSEGLEN; while (e) { if (e & 1) w64 *= p; p *= p; e >>= 1; } }
    float y = v0[c];
    float omw = 1.f - w;
#pragma unroll
    for (int seg = 0; seg < GSEG; seg++) {
        GCARRY[(size_t)ch*GSEG + seg] = y;
        y = w64*y + omw*GZ[(size_t)ch*GSEG + seg];
    }
}

__global__ __launch_bounds__(256) void growth_passB(const float* __restrict__ sw,
                                                    const float* __restrict__ z0,
                                                    const float* __restrict__ v0) {
    int gid = blockIdx.x*256 + threadIdx.x;
    int c = gid & 511;
    int r = gid >> 9;
    int b = r & 15, seg = r >> 4;
    float w = 1.f/(1.f + expf(-sw[c >> 6]));
    float omw = 1.f - w;
    int t0 = seg * GSEGLEN;
    const float* vp = VBUF + (size_t)b*Tn*Dn + c;
    float*       gp = GBUF + (size_t)b*T1*Dn + c;
    float prev = (t0 == 0) ? z0[c] : vp[(size_t)(t0-1)*Dn];
    float y = GCARRY[(size_t)((b<<9)+c)*GSEG + seg];
    if (seg == 0) gp[0] = v0[c];
#pragma unroll 4
    for (int l = 0; l < GSEGLEN; l++) {
        float v = vp[(size_t)(t0+l)*Dn];
        y = w*y + omw*(v - prev);
        prev = v;
        gp[(size_t)(t0+l+1)*Dn] = y;
    }
}

// ---------------- layernorm helpers ----------------
__device__ __forceinline__ float block_reduce_sum(float v, float* red) {
    for (int o = 16; o; o >>= 1) v += __shfl_xor_sync(0xffffffffu, v, o);
    int wid = threadIdx.x >> 5;
    if ((threadIdx.x & 31) == 0) red[wid] = v;
    __syncthreads();
    if (threadIdx.x < 32) {
        float s = (threadIdx.x < 4) ? red[threadIdx.x] : 0.f;
        for (int o = 2; o; o >>= 1) s += __shfl_xor_sync(0xffffffffu, s, o);
        if (threadIdx.x == 0) red[0] = s;
    }
    __syncthreads();
    float r = red[0];
    __syncthreads();
    return r;
}

__global__ __launch_bounds__(128) void res2_kernel(const float* __restrict__ out_all,
                                                   const float* __restrict__ ng,
                                                   const float* __restrict__ nb) {
    __shared__ float red[32];
    int r = blockIdx.x;
    int b = r >> 10, t = r & 1023;
    const float* x1 = RES1 + (size_t)r*Dn;
    const float* gw = out_all + OFF_GROWTH + (size_t)(b*T1 + t + 1)*Dn;
    float vals[4]; float s = 0.f;
#pragma unroll
    for (int i = 0; i < 4; i++) {
        int d = threadIdx.x + i*128;
        vals[i] = x1[d] - gw[d];
        s += vals[i];
    }
    float mu = block_reduce_sum(s, red) * (1.0f/512.0f);
    float vs = 0.f;
#pragma unroll
    for (int i = 0; i < 4; i++) { float c = vals[i]-mu; vs += c*c; }
    float var = block_reduce_sum(vs, red) * (1.0f/512.0f);
    float inv = rsqrtf(var + 1e-5f);
#pragma unroll
    for (int i = 0; i < 4; i++) {
        int d = threadIdx.x + i*128;
        R2B[(size_t)r*Dn + d] = (vals[i]-mu)*inv*ng[d] + nb[d];
    }
}

__global__ __launch_bounds__(128) void res3_kernel(float* __restrict__ out_all,
                                                   const float* __restrict__ ng,
                                                   const float* __restrict__ nb) {
    __shared__ float red[32];
    int r = blockIdx.x;
    float vals[4]; float s = 0.f;
#pragma unroll
    for (int i = 0; i < 4; i++) {
        int d = threadIdx.x + i*128;
        vals[i] = R2B[(size_t)r*Dn + d] + FOUT[(size_t)r*Dn + d];
        s += vals[i];
    }
    float mu = block_reduce_sum(s, red) * (1.0f/512.0f);
    float vs = 0.f;
#pragma unroll
    for (int i = 0; i < 4; i++) { float c = vals[i]-mu; vs += c*c; }
    float var = block_reduce_sum(vs, red) * (1.0f/512.0f);
    float inv = rsqrtf(var + 1e-5f);
#pragma unroll
    for (int i = 0; i < 4; i++) {
        int d = threadIdx.x + i*128;
        out_all[OFF_RES3 + (size_t)r*Dn + d] = (vals[i]-mu)*inv*ng[d] + nb[d];
    }
}

// ---------------- level projections ----------------
__global__ __launch_bounds__(256) void levelproj_kernel(const float* __restrict__ out_all,
                                                        const float* __restrict__ gpw,
                                                        const float* __restrict__ spw) {
    int warp = (blockIdx.x*256 + threadIdx.x) >> 5;
    int lane = threadIdx.x & 31;
    if (warp >= Bn*Tn) return;
    int b = warp >> 10, t = warp & 1023;
    const float* gr = out_all + OFF_GROWTH + (size_t)(b*T1 + t)*Dn;
    const float* se = out_all + OFF_SEASON + (size_t)(b*TP + t)*Dn;
    float ag[7] = {}, as_[7] = {};
    for (int d = lane; d < 512; d += 32) {
        float g = gr[d], s = se[d];
#pragma unroll
        for (int c = 0; c < 7; c++) { ag[c] += g*gpw[d*7+c]; as_[c] += s*spw[d*7+c]; }
    }
#pragma unroll
    for (int c = 0; c < 7; c++) {
        for (int o = 16; o; o >>= 1) {
            ag[c]  += __shfl_xor_sync(0xffffffffu, ag[c],  o);
            as_[c] += __shfl_xor_sync(0xffffffffu, as_[c], o);
        }
    }
    if (lane == 0) {
#pragma unroll
        for (int c = 0; c < 7; c++) {
            GS_G[(size_t)warp*7 + c] = ag[c];
            GS_S[(size_t)warp*7 + c] = as_[c];
        }
    }
}

// ---------------- level EMA: blocked parallel scan ----------------
__global__ void level_passA(const float* __restrict__ level,
                            const float* __restrict__ lsw) {
    int gid = blockIdx.x*blockDim.x + threadIdx.x;
    if (gid >= Bn*COUTn*GSEG) return;
    int ch = gid % (Bn*COUTn), seg = gid / (Bn*COUTn);
    int b = ch / COUTn, c = ch % COUTn;
    float w = 1.f/(1.f + expf(-lsw[c]));
    float omw = 1.f - w;
    int t0 = seg * GSEGLEN;
    const float* lp = level + (size_t)b*Tn*COUTn + c;
    const float* gp = GS_G  + (size_t)b*Tn*COUTn + c;
    const float* sp = GS_S  + (size_t)b*Tn*COUTn + c;
    float z = 0.f;
    for (int l = 0; l < GSEGLEN; l++) {
        int t = t0 + l;
        float u = omw*(lp[t*COUTn] - sp[t*COUTn]) + w*gp[t*COUTn];
        z = w*z + u;
    }
    LZ[(size_t)ch*GSEG + seg] = z;
}

__global__ void level_carry(const float* __restrict__ lsw,
                            const float* __restrict__ lv0) {
    int ch = threadIdx.x;
    if (ch >= Bn*COUTn) return;
    int c = ch % COUTn;
    float w = 1.f/(1.f + expf(-lsw[c]));
    float w64 = 1.f;
    { float p = w; int e = GSEGLEN; while (e) { if (e & 1) w64 *= p; p *= p; e >>= 1; } }
    float y = lv0[c];
#pragma unroll
    for (int seg = 0; seg < GSEG; seg++) {
        LCARRY[(size_t)ch*GSEG + seg] = y;
        y = w64*y + LZ[(size_t)ch*GSEG + seg];
    }
}

__global__ void level_passB(const float* __restrict__ level,
                            const float* __restrict__ lsw,
                            float* __restrict__ out_all) {
    int gid = blockIdx.x*blockDim.x + threadIdx.x;
    if (gid >= Bn*COUTn*GSEG) return;
    int ch = gid % (Bn*COUTn), seg = gid / (Bn*COUTn);
    int b = ch / COUTn, c = ch % COUTn;
    float w = 1.f/(1.f + expf(-lsw[c]));
    float omw = 1.f - w;
    int t0 = seg * GSEGLEN;
    const float* lp = level + (size_t)b*Tn*COUTn + c;
    const float* gp = GS_G  + (size_t)b*Tn*COUTn + c;
    const float* sp = GS_S  + (size_t)b*Tn*COUTn + c;
    float* op = out_all + OFF_LEVEL + (size_t)b*Tn*COUTn + c;
    float y = LCARRY[(size_t)ch*GSEG + seg];
    for (int l = 0; l < GSEGLEN; l++) {
        int t = t0 + l;
        float u = omw*(lp[t*COUTn] - sp[t*COUTn]) + w*gp[t*COUTn];
        y = w*y + u;
        op[t*COUTn] = y;
    }
}

// ---------------- launch ----------------
extern "C" void kernel_launch(void* const* d_in, const int* in_sizes, int n_in,
                              void* d_out, int out_size) {
    const float* res      = (const float*)d_in[0];
    const float* level    = (const float*)d_in[1];
    const float* in_w     = (const float*)d_in[2];
    const float* out_w    = (const float*)d_in[3];
    const float* z0       = (const float*)d_in[4];
    const float* gsw      = (const float*)d_in[5];
    const float* gv0      = (const float*)d_in[6];
    const float* ff_w1    = (const float*)d_in[7];
    const float* ff_w2    = (const float*)d_in[8];
    const float* n1g      = (const float*)d_in[9];
    const float* n1b      = (const float*)d_in[10];
    const float* n2g      = (const float*)d_in[11];
    const float* n2b      = (const float*)d_in[12];
    const float* gpw      = (const float*)d_in[13];
    const float* spw      = (const float*)d_in[14];
    const float* lsw      = (const float*)d_in[15];
    const float* lv0      = (const float*)d_in[16];
    float* out = (float*)d_out;

    float *pRES1, *pVBUF, *pGBUF, *pR2, *pFBUF, *pFOUT;
    cudaGetSymbolAddress((void**)&pRES1, RES1);
    cudaGetSymbolAddress((void**)&pVBUF, VBUF);
    cudaGetSymbolAddress((void**)&pGBUF, GBUF);
    cudaGetSymbolAddress((void**)&pR2,   R2B);
    cudaGetSymbolAddress((void**)&pFBUF, FBUF);
    cudaGetSymbolAddress((void**)&pFOUT, FOUT);

    static int smem_set = 0;
    if (!smem_set) {
        cudaFuncSetAttribute(tf32gemm_kernel,
                             cudaFuncAttributeMaxDynamicSharedMemorySize, GEMM_SMEM);
        smem_set = 1;
    }

    // 1) FFT + top-k
    fft_topk_kernel<<<Bn*(Dn/4), 256>>>(res);
    // 2) season + res1
    season_kernel<<<dim3(2, Bn, 10), 256>>>(res, out);
    // 3) v = res1 @ in_proj_w
    tf32gemm_kernel<<<dim3(Dn/128, (Bn*Tn)/128), 256, GEMM_SMEM>>>(pRES1, in_w, pVBUF,
                                                                   Bn*Tn, Dn, Dn, 0);
    // 4) diffs + EMA (blocked scan)
    growth_passA<<<(Bn*Dn*GSEG)/256, 256>>>(gsw, z0);
    growth_carry<<<(Bn*Dn)/256, 256>>>(gsw, gv0);
    growth_passB<<<(Bn*Dn*GSEG)/256, 256>>>(gsw, z0, gv0);
    // 5) growth = GBUF @ out_proj_w -> d_out
    tf32gemm_kernel<<<dim3(Dn/128, (Bn*T1 + 127)/128), 256, GEMM_SMEM>>>(pGBUF, out_w,
                                                                         out + OFF_GROWTH,
                                                                         Bn*T1, Dn, Dn, 0);
    // 6) res2 = LN(res1 - growth[:,1:])
    res2_kernel<<<Bn*Tn, 128>>>(out, n1g, n1b);
    // 7) ffn1 = gelu(res2 @ ff_w1)
    tf32gemm_kernel<<<dim3(LATENTn/128, (Bn*Tn)/128), 256, GEMM_SMEM>>>(pR2, ff_w1, pFBUF,
                                                                        Bn*Tn, LATENTn, Dn, 1);
    // 8) ffn2 = ffn1 @ ff_w2
    tf32gemm_kernel<<<dim3(Dn/128, (Bn*Tn)/128), 256, GEMM_SMEM>>>(pFBUF, ff_w2, pFOUT,
                                                                   Bn*Tn, Dn, LATENTn, 0);
    // 9) res3 = LN(res2 + ffn2) -> d_out
    res3_kernel<<<Bn*Tn, 128>>>(out, n2g, n2b);
    // 10) level projections
    levelproj_kernel<<<(Bn*Tn*32)/256, 256>>>(out, gpw, spw);
    // 11) level EMA (blocked scan) -> d_out
    level_passA<<<(Bn*COUTn*GSEG + 255)/256, 256>>>(level, lsw);
    level_carry<<<1, 128>>>(lsw, lv0);
    level_passB<<<(Bn*COUTn*GSEG + 255)/256, 256>>>(level, lsw, out);
}

// round 4
// speedup vs baseline: 1.1113x; 1.1113x over previous
#include <cuda_runtime.h>
#include <math.h>

#define Bn 16
#define Tn 1024
#define Dn 512
#define Hn 8
#define HDn 64
#define COUTn 7
#define PREDn 96
#define Kn 8
#define LATENTn 2048
#define TP (Tn + PREDn)   /* 1120 */
#define T1 (Tn + 1)       /* 1025 */

#define OFF_RES3   0
#define OFF_LEVEL  (Bn*Tn*Dn)
#define OFF_GROWTH (OFF_LEVEL + Bn*Tn*COUTn)
#define OFF_SEASON (OFF_GROWTH + Bn*T1*Dn)

#define GSEG 16
#define GSEGLEN 64

// GEMM tiling
#define STAGES 3
#define BKf 32
#define APADf 36
#define BPADf 136
#define A_STAGE_FLOATS (128*APADf)
#define B_STAGE_FLOATS (BKf*BPADf)
#define GEMM_SMEM (STAGES*(A_STAGE_FLOATS + B_STAGE_FLOATS)*4)

// ---------------- scratch ----------------
__device__ float RES1[Bn*Tn*Dn];
__device__ float VBUF[Bn*Tn*Dn];
__device__ float GBUF[Bn*T1*Dn];
__device__ float R2B [Bn*Tn*Dn];
__device__ float FBUF[Bn*Tn*LATENTn];
__device__ float FOUT[Bn*Tn*Dn];
__device__ float TK_RE[Bn*Kn*Dn];
__device__ float TK_IM[Bn*Kn*Dn];
__device__ int   TK_M [Bn*Kn*Dn];
__device__ float GS_G[Bn*Tn*COUTn];
__device__ float GS_S[Bn*Tn*COUTn];
__device__ float GZ    [Bn*Dn*GSEG];
__device__ float GCARRY[Bn*Dn*GSEG];
__device__ float LZ    [Bn*COUTn*GSEG];
__device__ float LCARRY[Bn*COUTn*GSEG];

// ---------------- FFT (radix-2 DIF, 1024-pt) + top-8 per series ----------------
__global__ __launch_bounds__(256) void fft_topk_kernel(const float* __restrict__ x) {
    __shared__ float2 data[4][1024];
    __shared__ float2 tw[512];
    int tid = threadIdx.x;
    int b   = blockIdx.x >> 7;
    int d0  = (blockIdx.x & 127) << 2;

    for (int k = tid; k < 512; k += 256) {
        float s, c;
        sincosf(-6.283185307179586f * (float)k / 1024.0f, &s, &c);
        tw[k] = make_float2(c, s);
    }
    const float* xb = x + (size_t)b * Tn * Dn;
    for (int i = tid; i < 4096; i += 256) {
        int t = i >> 2, j = i & 3;
        data[j][t] = make_float2(xb[(size_t)t*Dn + d0 + j], 0.f);
    }
    __syncthreads();

    int tmul = 1;
    for (int half = 512; half >= 1; half >>= 1, tmul <<= 1) {
        for (int i = tid; i < 2048; i += 256) {
            int s  = i >> 9;
            int bf = i & 511;
            int k  = bf & (half - 1);
            int pos = 2*bf - k;
            float2 u = data[s][pos], v = data[s][pos + half];
            data[s][pos] = make_float2(u.x + v.x, u.y + v.y);
            float2 t2 = make_float2(u.x - v.x, u.y - v.y);
            float2 w  = tw[k * tmul];
            data[s][pos + half] = make_float2(t2.x*w.x - t2.y*w.y,
                                              t2.x*w.y + t2.y*w.x);
        }
        __syncthreads();
    }

    int wid = tid >> 5, lane = tid & 31;
    if (wid < 4) {
        int s = wid;
        int chosen[8];
#pragma unroll
        for (int q = 0; q < 8; q++) chosen[q] = -1;
#pragma unroll
        for (int it = 0; it < 8; it++) {
            float bestm = -1.f; int bestf = 1 << 20;
            for (int f = 1 + lane; f <= 511; f += 32) {
                bool used = false;
#pragma unroll
                for (int q = 0; q < 8; q++) used |= (chosen[q] == f);
                if (used) continue;
                int j = (int)(__brev((unsigned)f) >> 22);
                float2 v = data[s][j];
                float m2 = v.x*v.x + v.y*v.y;
                if (m2 > bestm || (m2 == bestm && f < bestf)) { bestm = m2; bestf = f; }
            }
            for (int off = 16; off; off >>= 1) {
                float om = __shfl_xor_sync(0xffffffffu, bestm, off);
                int   of = __shfl_xor_sync(0xffffffffu, bestf, off);
                if (om > bestm || (om == bestm && of < bestf)) { bestm = om; bestf = of; }
            }
            chosen[it] = bestf;
        }
        if (lane == 0) {
            int d = d0 + s;
#pragma unroll
            for (int it = 0; it < 8; it++) {
                int f = chosen[it];
                int j = (int)(__brev((unsigned)f) >> 22);
                float2 v = data[s][j];
                size_t o = ((size_t)b * Kn + it) * Dn + d;
                TK_M[o] = f; TK_RE[o] = v.x; TK_IM[o] = v.y;
            }
        }
    }
}

// ---------------- season reconstruction + res1 ----------------
__global__ __launch_bounds__(256) void season_kernel(const float* __restrict__ res,
                                                     float* __restrict__ out) {
    __shared__ float ctab[1024];
    for (int j = threadIdx.x; j < 1024; j += 256)
        ctab[j] = cosf(6.283185307179586f / 1024.0f * (float)j);
    __syncthreads();

    int d  = blockIdx.x * 256 + threadIdx.x;
    int b  = blockIdx.y;
    int t0 = blockIdx.z * 112;

    int ms[8]; float re[8], im[8];
#pragma unroll
    for (int k = 0; k < 8; k++) {
        size_t o = ((size_t)b*Kn + k)*Dn + d;
        ms[k] = TK_M[o];
        re[k] = TK_RE[o] * (2.0f / (float)Tn);
        im[k] = TK_IM[o] * (2.0f / (float)Tn);
    }
    float*       seas = out + OFF_SEASON + (size_t)b*TP*Dn;
    const float* rb   = res + (size_t)b*Tn*Dn;
    float*       r1   = RES1 + (size_t)b*Tn*Dn;

    for (int t = t0; t < t0 + 112; t++) {
        float acc = 0.f;
#pragma unroll
        for (int k = 0; k < 8; k++) {
            int idx = (ms[k]*t) & 1023;
            acc += re[k]*ctab[idx] - im[k]*ctab[(idx + 768) & 1023];
        }
        seas[(size_t)t*Dn + d] = acc;
        if (t < Tn) r1[(size_t)t*Dn + d] = rb[(size_t)t*Dn + d] - acc;
    }
}

// ---------------- TF32 tensor-core GEMM, cp.async 3-stage pipeline ----------------
__device__ __forceinline__ unsigned f2tf32(float f) {
    unsigned u;
    asm("cvt.rna.tf32.f32 %0, %1;" : "=r"(u) : "f"(f));
    return u;
}

__device__ __forceinline__ void cp_async16(unsigned saddr, const void* gptr, bool valid) {
    int sz = valid ? 16 : 0;
    asm volatile("cp.async.cg.shared.global [%0], [%1], 16, %2;\n"
                 :: "r"(saddr), "l"(gptr), "r"(sz));
}

__global__ __launch_bounds__(256) void tf32gemm_kernel(const float* __restrict__ A,
                                                       const float* __restrict__ Bm,
                                                       float* __restrict__ C,
                                                       int M, int N, int K, int dogelu) {
    extern __shared__ float sm[];
    float* Asf = sm;                               // [STAGES][128][APADf]
    float* Bsf = sm + STAGES * A_STAGE_FLOATS;     // [STAGES][BKf][BPADf]
    unsigned As_base = (unsigned)__cvta_generic_to_shared(Asf);
    unsigned Bs_base = (unsigned)__cvta_generic_to_shared(Bsf);

    int tid = threadIdx.x;
    int row0 = blockIdx.y * 128, col0 = blockIdx.x * 128;
    int wid = tid >> 5, lane = tid & 31;
    int wm = (wid & 1) * 64, wn = (wid >> 1) * 32;
    int g = lane >> 2, tg = lane & 3;

    // copy indices: A 128x32 floats = 1024 16B-chunks; B 32x128 likewise
    int arow = tid >> 1, ac0 = (tid & 1) * 4;      // chunk-in-row base
    int brow = tid >> 3, bc0 = (tid & 7) * 4;
    int agr = row0 + arow;
    bool avalid = (agr < M);
    const float* agp = A + (size_t)agr * K + ac0 * 4;
    const float* bgp = Bm + (size_t)brow * N + col0 + bc0 * 4;

    float acc[4][4][4];
#pragma unroll
    for (int i = 0; i < 4; i++)
#pragma unroll
        for (int j = 0; j < 4; j++)
#pragma unroll
            for (int q = 0; q < 4; q++) acc[i][j][q] = 0.f;

    const int NT = K / BKf;

    // prologue: issue stages 0,1
#pragma unroll
    for (int s = 0; s < 2; s++) {
        unsigned adst = As_base + (s*A_STAGE_FLOATS + arow*APADf + ac0*4) * 4;
        unsigned bdst = Bs_base + (s*B_STAGE_FLOATS + brow*BPADf + bc0*4) * 4;
        const float* ag = agp + s * BKf;
        const float* bg = bgp + (size_t)s * BKf * N;
#pragma unroll
        for (int q = 0; q < 4; q++) {
            cp_async16(adst + q*16, ag + q*4, avalid);
            cp_async16(bdst + q*16, bg + q*4, true);
        }
        asm volatile("cp.async.commit_group;\n");
    }

    for (int it = 0; it < NT; it++) {
        if (it < NT - 1) asm volatile("cp.async.wait_group 1;\n");
        else             asm volatile("cp.async.wait_group 0;\n");
        __syncthreads();

        // issue stage it+2
        if (it + 2 < NT) {
            int s = (it + 2) % STAGES;
            unsigned adst = As_base + (s*A_STAGE_FLOATS + arow*APADf + ac0*4) * 4;
            unsigned bdst = Bs_base + (s*B_STAGE_FLOATS + brow*BPADf + bc0*4) * 4;
            const float* ag = agp + (it + 2) * BKf;
            const float* bg = bgp + (size_t)(it + 2) * BKf * N;
#pragma unroll
            for (int q = 0; q < 4; q++) {
                cp_async16(adst + q*16, ag + q*4, avalid);
                cp_async16(bdst + q*16, bg + q*4, true);
            }
            asm volatile("cp.async.commit_group;\n");
        }

        const float* Abuf = Asf + (it % STAGES) * A_STAGE_FLOATS;
        const float* Bbuf = Bsf + (it % STAGES) * B_STAGE_FLOATS;

#pragma unroll
        for (int kk = 0; kk < BKf; kk += 8) {
            unsigned af[4][4], bf[4][2];
#pragma unroll
            for (int mt = 0; mt < 4; mt++) {
                int m = wm + mt*16 + g;
                af[mt][0] = f2tf32(Abuf[(m  )*APADf + kk + tg    ]);
                af[mt][1] = f2tf32(Abuf[(m+8)*APADf + kk + tg    ]);
                af[mt][2] = f2tf32(Abuf[(m  )*APADf + kk + tg + 4]);
                af[mt][3] = f2tf32(Abuf[(m+8)*APADf + kk + tg + 4]);
            }
#pragma unroll
            for (int nt = 0; nt < 4; nt++) {
                int n = wn + nt*8 + g;
                bf[nt][0] = f2tf32(Bbuf[(kk+tg  )*BPADf + n]);
                bf[nt][1] = f2tf32(Bbuf[(kk+tg+4)*BPADf + n]);
            }
#pragma unroll
            for (int mt = 0; mt < 4; mt++)
#pragma unroll
                for (int nt = 0; nt < 4; nt++)
                    asm volatile(
                        "mma.sync.aligned.m16n8k8.row.col.f32.tf32.tf32.f32 "
                        "{%0,%1,%2,%3}, {%4,%5,%6,%7}, {%8,%9}, {%0,%1,%2,%3};"
                        : "+f"(acc[mt][nt][0]), "+f"(acc[mt][nt][1]),
                          "+f"(acc[mt][nt][2]), "+f"(acc[mt][nt][3])
                        : "r"(af[mt][0]), "r"(af[mt][1]), "r"(af[mt][2]), "r"(af[mt][3]),
                          "r"(bf[nt][0]), "r"(bf[nt][1]));
        }
        __syncthreads();
    }

#pragma unroll
    for (int mt = 0; mt < 4; mt++) {
#pragma unroll
        for (int nt = 0; nt < 4; nt++) {
            int r0 = row0 + wm + mt*16 + g;
            int c  = col0 + wn + nt*8 + 2*tg;
            float v[4];
#pragma unroll
            for (int q = 0; q < 4; q++) {
                float u = acc[mt][nt][q];
                if (dogelu) u = 0.5f*u*(1.0f + erff(u*0.70710678118654752f));
                v[q] = u;
            }
            if (r0 < M)     *(float2*)(C + (size_t)r0*N + c)     = make_float2(v[0], v[1]);
            if (r0 + 8 < M) *(float2*)(C + (size_t)(r0+8)*N + c) = make_float2(v[2], v[3]);
        }
    }
}

// ---------------- growth EMA: blocked parallel scan ----------------
__global__ __launch_bounds__(256) void growth_passA(const float* __restrict__ sw,
                                                    const float* __restrict__ z0) {
    int gid = blockIdx.x*256 + threadIdx.x;
    int c = gid & 511;
    int r = gid >> 9;
    int b = r & 15, seg = r >> 4;
    float w = 1.f/(1.f + expf(-sw[c >> 6]));
    int t0 = seg * GSEGLEN;
    const float* vp = VBUF + (size_t)b*Tn*Dn + c;
    float prev = (t0 == 0) ? z0[c] : vp[(size_t)(t0-1)*Dn];
    float z = 0.f;
#pragma unroll 4
    for (int l = 0; l < GSEGLEN; l++) {
        float v = vp[(size_t)(t0+l)*Dn];
        z = w*z + (v - prev);
        prev = v;
    }
    GZ[(size_t)((b<<9)+c)*GSEG + seg] = z;
}

__global__ __launch_bounds__(256) void growth_carry(const float* __restrict__ sw,
                                                    const float* __restrict__ v0) {
    int ch = blockIdx.x*256 + threadIdx.x;
    int c = ch & 511;
    float w = 1.f/(1.f + expf(-sw[c >> 6]));
    float w64 = 1.f;
    { float p = w; int e = GSEGLEN; while (e) { if (e & 1) w64 *= p; p *= p; e >>= 1; } }
    float y = v0[c];
    float omw = 1.f - w;
#pragma unroll
    for (int seg = 0; seg < GSEG; seg++) {
        GCARRY[(size_t)ch*GSEG + seg] = y;
        y = w64*y + omw*GZ[(size_t)ch*GSEG + seg];
    }
}

__global__ __launch_bounds__(256) void growth_passB(const float* __restrict__ sw,
                                                    const float* __restrict__ z0,
                                                    const float* __restrict__ v0) {
    int gid = blockIdx.x*256 + threadIdx.x;
    int c = gid & 511;
    int r = gid >> 9;
    int b = r & 15, seg = r >> 4;
    float w = 1.f/(1.f + expf(-sw[c >> 6]));
    float omw = 1.f - w;
    int t0 = seg * GSEGLEN;
    const float* vp = VBUF + (size_t)b*Tn*Dn + c;
    float*       gp = GBUF + (size_t)b*T1*Dn + c;
    float prev = (t0 == 0) ? z0[c] : vp[(size_t)(t0-1)*Dn];
    float y = GCARRY[(size_t)((b<<9)+c)*GSEG + seg];
    if (seg == 0) gp[0] = v0[c];
#pragma unroll 4
    for (int l = 0; l < GSEGLEN; l++) {
        float v = vp[(size_t)(t0+l)*Dn];
        y = w*y + omw*(v - prev);
        prev = v;
        gp[(size_t)(t0+l+1)*Dn] = y;
    }
}

// ---------------- layernorm helpers ----------------
__device__ __forceinline__ float block_reduce_sum(float v, float* red) {
    for (int o = 16; o; o >>= 1) v += __shfl_xor_sync(0xffffffffu, v, o);
    int wid = threadIdx.x >> 5;
    if ((threadIdx.x & 31) == 0) red[wid] = v;
    __syncthreads();
    if (threadIdx.x < 32) {
        float s = (threadIdx.x < 4) ? red[threadIdx.x] : 0.f;
        for (int o = 2; o; o >>= 1) s += __shfl_xor_sync(0xffffffffu, s, o);
        if (threadIdx.x == 0) red[0] = s;
    }
    __syncthreads();
    float r = red[0];
    __syncthreads();
    return r;
}

__global__ __launch_bounds__(128) void res2_kernel(const float* __restrict__ out_all,
                                                   const float* __restrict__ ng,
                                                   const float* __restrict__ nb) {
    __shared__ float red[32];
    int r = blockIdx.x;
    int b = r >> 10, t = r & 1023;
    const float* x1 = RES1 + (size_t)r*Dn;
    const float* gw = out_all + OFF_GROWTH + (size_t)(b*T1 + t + 1)*Dn;
    float vals[4]; float s = 0.f;
#pragma unroll
    for (int i = 0; i < 4; i++) {
        int d = threadIdx.x + i*128;
        vals[i] = x1[d] - gw[d];
        s += vals[i];
    }
    float mu = block_reduce_sum(s, red) * (1.0f/512.0f);
    float vs = 0.f;
#pragma unroll
    for (int i = 0; i < 4; i++) { float c = vals[i]-mu; vs += c*c; }
    float var = block_reduce_sum(vs, red) * (1.0f/512.0f);
    float inv = rsqrtf(var + 1e-5f);
#pragma unroll
    for (int i = 0; i < 4; i++) {
        int d = threadIdx.x + i*128;
        R2B[(size_t)r*Dn + d] = (vals[i]-mu)*inv*ng[d] + nb[d];
    }
}

__global__ __launch_bounds__(128) void res3_kernel(float* __restrict__ out_all,
                                                   const float* __restrict__ ng,
                                                   const float* __restrict__ nb) {
    __shared__ float red[32];
    int r = blockIdx.x;
    float vals[4]; float s = 0.f;
#pragma unroll
    for (int i = 0; i < 4; i++) {
        int d = threadIdx.x + i*128;
        vals[i] = R2B[(size_t)r*Dn + d] + FOUT[(size_t)r*Dn + d];
        s += vals[i];
    }
    float mu = block_reduce_sum(s, red) * (1.0f/512.0f);
    float vs = 0.f;
#pragma unroll
    for (int i = 0; i < 4; i++) { float c = vals[i]-mu; vs += c*c; }
    float var = block_reduce_sum(vs, red) * (1.0f/512.0f);
    float inv = rsqrtf(var + 1e-5f);
#pragma unroll
    for (int i = 0; i < 4; i++) {
        int d = threadIdx.x + i*128;
        out_all[OFF_RES3 + (size_t)r*Dn + d] = (vals[i]-mu)*inv*ng[d] + nb[d];
    }
}

// ---------------- level projections ----------------
__global__ __launch_bounds__(256) void levelproj_kernel(const float* __restrict__ out_all,
                                                        const float* __restrict__ gpw,
                                                        const float* __restrict__ spw) {
    int warp = (blockIdx.x*256 + threadIdx.x) >> 5;
    int lane = threadIdx.x & 31;
    if (warp >= Bn*Tn) return;
    int b = warp >> 10, t = warp & 1023;
    const float* gr = out_all + OFF_GROWTH + (size_t)(b*T1 + t)*Dn;
    const float* se = out_all + OFF_SEASON + (size_t)(b*TP + t)*Dn;
    float ag[7] = {}, as_[7] = {};
    for (int d = lane; d < 512; d += 32) {
        float g = gr[d], s = se[d];
#pragma unroll
        for (int c = 0; c < 7; c++) { ag[c] += g*gpw[d*7+c]; as_[c] += s*spw[d*7+c]; }
    }
#pragma unroll
    for (int c = 0; c < 7; c++) {
        for (int o = 16; o; o >>= 1) {
            ag[c]  += __shfl_xor_sync(0xffffffffu, ag[c],  o);
            as_[c] += __shfl_xor_sync(0xffffffffu, as_[c], o);
        }
    }
    if (lane == 0) {
#pragma unroll
        for (int c = 0; c < 7; c++) {
            GS_G[(size_t)warp*7 + c] = ag[c];
            GS_S[(size_t)warp*7 + c] = as_[c];
        }
    }
}

// ---------------- level EMA: blocked parallel scan ----------------
__global__ void level_passA(const float* __restrict__ level,
                            const float* __restrict__ lsw) {
    int gid = blockIdx.x*blockDim.x + threadIdx.x;
    if (gid >= Bn*COUTn*GSEG) return;
    int ch = gid % (Bn*COUTn), seg = gid / (Bn*COUTn);
    int b = ch / COUTn, c = ch % COUTn;
    float w = 1.f/(1.f + expf(-lsw[c]));
    float omw = 1.f - w;
    int t0 = seg * GSEGLEN;
    const float* lp = level + (size_t)b*Tn*COUTn + c;
    const float* gp = GS_G  + (size_t)b*Tn*COUTn + c;
    const float* sp = GS_S  + (size_t)b*Tn*COUTn + c;
    float z = 0.f;
    for (int l = 0; l < GSEGLEN; l++) {
        int t = t0 + l;
        float u = omw*(lp[t*COUTn] - sp[t*COUTn]) + w*gp[t*COUTn];
        z = w*z + u;
    }
    LZ[(size_t)ch*GSEG + seg] = z;
}

__global__ void level_carry(const float* __restrict__ lsw,
                            const float* __restrict__ lv0) {
    int ch = threadIdx.x;
    if (ch >= Bn*COUTn) return;
    int c = ch % COUTn;
    float w = 1.f/(1.f + expf(-lsw[c]));
    float w64 = 1.f;
    { float p = w; int e = GSEGLEN; while (e) { if (e & 1) w64 *= p; p *= p; e >>= 1; } }
    float y = lv0[c];
#pragma unroll
    for (int seg = 0; seg < GSEG; seg++) {
        LCARRY[(size_t)ch*GSEG + seg] = y;
        y = w64*y + LZ[(size_t)ch*GSEG + seg];
    }
}

__global__ void level_passB(const float* __restrict__ level,
                            const float* __restrict__ lsw,
                            float* __restrict__ out_all) {
    int gid = blockIdx.x*blockDim.x + threadIdx.x;
    if (gid >= Bn*COUTn*GSEG) return;
    int ch = gid % (Bn*COUTn), seg = gid / (Bn*COUTn);
    int b = ch / COUTn, c = ch % COUTn;
    float w = 1.f/(1.f + expf(-lsw[c]));
    float omw = 1.f - w;
    int t0 = seg * GSEGLEN;
    const float* lp = level + (size_t)b*Tn*COUTn + c;
    const float* gp = GS_G  + (size_t)b*Tn*COUTn + c;
    const float* sp = GS_S  + (size_t)b*Tn*COUTn + c;
    float* op = out_all + OFF_LEVEL + (size_t)b*Tn*COUTn + c;
    float y = LCARRY[(size_t)ch*GSEG + seg];
    for (int l = 0; l < GSEGLEN; l++) {
        int t = t0 + l;
        float u = omw*(lp[t*COUTn] - sp[t*COUTn]) + w*gp[t*COUTn];
        y = w*y + u;
        op[t*COUTn] = y;
    }
}

// ---------------- launch ----------------
extern "C" void kernel_launch(void* const* d_in, const int* in_sizes, int n_in,
                              void* d_out, int out_size) {
    const float* res      = (const float*)d_in[0];
    const float* level    = (const float*)d_in[1];
    const float* in_w     = (const float*)d_in[2];
    const float* out_w    = (const float*)d_in[3];
    const float* z0       = (const float*)d_in[4];
    const float* gsw      = (const float*)d_in[5];
    const float* gv0      = (const float*)d_in[6];
    const float* ff_w1    = (const float*)d_in[7];
    const float* ff_w2    = (const float*)d_in[8];
    const float* n1g      = (const float*)d_in[9];
    const float* n1b      = (const float*)d_in[10];
    const float* n2g      = (const float*)d_in[11];
    const float* n2b      = (const float*)d_in[12];
    const float* gpw      = (const float*)d_in[13];
    const float* spw      = (const float*)d_in[14];
    const float* lsw      = (const float*)d_in[15];
    const float* lv0      = (const float*)d_in[16];
    float* out = (float*)d_out;

    float *pRES1, *pVBUF, *pGBUF, *pR2, *pFBUF, *pFOUT;
    cudaGetSymbolAddress((void**)&pRES1, RES1);
    cudaGetSymbolAddress((void**)&pVBUF, VBUF);
    cudaGetSymbolAddress((void**)&pGBUF, GBUF);
    cudaGetSymbolAddress((void**)&pR2,   R2B);
    cudaGetSymbolAddress((void**)&pFBUF, FBUF);
    cudaGetSymbolAddress((void**)&pFOUT, FOUT);

    static int smem_set = 0;
    if (!smem_set) {
        cudaFuncSetAttribute(tf32gemm_kernel,
                             cudaFuncAttributeMaxDynamicSharedMemorySize, GEMM_SMEM);
        smem_set = 1;
    }

    // 1) FFT + top-k
    fft_topk_kernel<<<Bn*(Dn/4), 256>>>(res);
    // 2) season + res1
    season_kernel<<<dim3(2, Bn, 10), 256>>>(res, out);
    // 3) v = res1 @ in_proj_w
    tf32gemm_kernel<<<dim3(Dn/128, (Bn*Tn)/128), 256, GEMM_SMEM>>>(pRES1, in_w, pVBUF,
                                                                   Bn*Tn, Dn, Dn, 0);
    // 4) diffs + EMA (blocked scan)
    growth_passA<<<(Bn*Dn*GSEG)/256, 256>>>(gsw, z0);
    growth_carry<<<(Bn*Dn)/256, 256>>>(gsw, gv0);
    growth_passB<<<(Bn*Dn*GSEG)/256, 256>>>(gsw, z0, gv0);
    // 5) growth = GBUF @ out_proj_w -> d_out
    tf32gemm_kernel<<<dim3(Dn/128, (Bn*T1 + 127)/128), 256, GEMM_SMEM>>>(pGBUF, out_w,
                                                                         out + OFF_GROWTH,
                                                                         Bn*T1, Dn, Dn, 0);
    // 6) res2 = LN(res1 - growth[:,1:])
    res2_kernel<<<Bn*Tn, 128>>>(out, n1g, n1b);
    // 7) ffn1 = gelu(res2 @ ff_w1)
    tf32gemm_kernel<<<dim3(LATENTn/128, (Bn*Tn)/128), 256, GEMM_SMEM>>>(pR2, ff_w1, pFBUF,
                                                                        Bn*Tn, LATENTn, Dn, 1);
    // 8) ffn2 = ffn1 @ ff_w2
    tf32gemm_kernel<<<dim3(Dn/128, (Bn*Tn)/128), 256, GEMM_SMEM>>>(pFBUF, ff_w2, pFOUT,
                                                                   Bn*Tn, Dn, LATENTn, 0);
    // 9) res3 = LN(res2 + ffn2) -> d_out
    res3_kernel<<<Bn*Tn, 128>>>(out, n2g, n2b);
    // 10) level projections
    levelproj_kernel<<<(Bn*Tn*32)/256, 256>>>(out, gpw, spw);
    // 11) level EMA (blocked scan) -> d_out
    level_passA<<<(Bn*COUTn*GSEG + 255)/256, 256>>>(level, lsw);
    level_carry<<<1, 128>>>(lsw, lv0);
    level_passB<<<(Bn*COUTn*GSEG + 255)/256, 256>>>(level, lsw, out);
}

// round 5
// speedup vs baseline: 1.1758x; 1.0580x over previous
#include <cuda_runtime.h>
#include <math.h>

#define Bn 16
#define Tn 1024
#define Dn 512
#define Hn 8
#define HDn 64
#define COUTn 7
#define PREDn 96
#define Kn 8
#define LATENTn 2048
#define TP (Tn + PREDn)   /* 1120 */
#define T1 (Tn + 1)       /* 1025 */

#define OFF_RES3   0
#define OFF_LEVEL  (Bn*Tn*Dn)
#define OFF_GROWTH (OFF_LEVEL + Bn*Tn*COUTn)
#define OFF_SEASON (OFF_GROWTH + Bn*T1*Dn)

#define GSEG 16
#define GSEGLEN 64

// GEMM tiling
#define STAGES 3
#define BKf 32
#define APADf 36
#define BPADf 136
#define A_STAGE_FLOATS (128*APADf)
#define B_STAGE_FLOATS (BKf*BPADf)
#define GEMM_SMEM (STAGES*(A_STAGE_FLOATS + B_STAGE_FLOATS)*4)

// ---------------- scratch ----------------
__device__ float RES1 [Bn*Tn*Dn];
__device__ float RES1R[Bn*Tn*Dn];
__device__ float VBUF[Bn*Tn*Dn];
__device__ float GBUF[Bn*T1*Dn];
__device__ float R2B [Bn*Tn*Dn];
__device__ float R2BR[Bn*Tn*Dn];
__device__ float FBUF[Bn*Tn*LATENTn];
__device__ float FOUT[Bn*Tn*Dn];
__device__ float WINR [Dn*Dn];
__device__ float WOUTR[Dn*Dn];
__device__ float W1R  [Dn*LATENTn];
__device__ float W2R  [LATENTn*Dn];
__device__ float TK_RE[Bn*Kn*Dn];
__device__ float TK_IM[Bn*Kn*Dn];
__device__ int   TK_M [Bn*Kn*Dn];
__device__ float GS_G[Bn*Tn*COUTn];
__device__ float GS_S[Bn*Tn*COUTn];
__device__ float GZ    [Bn*Dn*GSEG];
__device__ float GCARRY[Bn*Dn*GSEG];
__device__ float LZ    [Bn*COUTn*GSEG];
__device__ float LCARRY[Bn*COUTn*GSEG];

__device__ __forceinline__ unsigned f2tf32(float f) {
    unsigned u;
    asm("cvt.rna.tf32.f32 %0, %1;" : "=r"(u) : "f"(f));
    return u;
}
__device__ __forceinline__ float rtf(float f) { return __uint_as_float(f2tf32(f)); }

// ---------------- round-copy (weights -> tf32 bit patterns) ----------------
__global__ __launch_bounds__(256) void roundcopy4(const float4* __restrict__ src,
                                                  float4* __restrict__ dst, int n4) {
    int i = blockIdx.x*256 + threadIdx.x;
    if (i < n4) {
        float4 v = src[i];
        dst[i] = make_float4(rtf(v.x), rtf(v.y), rtf(v.z), rtf(v.w));
    }
}

// ---------------- FFT (radix-2 DIF, 1024-pt) + top-8 per series ----------------
__global__ __launch_bounds__(256) void fft_topk_kernel(const float* __restrict__ x) {
    __shared__ float2 data[4][1024];
    __shared__ float2 tw[512];
    int tid = threadIdx.x;
    int b   = blockIdx.x >> 7;
    int d0  = (blockIdx.x & 127) << 2;

    for (int k = tid; k < 512; k += 256) {
        float s, c;
        sincosf(-6.283185307179586f * (float)k / 1024.0f, &s, &c);
        tw[k] = make_float2(c, s);
    }
    const float* xb = x + (size_t)b * Tn * Dn;
    for (int i = tid; i < 4096; i += 256) {
        int t = i >> 2, j = i & 3;
        data[j][t] = make_float2(xb[(size_t)t*Dn + d0 + j], 0.f);
    }
    __syncthreads();

    int tmul = 1;
    for (int half = 512; half >= 1; half >>= 1, tmul <<= 1) {
        for (int i = tid; i < 2048; i += 256) {
            int s  = i >> 9;
            int bf = i & 511;
            int k  = bf & (half - 1);
            int pos = 2*bf - k;
            float2 u = data[s][pos], v = data[s][pos + half];
            data[s][pos] = make_float2(u.x + v.x, u.y + v.y);
            float2 t2 = make_float2(u.x - v.x, u.y - v.y);
            float2 w  = tw[k * tmul];
            data[s][pos + half] = make_float2(t2.x*w.x - t2.y*w.y,
                                              t2.x*w.y + t2.y*w.x);
        }
        __syncthreads();
    }

    int wid = tid >> 5, lane = tid & 31;
    if (wid < 4) {
        int s = wid;
        int chosen[8];
#pragma unroll
        for (int q = 0; q < 8; q++) chosen[q] = -1;
#pragma unroll
        for (int it = 0; it < 8; it++) {
            float bestm = -1.f; int bestf = 1 << 20;
            for (int f = 1 + lane; f <= 511; f += 32) {
                bool used = false;
#pragma unroll
                for (int q = 0; q < 8; q++) used |= (chosen[q] == f);
                if (used) continue;
                int j = (int)(__brev((unsigned)f) >> 22);
                float2 v = data[s][j];
                float m2 = v.x*v.x + v.y*v.y;
                if (m2 > bestm || (m2 == bestm && f < bestf)) { bestm = m2; bestf = f; }
            }
            for (int off = 16; off; off >>= 1) {
                float om = __shfl_xor_sync(0xffffffffu, bestm, off);
                int   of = __shfl_xor_sync(0xffffffffu, bestf, off);
                if (om > bestm || (om == bestm && of < bestf)) { bestm = om; bestf = of; }
            }
            chosen[it] = bestf;
        }
        if (lane == 0) {
            int d = d0 + s;
#pragma unroll
            for (int it = 0; it < 8; it++) {
                int f = chosen[it];
                int j = (int)(__brev((unsigned)f) >> 22);
                float2 v = data[s][j];
                size_t o = ((size_t)b * Kn + it) * Dn + d;
                TK_M[o] = f; TK_RE[o] = v.x; TK_IM[o] = v.y;
            }
        }
    }
}

// ---------------- season reconstruction + res1 (+ rounded copy) ----------------
__global__ __launch_bounds__(256) void season_kernel(const float* __restrict__ res,
                                                     float* __restrict__ out) {
    __shared__ float ctab[1024];
    for (int j = threadIdx.x; j < 1024; j += 256)
        ctab[j] = cosf(6.283185307179586f / 1024.0f * (float)j);
    __syncthreads();

    int d  = blockIdx.x * 256 + threadIdx.x;
    int b  = blockIdx.y;
    int t0 = blockIdx.z * 112;

    int ms[8]; float re[8], im[8];
#pragma unroll
    for (int k = 0; k < 8; k++) {
        size_t o = ((size_t)b*Kn + k)*Dn + d;
        ms[k] = TK_M[o];
        re[k] = TK_RE[o] * (2.0f / (float)Tn);
        im[k] = TK_IM[o] * (2.0f / (float)Tn);
    }
    float*       seas = out + OFF_SEASON + (size_t)b*TP*Dn;
    const float* rb   = res + (size_t)b*Tn*Dn;
    float*       r1   = RES1  + (size_t)b*Tn*Dn;
    float*       r1r  = RES1R + (size_t)b*Tn*Dn;

    for (int t = t0; t < t0 + 112; t++) {
        float acc = 0.f;
#pragma unroll
        for (int k = 0; k < 8; k++) {
            int idx = (ms[k]*t) & 1023;
            acc += re[k]*ctab[idx] - im[k]*ctab[(idx + 768) & 1023];
        }
        seas[(size_t)t*Dn + d] = acc;
        if (t < Tn) {
            float v = rb[(size_t)t*Dn + d] - acc;
            r1 [(size_t)t*Dn + d] = v;
            r1r[(size_t)t*Dn + d] = rtf(v);
        }
    }
}

// ---------------- TF32 GEMM: cp.async 3-stage, pre-rounded inputs ----------------
__device__ __forceinline__ void cp_async16(unsigned saddr, const void* gptr, bool valid) {
    int sz = valid ? 16 : 0;
    asm volatile("cp.async.cg.shared.global [%0], [%1], 16, %2;\n"
                 :: "r"(saddr), "l"(gptr), "r"(sz));
}

__global__ __launch_bounds__(256) void tf32gemm_kernel(const float* __restrict__ A,
                                                       const float* __restrict__ Bm,
                                                       float* __restrict__ C,
                                                       int M, int N, int K,
                                                       int dogelu, int roundout) {
    extern __shared__ float sm[];
    float* Asf = sm;                               // [STAGES][128][APADf]
    float* Bsf = sm + STAGES * A_STAGE_FLOATS;     // [STAGES][BKf][BPADf]
    unsigned As_base = (unsigned)__cvta_generic_to_shared(Asf);
    unsigned Bs_base = (unsigned)__cvta_generic_to_shared(Bsf);

    int tid = threadIdx.x;
    int row0 = blockIdx.y * 128, col0 = blockIdx.x * 128;
    int wid = tid >> 5, lane = tid & 31;
    int wm = (wid & 1) * 64, wn = (wid >> 1) * 32;
    int g = lane >> 2, tg = lane & 3;

    int arow = tid >> 1, ac0 = (tid & 1) * 4;
    int brow = tid >> 3, bc0 = (tid & 7) * 4;
    int agr = row0 + arow;
    bool avalid = (agr < M);
    const float* agp = A + (size_t)agr * K + ac0 * 4;
    const float* bgp = Bm + (size_t)brow * N + col0 + bc0 * 4;

    float acc[4][4][4];
#pragma unroll
    for (int i = 0; i < 4; i++)
#pragma unroll
        for (int j = 0; j < 4; j++)
#pragma unroll
            for (int q = 0; q < 4; q++) acc[i][j][q] = 0.f;

    const int NT = K / BKf;

#pragma unroll
    for (int s = 0; s < 2; s++) {
        unsigned adst = As_base + (s*A_STAGE_FLOATS + arow*APADf + ac0*4) * 4;
        unsigned bdst = Bs_base + (s*B_STAGE_FLOATS + brow*BPADf + bc0*4) * 4;
        const float* ag = agp + s * BKf;
        const float* bg = bgp + (size_t)s * BKf * N;
#pragma unroll
        for (int q = 0; q < 4; q++) {
            cp_async16(adst + q*16, ag + q*4, avalid);
            cp_async16(bdst + q*16, bg + q*4, true);
        }
        asm volatile("cp.async.commit_group;\n");
    }

    for (int it = 0; it < NT; it++) {
        if (it < NT - 1) asm volatile("cp.async.wait_group 1;\n");
        else             asm volatile("cp.async.wait_group 0;\n");
        __syncthreads();

        if (it + 2 < NT) {
            int s = (it + 2) % STAGES;
            unsigned adst = As_base + (s*A_STAGE_FLOATS + arow*APADf + ac0*4) * 4;
            unsigned bdst = Bs_base + (s*B_STAGE_FLOATS + brow*BPADf + bc0*4) * 4;
            const float* ag = agp + (it + 2) * BKf;
            const float* bg = bgp + (size_t)(it + 2) * BKf * N;
#pragma unroll
            for (int q = 0; q < 4; q++) {
                cp_async16(adst + q*16, ag + q*4, avalid);
                cp_async16(bdst + q*16, bg + q*4, true);
            }
            asm volatile("cp.async.commit_group;\n");
        }

        const float* Abuf = Asf + (it % STAGES) * A_STAGE_FLOATS;
        const float* Bbuf = Bsf + (it % STAGES) * B_STAGE_FLOATS;

#pragma unroll
        for (int kk = 0; kk < BKf; kk += 8) {
            unsigned af[4][4], bf[4][2];
#pragma unroll
            for (int mt = 0; mt < 4; mt++) {
                int m = wm + mt*16 + g;
                af[mt][0] = __float_as_uint(Abuf[(m  )*APADf + kk + tg    ]);
                af[mt][1] = __float_as_uint(Abuf[(m+8)*APADf + kk + tg    ]);
                af[mt][2] = __float_as_uint(Abuf[(m  )*APADf + kk + tg + 4]);
                af[mt][3] = __float_as_uint(Abuf[(m+8)*APADf + kk + tg + 4]);
            }
#pragma unroll
            for (int nt = 0; nt < 4; nt++) {
                int n = wn + nt*8 + g;
                bf[nt][0] = __float_as_uint(Bbuf[(kk+tg  )*BPADf + n]);
                bf[nt][1] = __float_as_uint(Bbuf[(kk+tg+4)*BPADf + n]);
            }
#pragma unroll
            for (int mt = 0; mt < 4; mt++)
#pragma unroll
                for (int nt = 0; nt < 4; nt++)
                    asm volatile(
                        "mma.sync.aligned.m16n8k8.row.col.f32.tf32.tf32.f32 "
                        "{%0,%1,%2,%3}, {%4,%5,%6,%7}, {%8,%9}, {%0,%1,%2,%3};"
                        : "+f"(acc[mt][nt][0]), "+f"(acc[mt][nt][1]),
                          "+f"(acc[mt][nt][2]), "+f"(acc[mt][nt][3])
                        : "r"(af[mt][0]), "r"(af[mt][1]), "r"(af[mt][2]), "r"(af[mt][3]),
                          "r"(bf[nt][0]), "r"(bf[nt][1]));
        }
        __syncthreads();
    }

#pragma unroll
    for (int mt = 0; mt < 4; mt++) {
#pragma unroll
        for (int nt = 0; nt < 4; nt++) {
            int r0 = row0 + wm + mt*16 + g;
            int c  = col0 + wn + nt*8 + 2*tg;
            float v[4];
#pragma unroll
            for (int q = 0; q < 4; q++) {
                float u = acc[mt][nt][q];
                if (dogelu) u = 0.5f*u*(1.0f + erff(u*0.70710678118654752f));
                if (roundout) u = rtf(u);
                v[q] = u;
            }
            if (r0 < M)     *(float2*)(C + (size_t)r0*N + c)     = make_float2(v[0], v[1]);
            if (r0 + 8 < M) *(float2*)(C + (size_t)(r0+8)*N + c) = make_float2(v[2], v[3]);
        }
    }
}

// ---------------- growth EMA: blocked parallel scan ----------------
__global__ __launch_bounds__(256) void growth_passA(const float* __restrict__ sw,
                                                    const float* __restrict__ z0) {
    int gid = blockIdx.x*256 + threadIdx.x;
    int c = gid & 511;
    int r = gid >> 9;
    int b = r & 15, seg = r >> 4;
    float w = 1.f/(1.f + expf(-sw[c >> 6]));
    int t0 = seg * GSEGLEN;
    const float* vp = VBUF + (size_t)b*Tn*Dn + c;
    float prev = (t0 == 0) ? z0[c] : vp[(size_t)(t0-1)*Dn];
    float z = 0.f;
#pragma unroll 4
    for (int l = 0; l < GSEGLEN; l++) {
        float v = vp[(size_t)(t0+l)*Dn];
        z = w*z + (v - prev);
        prev = v;
    }
    GZ[(size_t)((b<<9)+c)*GSEG + seg] = z;
}

__global__ __launch_bounds__(256) void growth_carry(const float* __restrict__ sw,
                                                    const float* __restrict__ v0) {
    int ch = blockIdx.x*256 + threadIdx.x;
    int c = ch & 511;
    float w = 1.f/(1.f + expf(-sw[c >> 6]));
    float w64 = 1.f;
    { float p = w; int e = GSEGLEN; while (e) { if (e & 1) w64 *= p; p *= p; e >>= 1; } }
    float y = v0[c];
    float omw = 1.f - w;
#pragma unroll
    for (int seg = 0; seg < GSEG; seg++) {
        GCARRY[(size_t)ch*GSEG + seg] = y;
        y = w64*y + omw*GZ[(size_t)ch*GSEG + seg];
    }
}

// stores GBUF pre-rounded to tf32 (GBUF feeds only GEMM2)
__global__ __launch_bounds__(256) void growth_passB(const float* __restrict__ sw,
                                                    const float* __restrict__ z0,
                                                    const float* __restrict__ v0) {
    int gid = blockIdx.x*256 + threadIdx.x;
    int c = gid & 511;
    int r = gid >> 9;
    int b = r & 15, seg = r >> 4;
    float w = 1.f/(1.f + expf(-sw[c >> 6]));
    float omw = 1.f - w;
    int t0 = seg * GSEGLEN;
    const float* vp = VBUF + (size_t)b*Tn*Dn + c;
    float*       gp = GBUF + (size_t)b*T1*Dn + c;
    float prev = (t0 == 0) ? z0[c] : vp[(size_t)(t0-1)*Dn];
    float y = GCARRY[(size_t)((b<<9)+c)*GSEG + seg];
    if (seg == 0) gp[0] = rtf(v0[c]);
#pragma unroll 4
    for (int l = 0; l < GSEGLEN; l++) {
        float v = vp[(size_t)(t0+l)*Dn];
        y = w*y + omw*(v - prev);
        prev = v;
        gp[(size_t)(t0+l+1)*Dn] = rtf(y);
    }
}

// ---------------- layernorm helpers ----------------
__device__ __forceinline__ float block_reduce_sum(float v, float* red) {
    for (int o = 16; o; o >>= 1) v += __shfl_xor_sync(0xffffffffu, v, o);
    int wid = threadIdx.x >> 5;
    if ((threadIdx.x & 31) == 0) red[wid] = v;
    __syncthreads();
    if (threadIdx.x < 32) {
        float s = (threadIdx.x < 4) ? red[threadIdx.x] : 0.f;
        for (int o = 2; o; o >>= 1) s += __shfl_xor_sync(0xffffffffu, s, o);
        if (threadIdx.x == 0) red[0] = s;
    }
    __syncthreads();
    float r = red[0];
    __syncthreads();
    return r;
}

__global__ __launch_bounds__(128) void res2_kernel(const float* __restrict__ out_all,
                                                   const float* __restrict__ ng,
                                                   const float* __restrict__ nb) {
    __shared__ float red[32];
    int r = blockIdx.x;
    int b = r >> 10, t = r & 1023;
    const float* x1 = RES1 + (size_t)r*Dn;
    const float* gw = out_all + OFF_GROWTH + (size_t)(b*T1 + t + 1)*Dn;
    float vals[4]; float s = 0.f;
#pragma unroll
    for (int i = 0; i < 4; i++) {
        int d = threadIdx.x + i*128;
        vals[i] = x1[d] - gw[d];
        s += vals[i];
    }
    float mu = block_reduce_sum(s, red) * (1.0f/512.0f);
    float vs = 0.f;
#pragma unroll
    for (int i = 0; i < 4; i++) { float c = vals[i]-mu; vs += c*c; }
    float var = block_reduce_sum(vs, red) * (1.0f/512.0f);
    float inv = rsqrtf(var + 1e-5f);
#pragma unroll
    for (int i = 0; i < 4; i++) {
        int d = threadIdx.x + i*128;
        float v = (vals[i]-mu)*inv*ng[d] + nb[d];
        R2B [(size_t)r*Dn + d] = v;
        R2BR[(size_t)r*Dn + d] = rtf(v);
    }
}

__global__ __launch_bounds__(128) void res3_kernel(float* __restrict__ out_all,
                                                   const float* __restrict__ ng,
                                                   const float* __restrict__ nb) {
    __shared__ float red[32];
    int r = blockIdx.x;
    float vals[4]; float s = 0.f;
#pragma unroll
    for (int i = 0; i < 4; i++) {
        int d = threadIdx.x + i*128;
        vals[i] = R2B[(size_t)r*Dn + d] + FOUT[(size_t)r*Dn + d];
        s += vals[i];
    }
    float mu = block_reduce_sum(s, red) * (1.0f/512.0f);
    float vs = 0.f;
#pragma unroll
    for (int i = 0; i < 4; i++) { float c = vals[i]-mu; vs += c*c; }
    float var = block_reduce_sum(vs, red) * (1.0f/512.0f);
    float inv = rsqrtf(var + 1e-5f);
#pragma unroll
    for (int i = 0; i < 4; i++) {
        int d = threadIdx.x + i*128;
        out_all[OFF_RES3 + (size_t)r*Dn + d] = (vals[i]-mu)*inv*ng[d] + nb[d];
    }
}

// ---------------- level projections ----------------
__global__ __launch_bounds__(256) void levelproj_kernel(const float* __restrict__ out_all,
                                                        const float* __restrict__ gpw,
                                                        const float* __restrict__ spw) {
    int warp = (blockIdx.x*256 + threadIdx.x) >> 5;
    int lane = threadIdx.x & 31;
    if (warp >= Bn*Tn) return;
    int b = warp >> 10, t = warp & 1023;
    const float* gr = out_all + OFF_GROWTH + (size_t)(b*T1 + t)*Dn;
    const float* se = out_all + OFF_SEASON + (size_t)(b*TP + t)*Dn;
    float ag[7] = {}, as_[7] = {};
    for (int d = lane; d < 512; d += 32) {
        float g = gr[d], s = se[d];
#pragma unroll
        for (int c = 0; c < 7; c++) { ag[c] += g*gpw[d*7+c]; as_[c] += s*spw[d*7+c]; }
    }
#pragma unroll
    for (int c = 0; c < 7; c++) {
        for (int o = 16; o; o >>= 1) {
            ag[c]  += __shfl_xor_sync(0xffffffffu, ag[c],  o);
            as_[c] += __shfl_xor_sync(0xffffffffu, as_[c], o);
        }
    }
    if (lane == 0) {
#pragma unroll
        for (int c = 0; c < 7; c++) {
            GS_G[(size_t)warp*7 + c] = ag[c];
            GS_S[(size_t)warp*7 + c] = as_[c];
        }
    }
}

// ---------------- level EMA: blocked parallel scan ----------------
__global__ void level_passA(const float* __restrict__ level,
                            const float* __restrict__ lsw) {
    int gid = blockIdx.x*blockDim.x + threadIdx.x;
    if (gid >= Bn*COUTn*GSEG) return;
    int ch = gid % (Bn*COUTn), seg = gid / (Bn*COUTn);
    int b = ch / COUTn, c = ch % COUTn;
    float w = 1.f/(1.f + expf(-lsw[c]));
    float omw = 1.f - w;
    int t0 = seg * GSEGLEN;
    const float* lp = level + (size_t)b*Tn*COUTn + c;
    const float* gp = GS_G  + (size_t)b*Tn*COUTn + c;
    const float* sp = GS_S  + (size_t)b*Tn*COUTn + c;
    float z = 0.f;
    for (int l = 0; l < GSEGLEN; l++) {
        int t = t0 + l;
        float u = omw*(lp[t*COUTn] - sp[t*COUTn]) + w*gp[t*COUTn];
        z = w*z + u;
    }
    LZ[(size_t)ch*GSEG + seg] = z;
}

__global__ void level_carry(const float* __restrict__ lsw,
                            const float* __restrict__ lv0) {
    int ch = threadIdx.x;
    if (ch >= Bn*COUTn) return;
    int c = ch % COUTn;
    float w = 1.f/(1.f + expf(-lsw[c]));
    float w64 = 1.f;
    { float p = w; int e = GSEGLEN; while (e) { if (e & 1) w64 *= p; p *= p; e >>= 1; } }
    float y = lv0[c];
#pragma unroll
    for (int seg = 0; seg < GSEG; seg++) {
        LCARRY[(size_t)ch*GSEG + seg] = y;
        y = w64*y + LZ[(size_t)ch*GSEG + seg];
    }
}

__global__ void level_passB(const float* __restrict__ level,
                            const float* __restrict__ lsw,
                            float* __restrict__ out_all) {
    int gid = blockIdx.x*blockDim.x + threadIdx.x;
    if (gid >= Bn*COUTn*GSEG) return;
    int ch = gid % (Bn*COUTn), seg = gid / (Bn*COUTn);
    int b = ch / COUTn, c = ch % COUTn;
    float w = 1.f/(1.f + expf(-lsw[c]));
    float omw = 1.f - w;
    int t0 = seg * GSEGLEN;
    const float* lp = level + (size_t)b*Tn*COUTn + c;
    const float* gp = GS_G  + (size_t)b*Tn*COUTn + c;
    const float* sp = GS_S  + (size_t)b*Tn*COUTn + c;
    float* op = out_all + OFF_LEVEL + (size_t)b*Tn*COUTn + c;
    float y = LCARRY[(size_t)ch*GSEG + seg];
    for (int l = 0; l < GSEGLEN; l++) {
        int t = t0 + l;
        float u = omw*(lp[t*COUTn] - sp[t*COUTn]) + w*gp[t*COUTn];
        y = w*y + u;
        op[t*COUTn] = y;
    }
}

// ---------------- launch ----------------
extern "C" void kernel_launch(void* const* d_in, const int* in_sizes, int n_in,
                              void* d_out, int out_size) {
    const float* res      = (const float*)d_in[0];
    const float* level    = (const float*)d_in[1];
    const float* in_w     = (const float*)d_in[2];
    const float* out_w    = (const float*)d_in[3];
    const float* z0       = (const float*)d_in[4];
    const float* gsw      = (const float*)d_in[5];
    const float* gv0      = (const float*)d_in[6];
    const float* ff_w1    = (const float*)d_in[7];
    const float* ff_w2    = (const float*)d_in[8];
    const float* n1g      = (const float*)d_in[9];
    const float* n1b      = (const float*)d_in[10];
    const float* n2g      = (const float*)d_in[11];
    const float* n2b      = (const float*)d_in[12];
    const float* gpw      = (const float*)d_in[13];
    const float* spw      = (const float*)d_in[14];
    const float* lsw      = (const float*)d_in[15];
    const float* lv0      = (const float*)d_in[16];
    float* out = (float*)d_out;

    float *pRES1R, *pVBUF, *pGBUF, *pR2R, *pFBUF, *pFOUT;
    float *pWIN, *pWOUT, *pW1, *pW2;
    cudaGetSymbolAddress((void**)&pRES1R, RES1R);
    cudaGetSymbolAddress((void**)&pVBUF,  VBUF);
    cudaGetSymbolAddress((void**)&pGBUF,  GBUF);
    cudaGetSymbolAddress((void**)&pR2R,   R2BR);
    cudaGetSymbolAddress((void**)&pFBUF,  FBUF);
    cudaGetSymbolAddress((void**)&pFOUT,  FOUT);
    cudaGetSymbolAddress((void**)&pWIN,   WINR);
    cudaGetSymbolAddress((void**)&pWOUT,  WOUTR);
    cudaGetSymbolAddress((void**)&pW1,    W1R);
    cudaGetSymbolAddress((void**)&pW2,    W2R);

    static int smem_set = 0;
    if (!smem_set) {
        cudaFuncSetAttribute(tf32gemm_kernel,
                             cudaFuncAttributeMaxDynamicSharedMemorySize, GEMM_SMEM);
        smem_set = 1;
    }

    // 0) round weights to tf32 bit patterns
    roundcopy4<<<(Dn*Dn/4 + 255)/256, 256>>>((const float4*)in_w,  (float4*)pWIN,  Dn*Dn/4);
    roundcopy4<<<(Dn*Dn/4 + 255)/256, 256>>>((const float4*)out_w, (float4*)pWOUT, Dn*Dn/4);
    roundcopy4<<<(Dn*LATENTn/4 + 255)/256, 256>>>((const float4*)ff_w1, (float4*)pW1, Dn*LATENTn/4);
    roundcopy4<<<(Dn*LATENTn/4 + 255)/256, 256>>>((const float4*)ff_w2, (float4*)pW2, Dn*LATENTn/4);

    // 1) FFT + top-k
    fft_topk_kernel<<<Bn*(Dn/4), 256>>>(res);
    // 2) season + res1 (+rounded)
    season_kernel<<<dim3(2, Bn, 10), 256>>>(res, out);
    // 3) v = res1 @ in_proj_w
    tf32gemm_kernel<<<dim3(Dn/128, (Bn*Tn)/128), 256, GEMM_SMEM>>>(pRES1R, pWIN, pVBUF,
                                                                   Bn*Tn, Dn, Dn, 0, 0);
    // 4) diffs + EMA (blocked scan)
    growth_passA<<<(Bn*Dn*GSEG)/256, 256>>>(gsw, z0);
    growth_carry<<<(Bn*Dn)/256, 256>>>(gsw, gv0);
    growth_passB<<<(Bn*Dn*GSEG)/256, 256>>>(gsw, z0, gv0);
    // 5) growth = GBUF @ out_proj_w -> d_out
    tf32gemm_kernel<<<dim3(Dn/128, (Bn*T1 + 127)/128), 256, GEMM_SMEM>>>(pGBUF, pWOUT,
                                                                         out + OFF_GROWTH,
                                                                         Bn*T1, Dn, Dn, 0, 0);
    // 6) res2 = LN(res1 - growth[:,1:])  (+rounded copy)
    res2_kernel<<<Bn*Tn, 128>>>(out, n1g, n1b);
    // 7) ffn1 = gelu(res2 @ ff_w1), rounded for GEMM4
    tf32gemm_kernel<<<dim3(LATENTn/128, (Bn*Tn)/128), 256, GEMM_SMEM>>>(pR2R, pW1, pFBUF,
                                                                        Bn*Tn, LATENTn, Dn, 1, 1);
    // 8) ffn2 = ffn1 @ ff_w2
    tf32gemm_kernel<<<dim3(Dn/128, (Bn*Tn)/128), 256, GEMM_SMEM>>>(pFBUF, pW2, pFOUT,
                                                                   Bn*Tn, Dn, LATENTn, 0, 0);
    // 9) res3 = LN(res2 + ffn2) -> d_out
    res3_kernel<<<Bn*Tn, 128>>>(out, n2g, n2b);
    // 10) level projections
    levelproj_kernel<<<(Bn*Tn*32)/256, 256>>>(out, gpw, spw);
    // 11) level EMA (blocked scan) -> d_out
    level_passA<<<(Bn*COUTn*GSEG + 255)/256, 256>>>(level, lsw);
    level_carry<<<1, 128>>>(lsw, lv0);
    level_passB<<<(Bn*COUTn*GSEG + 255)/256, 256>>>(level, lsw, out);
}

// round 8
// speedup vs baseline: 1.8083x; 1.5379x over previous
#include <cuda_runtime.h>
#include <cuda_fp16.h>
#include <math.h>
#include <stdint.h>

#define Bn 16
#define Tn 1024
#define Dn 512
#define COUTn 7
#define PREDn 96
#define Kn 8
#define LATENTn 2048
#define TP (Tn + PREDn)
#define T1 (Tn + 1)

#define OFF_RES3   0
#define OFF_LEVEL  (Bn*Tn*Dn)
#define OFF_GROWTH (OFF_LEVEL + Bn*Tn*COUTn)
#define OFF_SEASON (OFF_GROWTH + Bn*T1*Dn)

#define GSEG 16
#define GSEGLEN 64

// fp16 GEMM tiling
#define STAGESH 3
#define BKH 32                     /* k halfs per stage */
#define APADH 40                   /* padded halfs per row: 80B, 16B-aligned rows */
#define STG_HALFS (128*APADH)      /* halfs per matrix-stage = 5120 */
#define HS_TOTAL (STAGESH*2*STG_HALFS*2)   /* bytes = 61440 */

// ---------------- scratch ----------------
__device__ float RES1 [Bn*Tn*Dn];
__device__ __align__(256) __half RES1H[Bn*Tn*Dn];
__device__ float VBUF[Bn*Tn*Dn];
__device__ __align__(256) __half GBUFH[Bn*T1*Dn];
__device__ float R2B [Bn*Tn*Dn];
__device__ __align__(256) __half R2BH[Bn*Tn*Dn];
__device__ __align__(256) __half FBUFH[Bn*Tn*LATENTn];
__device__ float FOUT[Bn*Tn*Dn];
__device__ __align__(256) __half WT_IN [Dn*Dn];      // [N][K]
__device__ __align__(256) __half WT_OUT[Dn*Dn];
__device__ __align__(256) __half WT_1  [LATENTn*Dn];
__device__ __align__(256) __half WT_2  [Dn*LATENTn];
__device__ float TK_RE[Bn*Kn*Dn];
__device__ float TK_IM[Bn*Kn*Dn];
__device__ int   TK_M [Bn*Kn*Dn];
__device__ float GS_G[Bn*Tn*COUTn];
__device__ float GS_S[Bn*Tn*COUTn];
__device__ float GZ    [Bn*Dn*GSEG];
__device__ float GCARRY[Bn*Dn*GSEG];
__device__ float LZ    [Bn*COUTn*GSEG];
__device__ float LCARRY[Bn*COUTn*GSEG];

// ---------------- transpose to half: dst[c][r] = (half)src[r][c] ----------------
__global__ __launch_bounds__(256) void transpose_half(const float* __restrict__ src,
                                                      __half* __restrict__ dst,
                                                      int R, int Ccol) {
    __shared__ float t[32][33];
    int tx = threadIdx.x & 31, ty = threadIdx.x >> 5;
    int c0 = blockIdx.x*32, r0 = blockIdx.y*32;
#pragma unroll
    for (int i = 0; i < 4; i++)
        t[ty + i*8][tx] = src[(size_t)(r0 + ty + i*8)*Ccol + c0 + tx];
    __syncthreads();
#pragma unroll
    for (int i = 0; i < 4; i++)
        dst[(size_t)(c0 + ty + i*8)*R + r0 + tx] = __float2half(t[tx][ty + i*8]);
}

// ---------------- FFT (radix-2 DIF, 1024-pt) + top-8 per series ----------------
__global__ __launch_bounds__(256) void fft_topk_kernel(const float* __restrict__ x) {
    __shared__ float2 data[4][1024];
    __shared__ float2 tw[512];
    int tid = threadIdx.x;
    int b   = blockIdx.x >> 7;
    int d0  = (blockIdx.x & 127) << 2;

    for (int k = tid; k < 512; k += 256) {
        float s, c;
        sincosf(-6.283185307179586f * (float)k / 1024.0f, &s, &c);
        tw[k] = make_float2(c, s);
    }
    const float* xb = x + (size_t)b * Tn * Dn;
    for (int i = tid; i < 4096; i += 256) {
        int t = i >> 2, j = i & 3;
        data[j][t] = make_float2(xb[(size_t)t*Dn + d0 + j], 0.f);
    }
    __syncthreads();

    int tmul = 1;
    for (int half = 512; half >= 1; half >>= 1, tmul <<= 1) {
        for (int i = tid; i < 2048; i += 256) {
            int s  = i >> 9;
            int bf = i & 511;
            int k  = bf & (half - 1);
            int pos = 2*bf - k;
            float2 u = data[s][pos], v = data[s][pos + half];
            data[s][pos] = make_float2(u.x + v.x, u.y + v.y);
            float2 t2 = make_float2(u.x - v.x, u.y - v.y);
            float2 w  = tw[k * tmul];
            data[s][pos + half] = make_float2(t2.x*w.x - t2.y*w.y,
                                              t2.x*w.y + t2.y*w.x);
        }
        __syncthreads();
    }

    int wid = tid >> 5, lane = tid & 31;
    if (wid < 4) {
        int s = wid;
        int chosen[8];
#pragma unroll
        for (int q = 0; q < 8; q++) chosen[q] = -1;
#pragma unroll
        for (int it = 0; it < 8; it++) {
            float bestm = -1.f; int bestf = 1 << 20;
            for (int f = 1 + lane; f <= 511; f += 32) {
                bool used = false;
#pragma unroll
                for (int q = 0; q < 8; q++) used |= (chosen[q] == f);
                if (used) continue;
                int j = (int)(__brev((unsigned)f) >> 22);
                float2 v = data[s][j];
                float m2 = v.x*v.x + v.y*v.y;
                if (m2 > bestm || (m2 == bestm && f < bestf)) { bestm = m2; bestf = f; }
            }
            for (int off = 16; off; off >>= 1) {
                float om = __shfl_xor_sync(0xffffffffu, bestm, off);
                int   of = __shfl_xor_sync(0xffffffffu, bestf, off);
                if (om > bestm || (om == bestm && of < bestf)) { bestm = om; bestf = of; }
            }
            chosen[it] = bestf;
        }
        if (lane == 0) {
            int d = d0 + s;
#pragma unroll
            for (int it = 0; it < 8; it++) {
                int f = chosen[it];
                int j = (int)(__brev((unsigned)f) >> 22);
                float2 v = data[s][j];
                size_t o = ((size_t)b * Kn + it) * Dn + d;
                TK_M[o] = f; TK_RE[o] = v.x; TK_IM[o] = v.y;
            }
        }
    }
}

// ---------------- season reconstruction + res1 (f32 + half) ----------------
__global__ __launch_bounds__(256) void season_kernel(const float* __restrict__ res,
                                                     float* __restrict__ out) {
    __shared__ float ctab[1024];
    for (int j = threadIdx.x; j < 1024; j += 256)
        ctab[j] = cosf(6.283185307179586f / 1024.0f * (float)j);
    __syncthreads();

    int d  = blockIdx.x * 256 + threadIdx.x;
    int b  = blockIdx.y;
    int t0 = blockIdx.z * 112;

    int ms[8]; float re[8], im[8];
#pragma unroll
    for (int k = 0; k < 8; k++) {
        size_t o = ((size_t)b*Kn + k)*Dn + d;
        ms[k] = TK_M[o];
        re[k] = TK_RE[o] * (2.0f / (float)Tn);
        im[k] = TK_IM[o] * (2.0f / (float)Tn);
    }
    float*       seas = out + OFF_SEASON + (size_t)b*TP*Dn;
    const float* rb   = res + (size_t)b*Tn*Dn;
    float*       r1   = RES1  + (size_t)b*Tn*Dn;
    __half*      r1h  = RES1H + (size_t)b*Tn*Dn;

    for (int t = t0; t < t0 + 112; t++) {
        float acc = 0.f;
#pragma unroll
        for (int k = 0; k < 8; k++) {
            int idx = (ms[k]*t) & 1023;
            acc += re[k]*ctab[idx] - im[k]*ctab[(idx + 768) & 1023];
        }
        seas[(size_t)t*Dn + d] = acc;
        if (t < Tn) {
            float v = rb[(size_t)t*Dn + d] - acc;
            r1 [(size_t)t*Dn + d] = v;
            r1h[(size_t)t*Dn + d] = __float2half(v);
        }
    }
}

// ---------------- fp16 tensor-core GEMM, cp.async 3-stage ----------------
__device__ __forceinline__ void cp_async16(unsigned saddr, const void* gptr, bool valid) {
    int sz = valid ? 16 : 0;
    asm volatile("cp.async.cg.shared.global [%0], [%1], 16, %2;\n"
                 :: "r"(saddr), "l"(gptr), "r"(sz));
}

__global__ __launch_bounds__(256) void hgemm_kernel(const __half* __restrict__ A,
                                                    const __half* __restrict__ BT,  // [N][K]
                                                    float* __restrict__ C,
                                                    __half* __restrict__ CH,
                                                    int M, int N, int K,
                                                    int dogelu, int outhalf) {
    extern __shared__ __half smh[];
    __half* Ash = smh;                              // [STAGESH][128][APADH]
    __half* Bsh = smh + STAGESH * STG_HALFS;
    unsigned As_base = (unsigned)__cvta_generic_to_shared(Ash);
    unsigned Bs_base = (unsigned)__cvta_generic_to_shared(Bsh);

    int tid = threadIdx.x;
    int row0 = blockIdx.y * 128, col0 = blockIdx.x * 128;
    int wid = tid >> 5, lane = tid & 31;
    int wm = (wid & 1) * 64, wn = (wid >> 1) * 32;
    int g = lane >> 2, tg = lane & 3;

    float acc[4][4][4];
#pragma unroll
    for (int i = 0; i < 4; i++)
#pragma unroll
        for (int j = 0; j < 4; j++)
#pragma unroll
            for (int q = 0; q < 4; q++) acc[i][j][q] = 0.f;

    const int NT = K / BKH;

    // chunk layout: ch in [0,512): r = ch>>2, cq = ch&3 (cq*8 halfs = 16B)
    int ch0 = tid, ch1 = tid + 256;
    int ra0 = ch0 >> 2, ca0 = ch0 & 3;
    int ra1 = ch1 >> 2, ca1 = ch1 & 3;
    bool av0 = (row0 + ra0) < M, av1 = (row0 + ra1) < M;
    const __half* ag0 = A + (size_t)(row0 + ra0)*K + ca0*8;
    const __half* ag1 = A + (size_t)(row0 + ra1)*K + ca1*8;
    const __half* bg0 = BT + (size_t)(col0 + ra0)*K + ca0*8;
    const __half* bg1 = BT + (size_t)(col0 + ra1)*K + ca1*8;
    unsigned ad0 = (unsigned)(ra0*APADH + ca0*8)*2, ad1 = (unsigned)(ra1*APADH + ca1*8)*2;

#pragma unroll
    for (int s = 0; s < 2; s++) {
        unsigned ab = As_base + s*STG_HALFS*2, bb = Bs_base + s*STG_HALFS*2;
        int k0 = s * BKH;
        cp_async16(ab + ad0, ag0 + k0, av0);
        cp_async16(ab + ad1, ag1 + k0, av1);
        cp_async16(bb + ad0, bg0 + k0, true);
        cp_async16(bb + ad1, bg1 + k0, true);
        asm volatile("cp.async.commit_group;\n");
    }

    for (int it = 0; it < NT; it++) {
        if (it < NT - 1) asm volatile("cp.async.wait_group 1;\n");
        else             asm volatile("cp.async.wait_group 0;\n");
        __syncthreads();

        if (it + 2 < NT) {
            int s = (it + 2) % STAGESH, k0 = (it + 2) * BKH;
            unsigned ab = As_base + s*STG_HALFS*2, bb = Bs_base + s*STG_HALFS*2;
            cp_async16(ab + ad0, ag0 + k0, av0);
            cp_async16(ab + ad1, ag1 + k0, av1);
            cp_async16(bb + ad0, bg0 + k0, true);
            cp_async16(bb + ad1, bg1 + k0, true);
            asm volatile("cp.async.commit_group;\n");
        }

        const __half* Abuf = Ash + (it % STAGESH) * STG_HALFS;
        const __half* Bbuf = Bsh + (it % STAGESH) * STG_HALFS;

#pragma unroll
        for (int kk = 0; kk < BKH; kk += 16) {
            unsigned af[4][4], bf[4][2];
#pragma unroll
            for (int mt = 0; mt < 4; mt++) {
                int m = wm + mt*16 + g;
                af[mt][0] = *(const unsigned*)(Abuf + (m  )*APADH + kk + 2*tg);
                af[mt][1] = *(const unsigned*)(Abuf + (m+8)*APADH + kk + 2*tg);
                af[mt][2] = *(const unsigned*)(Abuf + (m  )*APADH + kk + 2*tg + 8);
                af[mt][3] = *(const unsigned*)(Abuf + (m+8)*APADH + kk + 2*tg + 8);
            }
#pragma unroll
            for (int nt = 0; nt < 4; nt++) {
                int n = wn + nt*8 + g;
                bf[nt][0] = *(const unsigned*)(Bbuf + n*APADH + kk + 2*tg);
                bf[nt][1] = *(const unsigned*)(Bbuf + n*APADH + kk + 2*tg + 8);
            }
#pragma unroll
            for (int mt = 0; mt < 4; mt++)
#pragma unroll
                for (int nt = 0; nt < 4; nt++)
                    asm volatile(
                        "mma.sync.aligned.m16n8k16.row.col.f32.f16.f16.f32 "
                        "{%0,%1,%2,%3}, {%4,%5,%6,%7}, {%8,%9}, {%0,%1,%2,%3};"
                        : "+f"(acc[mt][nt][0]), "+f"(acc[mt][nt][1]),
                          "+f"(acc[mt][nt][2]), "+f"(acc[mt][nt][3])
                        : "r"(af[mt][0]), "r"(af[mt][1]), "r"(af[mt][2]), "r"(af[mt][3]),
                          "r"(bf[nt][0]), "r"(bf[nt][1]));
        }
        __syncthreads();
    }

#pragma unroll
    for (int mt = 0; mt < 4; mt++) {
#pragma unroll
        for (int nt = 0; nt < 4; nt++) {
            int r0 = row0 + wm + mt*16 + g;
            int c  = col0 + wn + nt*8 + 2*tg;
            float v[4];
#pragma unroll
            for (int q = 0; q < 4; q++) {
                float u = acc[mt][nt][q];
                if (dogelu) u = 0.5f*u*(1.0f + erff(u*0.70710678118654752f));
                v[q] = u;
            }
            if (outhalf) {
                if (r0 < M)
                    *(__half2*)(CH + (size_t)r0*N + c) = __floats2half2_rn(v[0], v[1]);
                if (r0 + 8 < M)
                    *(__half2*)(CH + (size_t)(r0+8)*N + c) = __floats2half2_rn(v[2], v[3]);
            } else {
                if (r0 < M)     *(float2*)(C + (size_t)r0*N + c)     = make_float2(v[0], v[1]);
                if (r0 + 8 < M) *(float2*)(C + (size_t)(r0+8)*N + c) = make_float2(v[2], v[3]);
            }
        }
    }
}

// ---------------- growth EMA: blocked parallel scan ----------------
__global__ __launch_bounds__(256) void growth_passA(const float* __restrict__ sw,
                                                    const float* __restrict__ z0) {
    int gid = blockIdx.x*256 + threadIdx.x;
    int c = gid & 511;
    int r = gid >> 9;
    int b = r & 15, seg = r >> 4;
    float w = 1.f/(1.f + expf(-sw[c >> 6]));
    int t0 = seg * GSEGLEN;
    const float* vp = VBUF + (size_t)b*Tn*Dn + c;
    float prev = (t0 == 0) ? z0[c] : vp[(size_t)(t0-1)*Dn];
    float z = 0.f;
#pragma unroll 4
    for (int l = 0; l < GSEGLEN; l++) {
        float v = vp[(size_t)(t0+l)*Dn];
        z = w*z + (v - prev);
        prev = v;
    }
    GZ[(size_t)((b<<9)+c)*GSEG + seg] = z;
}

__global__ __launch_bounds__(256) void growth_carry(const float* __restrict__ sw,
                                                    const float* __restrict__ v0) {
    int ch = blockIdx.x*256 + threadIdx.x;
    int c = ch & 511;
    float w = 1.f/(1.f + expf(-sw[c >> 6]));
    float w64 = 1.f;
    { float p = w; int e = GSEGLEN; while (e) { if (e & 1) w64 *= p; p *= p; e >>= 1; } }
    float y = v0[c];
    float omw = 1.f - w;
#pragma unroll
    for (int seg = 0; seg < GSEG; seg++) {
        GCARRY[(size_t)ch*GSEG + seg] = y;
        y = w64*y + omw*GZ[(size_t)ch*GSEG + seg];
    }
}

// stores GBUFH as half (feeds only GEMM2)
__global__ __launch_bounds__(256) void growth_passB(const float* __restrict__ sw,
                                                    const float* __restrict__ z0,
                                                    const float* __restrict__ v0) {
    int gid = blockIdx.x*256 + threadIdx.x;
    int c = gid & 511;
    int r = gid >> 9;
    int b = r & 15, seg = r >> 4;
    float w = 1.f/(1.f + expf(-sw[c >> 6]));
    float omw = 1.f - w;
    int t0 = seg * GSEGLEN;
    const float* vp = VBUF + (size_t)b*Tn*Dn + c;
    __half*      gp = GBUFH + (size_t)b*T1*Dn + c;
    float prev = (t0 == 0) ? z0[c] : vp[(size_t)(t0-1)*Dn];
    float y = GCARRY[(size_t)((b<<9)+c)*GSEG + seg];
    if (seg == 0) gp[0] = __float2half(v0[c]);
#pragma unroll 4
    for (int l = 0; l < GSEGLEN; l++) {
        float v = vp[(size_t)(t0+l)*Dn];
        y = w*y + omw*(v - prev);
        prev = v;
        gp[(size_t)(t0+l+1)*Dn] = __float2half(y);
    }
}

// ---------------- layernorm helpers ----------------
__device__ __forceinline__ float block_reduce_sum(float v, float* red) {
    for (int o = 16; o; o >>= 1) v += __shfl_xor_sync(0xffffffffu, v, o);
    int wid = threadIdx.x >> 5;
    if ((threadIdx.x & 31) == 0) red[wid] = v;
    __syncthreads();
    if (threadIdx.x < 32) {
        float s = (threadIdx.x < 4) ? red[threadIdx.x] : 0.f;
        for (int o = 2; o; o >>= 1) s += __shfl_xor_sync(0xffffffffu, s, o);
        if (threadIdx.x == 0) red[0] = s;
    }
    __syncthreads();
    float r = red[0];
    __syncthreads();
    return r;
}

__global__ __launch_bounds__(128) void res2_kernel(const float* __restrict__ out_all,
                                                   const float* __restrict__ ng,
                                                   const float* __restrict__ nb) {
    __shared__ float red[32];
    int r = blockIdx.x;
    int b = r >> 10, t = r & 1023;
    const float* x1 = RES1 + (size_t)r*Dn;
    const float* gw = out_all + OFF_GROWTH + (size_t)(b*T1 + t + 1)*Dn;
    float vals[4]; float s = 0.f;
#pragma unroll
    for (int i = 0; i < 4; i++) {
        int d = threadIdx.x + i*128;
        vals[i] = x1[d] - gw[d];
        s += vals[i];
    }
    float mu = block_reduce_sum(s, red) * (1.0f/512.0f);
    float vs = 0.f;
#pragma unroll
    for (int i = 0; i < 4; i++) { float c = vals[i]-mu; vs += c*c; }
    float var = block_reduce_sum(vs, red) * (1.0f/512.0f);
    float inv = rsqrtf(var + 1e-5f);
#pragma unroll
    for (int i = 0; i < 4; i++) {
        int d = threadIdx.x + i*128;
        float v = (vals[i]-mu)*inv*ng[d] + nb[d];
        R2B [(size_t)r*Dn + d] = v;
        R2BH[(size_t)r*Dn + d] = __float2half(v);
    }
}

__global__ __launch_bounds__(128) void res3_kernel(float* __restrict__ out_all,
                                                   const float* __restrict__ ng,
                                                   const float* __restrict__ nb) {
    __shared__ float red[32];
    int r = blockIdx.x;
    float vals[4]; float s = 0.f;
#pragma unroll
    for (int i = 0; i < 4; i++) {
        int d = threadIdx.x + i*128;
        vals[i] = R2B[(size_t)r*Dn + d] + FOUT[(size_t)r*Dn + d];
        s += vals[i];
    }
    float mu = block_reduce_sum(s, red) * (1.0f/512.0f);
    float vs = 0.f;
#pragma unroll
    for (int i = 0; i < 4; i++) { float c = vals[i]-mu; vs += c*c; }
    float var = block_reduce_sum(vs, red) * (1.0f/512.0f);
    float inv = rsqrtf(var + 1e-5f);
#pragma unroll
    for (int i = 0; i < 4; i++) {
        int d = threadIdx.x + i*128;
        out_all[OFF_RES3 + (size_t)r*Dn + d] = (vals[i]-mu)*inv*ng[d] + nb[d];
    }
}

// ---------------- level projections ----------------
__global__ __launch_bounds__(256) void levelproj_kernel(const float* __restrict__ out_all,
                                                        const float* __restrict__ gpw,
                                                        const float* __restrict__ spw) {
    int warp = (blockIdx.x*256 + threadIdx.x) >> 5;
    int lane = threadIdx.x & 31;
    if (warp >= Bn*Tn) return;
    int b = warp >> 10, t = warp & 1023;
    const float* gr = out_all + OFF_GROWTH + (size_t)(b*T1 + t)*Dn;
    const float* se = out_all + OFF_SEASON + (size_t)(b*TP + t)*Dn;
    float ag[7] = {}, as_[7] = {};
    for (int d = lane; d < 512; d += 32) {
        float g = gr[d], s = se[d];
#pragma unroll
        for (int c = 0; c < 7; c++) { ag[c] += g*gpw[d*7+c]; as_[c] += s*spw[d*7+c]; }
    }
#pragma unroll
    for (int c = 0; c < 7; c++) {
        for (int o = 16; o; o >>= 1) {
            ag[c]  += __shfl_xor_sync(0xffffffffu, ag[c],  o);
            as_[c] += __shfl_xor_sync(0xffffffffu, as_[c], o);
        }
    }
    if (lane == 0) {
#pragma unroll
        for (int c = 0; c < 7; c++) {
            GS_G[(size_t)warp*7 + c] = ag[c];
            GS_S[(size_t)warp*7 + c] = as_[c];
        }
    }
}

// ---------------- level EMA: blocked parallel scan ----------------
__global__ void level_passA(const float* __restrict__ level,
                            const float* __restrict__ lsw) {
    int gid = blockIdx.x*blockDim.x + threadIdx.x;
    if (gid >= Bn*COUTn*GSEG) return;
    int ch = gid % (Bn*COUTn), seg = gid / (Bn*COUTn);
    int b = ch / COUTn, c = ch % COUTn;
    float w = 1.f/(1.f + expf(-lsw[c]));
    float omw = 1.f - w;
    int t0 = seg * GSEGLEN;
    const float* lp = level + (size_t)b*Tn*COUTn + c;
    const float* gp = GS_G  + (size_t)b*Tn*COUTn + c;
    const float* sp = GS_S  + (size_t)b*Tn*COUTn + c;
    float z = 0.f;
    for (int l = 0; l < GSEGLEN; l++) {
        int t = t0 + l;
        float u = omw*(lp[t*COUTn] - sp[t*COUTn]) + w*gp[t*COUTn];
        z = w*z + u;
    }
    LZ[(size_t)ch*GSEG + seg] = z;
}

__global__ void level_carry(const float* __restrict__ lsw,
                            const float* __restrict__ lv0) {
    int ch = threadIdx.x;
    if (ch >= Bn*COUTn) return;
    int c = ch % COUTn;
    float w = 1.f/(1.f + expf(-lsw[c]));
    float w64 = 1.f;
    { float p = w; int e = GSEGLEN; while (e) { if (e & 1) w64 *= p; p *= p; e >>= 1; } }
    float y = lv0[c];
#pragma unroll
    for (int seg = 0; seg < GSEG; seg++) {
        LCARRY[(size_t)ch*GSEG + seg] = y;
        y = w64*y + LZ[(size_t)ch*GSEG + seg];
    }
}

__global__ void level_passB(const float* __restrict__ level,
                            const float* __restrict__ lsw,
                            float* __restrict__ out_all) {
    int gid = blockIdx.x*blockDim.x + threadIdx.x;
    if (gid >= Bn*COUTn*GSEG) return;
    int ch = gid % (Bn*COUTn), seg = gid / (Bn*COUTn);
    int b = ch / COUTn, c = ch % COUTn;
    float w = 1.f/(1.f + expf(-lsw[c]));
    float omw = 1.f - w;
    int t0 = seg * GSEGLEN;
    const float* lp = level + (size_t)b*Tn*COUTn + c;
    const float* gp = GS_G  + (size_t)b*Tn*COUTn + c;
    const float* sp = GS_S  + (size_t)b*Tn*COUTn + c;
    float* op = out_all + OFF_LEVEL + (size_t)b*Tn*COUTn + c;
    float y = LCARRY[(size_t)ch*GSEG + seg];
    for (int l = 0; l < GSEGLEN; l++) {
        int t = t0 + l;
        float u = omw*(lp[t*COUTn] - sp[t*COUTn]) + w*gp[t*COUTn];
        y = w*y + u;
        op[t*COUTn] = y;
    }
}

// ---------------- launch ----------------
extern "C" void kernel_launch(void* const* d_in, const int* in_sizes, int n_in,
                              void* d_out, int out_size) {
    const float* res      = (const float*)d_in[0];
    const float* level    = (const float*)d_in[1];
    const float* in_w     = (const float*)d_in[2];
    const float* out_w    = (const float*)d_in[3];
    const float* z0       = (const float*)d_in[4];
    const float* gsw      = (const float*)d_in[5];
    const float* gv0      = (const float*)d_in[6];
    const float* ff_w1    = (const float*)d_in[7];
    const float* ff_w2    = (const float*)d_in[8];
    const float* n1g      = (const float*)d_in[9];
    const float* n1b      = (const float*)d_in[10];
    const float* n2g      = (const float*)d_in[11];
    const float* n2b      = (const float*)d_in[12];
    const float* gpw      = (const float*)d_in[13];
    const float* spw      = (const float*)d_in[14];
    const float* lsw      = (const float*)d_in[15];
    const float* lv0      = (const float*)d_in[16];
    float* out = (float*)d_out;

    float *pVBUF, *pFOUT;
    __half *pRES1H, *pGBUFH, *pR2H, *pFBUFH, *pWTIN, *pWTOUT, *pWT1, *pWT2;
    cudaGetSymbolAddress((void**)&pVBUF,  VBUF);
    cudaGetSymbolAddress((void**)&pFOUT,  FOUT);
    cudaGetSymbolAddress((void**)&pRES1H, RES1H);
    cudaGetSymbolAddress((void**)&pGBUFH, GBUFH);
    cudaGetSymbolAddress((void**)&pR2H,   R2BH);
    cudaGetSymbolAddress((void**)&pFBUFH, FBUFH);
    cudaGetSymbolAddress((void**)&pWTIN,  WT_IN);
    cudaGetSymbolAddress((void**)&pWTOUT, WT_OUT);
    cudaGetSymbolAddress((void**)&pWT1,   WT_1);
    cudaGetSymbolAddress((void**)&pWT2,   WT_2);

    static int attr_set = 0;
    if (!attr_set) {
        cudaFuncSetAttribute(hgemm_kernel,
                             cudaFuncAttributeMaxDynamicSharedMemorySize, HS_TOTAL);
        attr_set = 1;
    }

    // 0) weights: transpose + half -> [N][K]
    transpose_half<<<dim3(Dn/32, Dn/32), 256>>>(in_w,  pWTIN,  Dn, Dn);
    transpose_half<<<dim3(Dn/32, Dn/32), 256>>>(out_w, pWTOUT, Dn, Dn);
    transpose_half<<<dim3(LATENTn/32, Dn/32), 256>>>(ff_w1, pWT1, Dn, LATENTn);
    transpose_half<<<dim3(Dn/32, LATENTn/32), 256>>>(ff_w2, pWT2, LATENTn, Dn);

    // 1) FFT + top-k
    fft_topk_kernel<<<Bn*(Dn/4), 256>>>(res);
    // 2) season + res1 (f32 + half)
    season_kernel<<<dim3(2, Bn, 10), 256>>>(res, out);
    // 3) v = res1 @ in_proj_w  (f32 out for scan)
    hgemm_kernel<<<dim3(Dn/128, (Bn*Tn)/128), 256, HS_TOTAL>>>(pRES1H, pWTIN,
                                                               pVBUF, 0,
                                                               Bn*Tn, Dn, Dn, 0, 0);
    // 4) diffs + EMA (blocked scan) -> GBUFH half
    growth_passA<<<(Bn*Dn*GSEG)/256, 256>>>(gsw, z0);
    growth_carry<<<(Bn*Dn)/256, 256>>>(gsw, gv0);
    growth_passB<<<(Bn*Dn*GSEG)/256, 256>>>(gsw, z0, gv0);
    // 5) growth = GBUFH @ out_proj_w -> d_out (f32)
    hgemm_kernel<<<dim3(Dn/128, (Bn*T1 + 127)/128), 256, HS_TOTAL>>>(pGBUFH, pWTOUT,
                                                                     out + OFF_GROWTH, 0,
                                                                     Bn*T1, Dn, Dn, 0, 0);
    // 6) res2 = LN(res1 - growth[:,1:]) (f32 + half)
    res2_kernel<<<Bn*Tn, 128>>>(out, n1g, n1b);
    // 7) ffn1 = gelu(res2 @ ff_w1) -> half FBUFH
    hgemm_kernel<<<dim3(LATENTn/128, (Bn*Tn)/128), 256, HS_TOTAL>>>(pR2H, pWT1,
                                                                    0, pFBUFH,
                                                                    Bn*Tn, LATENTn, Dn, 1, 1);
    // 8) ffn2 = ffn1 @ ff_w2 -> f32 FOUT
    hgemm_kernel<<<dim3(Dn/128, (Bn*Tn)/128), 256, HS_TOTAL>>>(pFBUFH, pWT2,
                                                               pFOUT, 0,
                                                               Bn*Tn, Dn, LATENTn, 0, 0);
    // 9) res3 = LN(res2 + ffn2) -> d_out
    res3_kernel<<<Bn*Tn, 128>>>(out, n2g, n2b);
    // 10) level projections
    levelproj_kernel<<<(Bn*Tn*32)/256, 256>>>(out, gpw, spw);
    // 11) level EMA (blocked scan) -> d_out
    level_passA<<<(Bn*COUTn*GSEG + 255)/256, 256>>>(level, lsw);
    level_carry<<<1, 128>>>(lsw, lv0);
    level_passB<<<(Bn*COUTn*GSEG + 255)/256, 256>>>(level, lsw, out);
}

// round 9
// speedup vs baseline: 2.0462x; 1.1316x over previous
#include <cuda_runtime.h>
#include <cuda_fp16.h>
#include <math.h>
#include <stdint.h>

#define Bn 16
#define Tn 1024
#define Dn 512
#define COUTn 7
#define PREDn 96
#define Kn 8
#define LATENTn 2048
#define TP (Tn + PREDn)
#define T1 (Tn + 1)

#define OFF_RES3   0
#define OFF_LEVEL  (Bn*Tn*Dn)
#define OFF_GROWTH (OFF_LEVEL + Bn*Tn*COUTn)
#define OFF_SEASON (OFF_GROWTH + Bn*T1*Dn)

#define GSEG 16
#define GSEGLEN 64

// fp16 GEMM tiling
#define STAGESH 3
#define BKH 32
#define APADH 40                   /* 80B rows, 16B-aligned */
#define STG_HALFS (128*APADH)
#define HS_TOTAL (STAGESH*2*STG_HALFS*2)   /* 61440 B */

// ---------------- scratch ----------------
__device__ float RES1 [Bn*Tn*Dn];
__device__ __align__(256) __half RES1H[Bn*Tn*Dn];
__device__ float VBUF[Bn*Tn*Dn];
__device__ __align__(256) __half GBUFH[Bn*T1*Dn];
__device__ float R2B [Bn*Tn*Dn];
__device__ __align__(256) __half R2BH[Bn*Tn*Dn];
__device__ __align__(256) __half FBUFH[Bn*Tn*LATENTn];
__device__ float FOUT[Bn*Tn*Dn];
__device__ __align__(256) __half WT_IN [Dn*Dn];
__device__ __align__(256) __half WT_OUT[Dn*Dn];
__device__ __align__(256) __half WT_1  [LATENTn*Dn];
__device__ __align__(256) __half WT_2  [Dn*LATENTn];
__device__ float GS_G[Bn*Tn*COUTn];
__device__ float GS_S[Bn*Tn*COUTn];
__device__ float GZ    [Bn*Dn*GSEG];
__device__ float GCARRY[Bn*Dn*GSEG];
__device__ float LZ    [Bn*COUTn*GSEG];
__device__ float LCARRY[Bn*COUTn*GSEG];

// ---------------- fused transpose of all 4 weight matrices ----------------
__global__ __launch_bounds__(256) void transpose4(const float* __restrict__ s0, __half* __restrict__ d0p,
                                                  const float* __restrict__ s1, __half* __restrict__ d1p,
                                                  const float* __restrict__ s2, __half* __restrict__ d2p,
                                                  const float* __restrict__ s3, __half* __restrict__ d3p) {
    __shared__ float t[32][33];
    int id = blockIdx.x;
    const float* src; __half* dst; int R, C, bx, by;
    if (id < 256)       { src = s0; dst = d0p; R = Dn;      C = Dn;      bx = id & 15;        by = id >> 4; }
    else if (id < 512)  { id -= 256;  src = s1; dst = d1p; R = Dn;      C = Dn;      bx = id & 15; by = id >> 4; }
    else if (id < 1536) { id -= 512;  src = s2; dst = d2p; R = Dn;      C = LATENTn; bx = id & 63; by = id >> 6; }
    else                { id -= 1536; src = s3; dst = d3p; R = LATENTn; C = Dn;      bx = id & 15; by = id >> 4; }
    int tx = threadIdx.x & 31, ty = threadIdx.x >> 5;
    int c0 = bx*32, r0 = by*32;
#pragma unroll
    for (int i = 0; i < 4; i++)
        t[ty + i*8][tx] = src[(size_t)(r0 + ty + i*8)*C + c0 + tx];
    __syncthreads();
#pragma unroll
    for (int i = 0; i < 4; i++)
        dst[(size_t)(c0 + ty + i*8)*R + r0 + tx] = __float2half(t[tx][ty + i*8]);
}

// ---------------- fused FFT + top-8 + season + res1 ----------------
__global__ __launch_bounds__(256) void fftseason_kernel(const float* __restrict__ x,
                                                        float* __restrict__ out) {
    __shared__ float2 data[4][1024];   // 32 KB
    __shared__ float2 tw[512];         // 4 KB
    __shared__ float  mag[4][512];     // 8 KB, recycled as cos table later
    __shared__ int    chm[4][8];
    __shared__ float  chre[4][8], chim[4][8];

    int tid = threadIdx.x;
    int b   = blockIdx.x >> 7;
    int d0  = (blockIdx.x & 127) << 2;

    for (int k = tid; k < 512; k += 256) {
        float s, c;
        sincosf(-6.283185307179586f * (float)k / 1024.0f, &s, &c);
        tw[k] = make_float2(c, s);
    }
    const float* xb = x + (size_t)b * Tn * Dn;
    for (int i = tid; i < 4096; i += 256) {
        int t = i >> 2, j = i & 3;
        data[j][t] = make_float2(xb[(size_t)t*Dn + d0 + j], 0.f);
    }
    __syncthreads();

    int tmul = 1;
    for (int half = 512; half >= 1; half >>= 1, tmul <<= 1) {
        for (int i = tid; i < 2048; i += 256) {
            int s  = i >> 9;
            int bf = i & 511;
            int k  = bf & (half - 1);
            int pos = 2*bf - k;
            float2 u = data[s][pos], v = data[s][pos + half];
            data[s][pos] = make_float2(u.x + v.x, u.y + v.y);
            float2 t2 = make_float2(u.x - v.x, u.y - v.y);
            float2 w  = tw[k * tmul];
            data[s][pos + half] = make_float2(t2.x*w.x - t2.y*w.y,
                                              t2.x*w.y + t2.y*w.x);
        }
        __syncthreads();
    }
    // X[f] at data[s][brev10(f)]

    // magnitudes
    for (int i = tid; i < 2048; i += 256) {
        int s = i >> 9, f = i & 511;
        if (f == 0) { mag[s][0] = -1e30f; continue; }
        int j = (int)(__brev((unsigned)f) >> 22);
        float2 v = data[s][j];
        mag[s][f] = v.x*v.x + v.y*v.y;
    }
    __syncthreads();

    int wid = tid >> 5, lane = tid & 31;
    if (wid < 4) {
        int s = wid;
#pragma unroll
        for (int it = 0; it < 8; it++) {
            float bestm = -1e29f; int bestf = 1 << 20;
            for (int f = lane; f < 512; f += 32) {
                float m2 = mag[s][f];
                if (m2 > bestm || (m2 == bestm && f < bestf)) { bestm = m2; bestf = f; }
            }
            for (int off = 16; off; off >>= 1) {
                float om = __shfl_xor_sync(0xffffffffu, bestm, off);
                int   of = __shfl_xor_sync(0xffffffffu, bestf, off);
                if (om > bestm || (om == bestm && of < bestf)) { bestm = om; bestf = of; }
            }
            if (lane == 0) {
                int j = (int)(__brev((unsigned)bestf) >> 22);
                float2 v = data[s][j];
                chm [s][it] = bestf;
                chre[s][it] = v.x * (2.0f / (float)Tn);
                chim[s][it] = v.y * (2.0f / (float)Tn);
                mag[s][bestf] = -1e30f;
            }
            __syncwarp();
        }
    }
    __syncthreads();

    // recycle mag[] as 1024-entry cos table
    float* ctab = &mag[0][0];
    for (int j = tid; j < 1024; j += 256)
        ctab[j] = (j < 512) ? tw[j].x : -tw[j - 512].x;
    __syncthreads();

    // season reconstruction: thread handles series s = tid&3, t strided by 64
    {
        int s = tid & 3;
        int ms[8]; float re[8], im[8];
#pragma unroll
        for (int k = 0; k < 8; k++) { ms[k] = chm[s][k]; re[k] = chre[s][k]; im[k] = chim[s][k]; }
        int d = d0 + s;
        float*       seas = out + OFF_SEASON + (size_t)b*TP*Dn + d;
        const float* rb   = x + (size_t)b*Tn*Dn + d;
        float*       r1   = RES1  + (size_t)b*Tn*Dn + d;
        __half*      r1h  = RES1H + (size_t)b*Tn*Dn + d;
        for (int t = tid >> 2; t < TP; t += 64) {
            float acc = 0.f;
#pragma unroll
            for (int k = 0; k < 8; k++) {
                int idx = (ms[k]*t) & 1023;
                acc += re[k]*ctab[idx] - im[k]*ctab[(idx + 768) & 1023];
            }
            seas[(size_t)t*Dn] = acc;
            if (t < Tn) {
                float v = rb[(size_t)t*Dn] - acc;
                r1 [(size_t)t*Dn] = v;
                r1h[(size_t)t*Dn] = __float2half(v);
            }
        }
    }
}

// ---------------- fp16 tensor-core GEMM, cp.async 3-stage ----------------
__device__ __forceinline__ void cp_async16(unsigned saddr, const void* gptr, bool valid) {
    int sz = valid ? 16 : 0;
    asm volatile("cp.async.cg.shared.global [%0], [%1], 16, %2;\n"
                 :: "r"(saddr), "l"(gptr), "r"(sz));
}

__global__ __launch_bounds__(256) void hgemm_kernel(const __half* __restrict__ A,
                                                    const __half* __restrict__ BT,
                                                    float* __restrict__ C,
                                                    __half* __restrict__ CH,
                                                    int M, int N, int K,
                                                    int dogelu, int outhalf) {
    extern __shared__ __half smh[];
    __half* Ash = smh;
    __half* Bsh = smh + STAGESH * STG_HALFS;
    unsigned As_base = (unsigned)__cvta_generic_to_shared(Ash);
    unsigned Bs_base = (unsigned)__cvta_generic_to_shared(Bsh);

    int tid = threadIdx.x;
    int row0 = blockIdx.y * 128, col0 = blockIdx.x * 128;
    int wid = tid >> 5, lane = tid & 31;
    int wm = (wid & 1) * 64, wn = (wid >> 1) * 32;
    int g = lane >> 2, tg = lane & 3;

    float acc[4][4][4];
#pragma unroll
    for (int i = 0; i < 4; i++)
#pragma unroll
        for (int j = 0; j < 4; j++)
#pragma unroll
            for (int q = 0; q < 4; q++) acc[i][j][q] = 0.f;

    const int NT = K / BKH;

    int ch0 = tid, ch1 = tid + 256;
    int ra0 = ch0 >> 2, ca0 = ch0 & 3;
    int ra1 = ch1 >> 2, ca1 = ch1 & 3;
    bool av0 = (row0 + ra0) < M, av1 = (row0 + ra1) < M;
    const __half* ag0 = A + (size_t)(row0 + ra0)*K + ca0*8;
    const __half* ag1 = A + (size_t)(row0 + ra1)*K + ca1*8;
    const __half* bg0 = BT + (size_t)(col0 + ra0)*K + ca0*8;
    const __half* bg1 = BT + (size_t)(col0 + ra1)*K + ca1*8;
    unsigned ad0 = (unsigned)(ra0*APADH + ca0*8)*2, ad1 = (unsigned)(ra1*APADH + ca1*8)*2;

#pragma unroll
    for (int s = 0; s < 2; s++) {
        unsigned ab = As_base + s*STG_HALFS*2, bb = Bs_base + s*STG_HALFS*2;
        int k0 = s * BKH;
        cp_async16(ab + ad0, ag0 + k0, av0);
        cp_async16(ab + ad1, ag1 + k0, av1);
        cp_async16(bb + ad0, bg0 + k0, true);
        cp_async16(bb + ad1, bg1 + k0, true);
        asm volatile("cp.async.commit_group;\n");
    }

    for (int it = 0; it < NT; it++) {
        if (it < NT - 1) asm volatile("cp.async.wait_group 1;\n");
        else             asm volatile("cp.async.wait_group 0;\n");
        __syncthreads();

        if (it + 2 < NT) {
            int s = (it + 2) % STAGESH, k0 = (it + 2) * BKH;
            unsigned ab = As_base + s*STG_HALFS*2, bb = Bs_base + s*STG_HALFS*2;
            cp_async16(ab + ad0, ag0 + k0, av0);
            cp_async16(ab + ad1, ag1 + k0, av1);
            cp_async16(bb + ad0, bg0 + k0, true);
            cp_async16(bb + ad1, bg1 + k0, true);
            asm volatile("cp.async.commit_group;\n");
        }

        const __half* Abuf = Ash + (it % STAGESH) * STG_HALFS;
        const __half* Bbuf = Bsh + (it % STAGESH) * STG_HALFS;

#pragma unroll
        for (int kk = 0; kk < BKH; kk += 16) {
            unsigned af[4][4], bf[4][2];
#pragma unroll
            for (int mt = 0; mt < 4; mt++) {
                int m = wm + mt*16 + g;
                af[mt][0] = *(const unsigned*)(Abuf + (m  )*APADH + kk + 2*tg);
                af[mt][1] = *(const unsigned*)(Abuf + (m+8)*APADH + kk + 2*tg);
                af[mt][2] = *(const unsigned*)(Abuf + (m  )*APADH + kk + 2*tg + 8);
                af[mt][3] = *(const unsigned*)(Abuf + (m+8)*APADH + kk + 2*tg + 8);
            }
#pragma unroll
            for (int nt = 0; nt < 4; nt++) {
                int n = wn + nt*8 + g;
                bf[nt][0] = *(const unsigned*)(Bbuf + n*APADH + kk + 2*tg);
                bf[nt][1] = *(const unsigned*)(Bbuf + n*APADH + kk + 2*tg + 8);
            }
#pragma unroll
            for (int mt = 0; mt < 4; mt++)
#pragma unroll
                for (int nt = 0; nt < 4; nt++)
                    asm volatile(
                        "mma.sync.aligned.m16n8k16.row.col.f32.f16.f16.f32 "
                        "{%0,%1,%2,%3}, {%4,%5,%6,%7}, {%8,%9}, {%0,%1,%2,%3};"
                        : "+f"(acc[mt][nt][0]), "+f"(acc[mt][nt][1]),
                          "+f"(acc[mt][nt][2]), "+f"(acc[mt][nt][3])
                        : "r"(af[mt][0]), "r"(af[mt][1]), "r"(af[mt][2]), "r"(af[mt][3]),
                          "r"(bf[nt][0]), "r"(bf[nt][1]));
        }
        __syncthreads();
    }

#pragma unroll
    for (int mt = 0; mt < 4; mt++) {
#pragma unroll
        for (int nt = 0; nt < 4; nt++) {
            int r0 = row0 + wm + mt*16 + g;
            int c  = col0 + wn + nt*8 + 2*tg;
            float v[4];
#pragma unroll
            for (int q = 0; q < 4; q++) {
                float u = acc[mt][nt][q];
                if (dogelu) u = 0.5f*u*(1.0f + erff(u*0.70710678118654752f));
                v[q] = u;
            }
            if (outhalf) {
                if (r0 < M)
                    *(__half2*)(CH + (size_t)r0*N + c) = __floats2half2_rn(v[0], v[1]);
                if (r0 + 8 < M)
                    *(__half2*)(CH + (size_t)(r0+8)*N + c) = __floats2half2_rn(v[2], v[3]);
            } else {
                if (r0 < M)     *(float2*)(C + (size_t)r0*N + c)     = make_float2(v[0], v[1]);
                if (r0 + 8 < M) *(float2*)(C + (size_t)(r0+8)*N + c) = make_float2(v[2], v[3]);
            }
        }
    }
}

// ---------------- growth EMA: blocked parallel scan ----------------
__global__ __launch_bounds__(256) void growth_passA(const float* __restrict__ sw,
                                                    const float* __restrict__ z0) {
    int gid = blockIdx.x*256 + threadIdx.x;
    int c = gid & 511;
    int r = gid >> 9;
    int b = r & 15, seg = r >> 4;
    float w = 1.f/(1.f + expf(-sw[c >> 6]));
    int t0 = seg * GSEGLEN;
    const float* vp = VBUF + (size_t)b*Tn*Dn + c;
    float prev = (t0 == 0) ? z0[c] : vp[(size_t)(t0-1)*Dn];
    float z = 0.f;
#pragma unroll 4
    for (int l = 0; l < GSEGLEN; l++) {
        float v = vp[(size_t)(t0+l)*Dn];
        z = w*z + (v - prev);
        prev = v;
    }
    GZ[(size_t)((b<<9)+c)*GSEG + seg] = z;
}

__global__ __launch_bounds__(256) void growth_carry(const float* __restrict__ sw,
                                                    const float* __restrict__ v0) {
    int ch = blockIdx.x*256 + threadIdx.x;
    int c = ch & 511;
    float w = 1.f/(1.f + expf(-sw[c >> 6]));
    float w64 = 1.f;
    { float p = w; int e = GSEGLEN; while (e) { if (e & 1) w64 *= p; p *= p; e >>= 1; } }
    float y = v0[c];
    float omw = 1.f - w;
#pragma unroll
    for (int seg = 0; seg < GSEG; seg++) {
        GCARRY[(size_t)ch*GSEG + seg] = y;
        y = w64*y + omw*GZ[(size_t)ch*GSEG + seg];
    }
}

__global__ __launch_bounds__(256) void growth_passB(const float* __restrict__ sw,
                                                    const float* __restrict__ z0,
                                                    const float* __restrict__ v0) {
    int gid = blockIdx.x*256 + threadIdx.x;
    int c = gid & 511;
    int r = gid >> 9;
    int b = r & 15, seg = r >> 4;
    float w = 1.f/(1.f + expf(-sw[c >> 6]));
    float omw = 1.f - w;
    int t0 = seg * GSEGLEN;
    const float* vp = VBUF + (size_t)b*Tn*Dn + c;
    __half*      gp = GBUFH + (size_t)b*T1*Dn + c;
    float prev = (t0 == 0) ? z0[c] : vp[(size_t)(t0-1)*Dn];
    float y = GCARRY[(size_t)((b<<9)+c)*GSEG + seg];
    if (seg == 0) gp[0] = __float2half(v0[c]);
#pragma unroll 4
    for (int l = 0; l < GSEGLEN; l++) {
        float v = vp[(size_t)(t0+l)*Dn];
        y = w*y + omw*(v - prev);
        prev = v;
        gp[(size_t)(t0+l+1)*Dn] = __float2half(y);
    }
}

// ---------------- layernorm helpers ----------------
__device__ __forceinline__ float block_reduce_sum(float v, float* red) {
    for (int o = 16; o; o >>= 1) v += __shfl_xor_sync(0xffffffffu, v, o);
    int wid = threadIdx.x >> 5;
    if ((threadIdx.x & 31) == 0) red[wid] = v;
    __syncthreads();
    if (threadIdx.x < 32) {
        float s = (threadIdx.x < 4) ? red[threadIdx.x] : 0.f;
        for (int o = 2; o; o >>= 1) s += __shfl_xor_sync(0xffffffffu, s, o);
        if (threadIdx.x == 0) red[0] = s;
    }
    __syncthreads();
    float r = red[0];
    __syncthreads();
    return r;
}

__global__ __launch_bounds__(128) void res2_kernel(const float* __restrict__ out_all,
                                                   const float* __restrict__ ng,
                                                   const float* __restrict__ nb) {
    __shared__ float red[32];
    int r = blockIdx.x;
    int b = r >> 10, t = r & 1023;
    const float* x1 = RES1 + (size_t)r*Dn;
    const float* gw = out_all + OFF_GROWTH + (size_t)(b*T1 + t + 1)*Dn;
    float vals[4]; float s = 0.f;
#pragma unroll
    for (int i = 0; i < 4; i++) {
        int d = threadIdx.x + i*128;
        vals[i] = x1[d] - gw[d];
        s += vals[i];
    }
    float mu = block_reduce_sum(s, red) * (1.0f/512.0f);
    float vs = 0.f;
#pragma unroll
    for (int i = 0; i < 4; i++) { float c = vals[i]-mu; vs += c*c; }
    float var = block_reduce_sum(vs, red) * (1.0f/512.0f);
    float inv = rsqrtf(var + 1e-5f);
#pragma unroll
    for (int i = 0; i < 4; i++) {
        int d = threadIdx.x + i*128;
        float v = (vals[i]-mu)*inv*ng[d] + nb[d];
        R2B [(size_t)r*Dn + d] = v;
        R2BH[(size_t)r*Dn + d] = __float2half(v);
    }
}

__global__ __launch_bounds__(128) void res3_kernel(float* __restrict__ out_all,
                                                   const float* __restrict__ ng,
                                                   const float* __restrict__ nb) {
    __shared__ float red[32];
    int r = blockIdx.x;
    float vals[4]; float s = 0.f;
#pragma unroll
    for (int i = 0; i < 4; i++) {
        int d = threadIdx.x + i*128;
        vals[i] = R2B[(size_t)r*Dn + d] + FOUT[(size_t)r*Dn + d];
        s += vals[i];
    }
    float mu = block_reduce_sum(s, red) * (1.0f/512.0f);
    float vs = 0.f;
#pragma unroll
    for (int i = 0; i < 4; i++) { float c = vals[i]-mu; vs += c*c; }
    float var = block_reduce_sum(vs, red) * (1.0f/512.0f);
    float inv = rsqrtf(var + 1e-5f);
#pragma unroll
    for (int i = 0; i < 4; i++) {
        int d = threadIdx.x + i*128;
        out_all[OFF_RES3 + (size_t)r*Dn + d] = (vals[i]-mu)*inv*ng[d] + nb[d];
    }
}

// ---------------- level projections ----------------
__global__ __launch_bounds__(256) void levelproj_kernel(const float* __restrict__ out_all,
                                                        const float* __restrict__ gpw,
                                                        const float* __restrict__ spw) {
    int warp = (blockIdx.x*256 + threadIdx.x) >> 5;
    int lane = threadIdx.x & 31;
    if (warp >= Bn*Tn) return;
    int b = warp >> 10, t = warp & 1023;
    const float* gr = out_all + OFF_GROWTH + (size_t)(b*T1 + t)*Dn;
    const float* se = out_all + OFF_SEASON + (size_t)(b*TP + t)*Dn;
    float ag[7] = {}, as_[7] = {};
    for (int d = lane; d < 512; d += 32) {
        float g = gr[d], s = se[d];
#pragma unroll
        for (int c = 0; c < 7; c++) { ag[c] += g*gpw[d*7+c]; as_[c] += s*spw[d*7+c]; }
    }
#pragma unroll
    for (int c = 0; c < 7; c++) {
        for (int o = 16; o; o >>= 1) {
            ag[c]  += __shfl_xor_sync(0xffffffffu, ag[c],  o);
            as_[c] += __shfl_xor_sync(0xffffffffu, as_[c], o);
        }
    }
    if (lane == 0) {
#pragma unroll
        for (int c = 0; c < 7; c++) {
            GS_G[(size_t)warp*7 + c] = ag[c];
            GS_S[(size_t)warp*7 + c] = as_[c];
        }
    }
}

// ---------------- level EMA: blocked parallel scan ----------------
__global__ void level_passA(const float* __restrict__ level,
                            const float* __restrict__ lsw) {
    int gid = blockIdx.x*blockDim.x + threadIdx.x;
    if (gid >= Bn*COUTn*GSEG) return;
    int ch = gid % (Bn*COUTn), seg = gid / (Bn*COUTn);
    int b = ch / COUTn, c = ch % COUTn;
    float w = 1.f/(1.f + expf(-lsw[c]));
    float omw = 1.f - w;
    int t0 = seg * GSEGLEN;
    const float* lp = level + (size_t)b*Tn*COUTn + c;
    const float* gp = GS_G  + (size_t)b*Tn*COUTn + c;
    const float* sp = GS_S  + (size_t)b*Tn*COUTn + c;
    float z = 0.f;
    for (int l = 0; l < GSEGLEN; l++) {
        int t = t0 + l;
        float u = omw*(lp[t*COUTn] - sp[t*COUTn]) + w*gp[t*COUTn];
        z = w*z + u;
    }
    LZ[(size_t)ch*GSEG + seg] = z;
}

__global__ void level_carry(const float* __restrict__ lsw,
                            const float* __restrict__ lv0) {
    int ch = threadIdx.x;
    if (ch >= Bn*COUTn) return;
    int c = ch % COUTn;
    float w = 1.f/(1.f + expf(-lsw[c]));
    float w64 = 1.f;
    { float p = w; int e = GSEGLEN; while (e) { if (e & 1) w64 *= p; p *= p; e >>= 1; } }
    float y = lv0[c];
#pragma unroll
    for (int seg = 0; seg < GSEG; seg++) {
        LCARRY[(size_t)ch*GSEG + seg] = y;
        y = w64*y + LZ[(size_t)ch*GSEG + seg];
    }
}

__global__ void level_passB(const float* __restrict__ level,
                            const float* __restrict__ lsw,
                            float* __restrict__ out_all) {
    int gid = blockIdx.x*blockDim.x + threadIdx.x;
    if (gid >= Bn*COUTn*GSEG) return;
    int ch = gid % (Bn*COUTn), seg = gid / (Bn*COUTn);
    int b = ch / COUTn, c = ch % COUTn;
    float w = 1.f/(1.f + expf(-lsw[c]));
    float omw = 1.f - w;
    int t0 = seg * GSEGLEN;
    const float* lp = level + (size_t)b*Tn*COUTn + c;
    const float* gp = GS_G  + (size_t)b*Tn*COUTn + c;
    const float* sp = GS_S  + (size_t)b*Tn*COUTn + c;
    float* op = out_all + OFF_LEVEL + (size_t)b*Tn*COUTn + c;
    float y = LCARRY[(size_t)ch*GSEG + seg];
    for (int l = 0; l < GSEGLEN; l++) {
        int t = t0 + l;
        float u = omw*(lp[t*COUTn] - sp[t*COUTn]) + w*gp[t*COUTn];
        y = w*y + u;
        op[t*COUTn] = y;
    }
}

// ---------------- launch ----------------
extern "C" void kernel_launch(void* const* d_in, const int* in_sizes, int n_in,
                              void* d_out, int out_size) {
    const float* res      = (const float*)d_in[0];
    const float* level    = (const float*)d_in[1];
    const float* in_w     = (const float*)d_in[2];
    const float* out_w    = (const float*)d_in[3];
    const float* z0       = (const float*)d_in[4];
    const float* gsw      = (const float*)d_in[5];
    const float* gv0      = (const float*)d_in[6];
    const float* ff_w1    = (const float*)d_in[7];
    const float* ff_w2    = (const float*)d_in[8];
    const float* n1g      = (const float*)d_in[9];
    const float* n1b      = (const float*)d_in[10];
    const float* n2g      = (const float*)d_in[11];
    const float* n2b      = (const float*)d_in[12];
    const float* gpw      = (const float*)d_in[13];
    const float* spw      = (const float*)d_in[14];
    const float* lsw      = (const float*)d_in[15];
    const float* lv0      = (const float*)d_in[16];
    float* out = (float*)d_out;

    float *pVBUF, *pFOUT;
    __half *pRES1H, *pGBUFH, *pR2H, *pFBUFH, *pWTIN, *pWTOUT, *pWT1, *pWT2;
    cudaGetSymbolAddress((void**)&pVBUF,  VBUF);
    cudaGetSymbolAddress((void**)&pFOUT,  FOUT);
    cudaGetSymbolAddress((void**)&pRES1H, RES1H);
    cudaGetSymbolAddress((void**)&pGBUFH, GBUFH);
    cudaGetSymbolAddress((void**)&pR2H,   R2BH);
    cudaGetSymbolAddress((void**)&pFBUFH, FBUFH);
    cudaGetSymbolAddress((void**)&pWTIN,  WT_IN);
    cudaGetSymbolAddress((void**)&pWTOUT, WT_OUT);
    cudaGetSymbolAddress((void**)&pWT1,   WT_1);
    cudaGetSymbolAddress((void**)&pWT2,   WT_2);

    static int attr_set = 0;
    if (!attr_set) {
        cudaFuncSetAttribute(hgemm_kernel,
                             cudaFuncAttributeMaxDynamicSharedMemorySize, HS_TOTAL);
        attr_set = 1;
    }

    // 0) all 4 weight transposes in one launch
    transpose4<<<2560, 256>>>(in_w, pWTIN, out_w, pWTOUT, ff_w1, pWT1, ff_w2, pWT2);
    // 1) fused FFT + topk + season + res1
    fftseason_kernel<<<Bn*(Dn/4), 256>>>(res, out);
    // 2) v = res1 @ in_proj_w
    hgemm_kernel<<<dim3(Dn/128, (Bn*Tn)/128), 256, HS_TOTAL>>>(pRES1H, pWTIN,
                                                               pVBUF, 0,
                                                               Bn*Tn, Dn, Dn, 0, 0);
    // 3) diffs + EMA (blocked scan) -> GBUFH
    growth_passA<<<(Bn*Dn*GSEG)/256, 256>>>(gsw, z0);
    growth_carry<<<(Bn*Dn)/256, 256>>>(gsw, gv0);
    growth_passB<<<(Bn*Dn*GSEG)/256, 256>>>(gsw, z0, gv0);
    // 4) growth = GBUFH @ out_proj_w -> d_out
    hgemm_kernel<<<dim3(Dn/128, (Bn*T1 + 127)/128), 256, HS_TOTAL>>>(pGBUFH, pWTOUT,
                                                                     out + OFF_GROWTH, 0,
                                                                     Bn*T1, Dn, Dn, 0, 0);
    // 5) res2 = LN(res1 - growth[:,1:])
    res2_kernel<<<Bn*Tn, 128>>>(out, n1g, n1b);
    // 6) ffn1 = gelu(res2 @ ff_w1) -> half
    hgemm_kernel<<<dim3(LATENTn/128, (Bn*Tn)/128), 256, HS_TOTAL>>>(pR2H, pWT1,
                                                                    0, pFBUFH,
                                                                    Bn*Tn, LATENTn, Dn, 1, 1);
    // 7) ffn2 = ffn1 @ ff_w2 -> f32
    hgemm_kernel<<<dim3(Dn/128, (Bn*Tn)/128), 256, HS_TOTAL>>>(pFBUFH, pWT2,
                                                               pFOUT, 0,
                                                               Bn*Tn, Dn, LATENTn, 0, 0);
    // 8) res3 = LN(res2 + ffn2) -> d_out
    res3_kernel<<<Bn*Tn, 128>>>(out, n2g, n2b);
    // 9) level projections
    levelproj_kernel<<<(Bn*Tn*32)/256, 256>>>(out, gpw, spw);
    // 10) level EMA -> d_out
    level_passA<<<(Bn*COUTn*GSEG + 255)/256, 256>>>(level, lsw);
    level_carry<<<1, 128>>>(lsw, lv0);
    level_passB<<<(Bn*COUTn*GSEG + 255)/256, 256>>>(level, lsw, out);
}

// round 10
// speedup vs baseline: 2.1610x; 1.0561x over previous
#include <cuda_runtime.h>
#include <cuda_fp16.h>
#include <math.h>
#include <stdint.h>

#define Bn 16
#define Tn 1024
#define Dn 512
#define COUTn 7
#define PREDn 96
#define Kn 8
#define LATENTn 2048
#define TP (Tn + PREDn)
#define T1 (Tn + 1)

#define OFF_RES3   0
#define OFF_LEVEL  (Bn*Tn*Dn)
#define OFF_GROWTH (OFF_LEVEL + Bn*Tn*COUTn)
#define OFF_SEASON (OFF_GROWTH + Bn*T1*Dn)

#define GSEG 16
#define GSEGLEN 64

// fp16 GEMM tiling
#define STAGESH 3
#define BKH 32
#define APADH 40
#define STG_HALFS (128*APADH)
#define HS_TOTAL (STAGESH*2*STG_HALFS*2)   /* 61440 B */

// ---------------- scratch ----------------
__device__ float RES1 [Bn*Tn*Dn];
__device__ __align__(256) __half RES1H[Bn*Tn*Dn];
__device__ float VBUF[Bn*Tn*Dn];
__device__ __align__(256) __half GBUFH[Bn*T1*Dn];
__device__ float R2B [Bn*Tn*Dn];
__device__ __align__(256) __half R2BH[Bn*Tn*Dn];
__device__ __align__(256) __half FBUFH[Bn*Tn*LATENTn];
__device__ float FOUT[Bn*Tn*Dn];
__device__ __align__(256) __half WT_IN [Dn*Dn];
__device__ __align__(256) __half WT_OUT[Dn*Dn];
__device__ __align__(256) __half WT_1  [LATENTn*Dn];
__device__ __align__(256) __half WT_2  [Dn*LATENTn];
__device__ float GS_G[Bn*Tn*COUTn];
__device__ float GS_S[Bn*Tn*COUTn];

// ---------------- fused transpose of all 4 weight matrices ----------------
__global__ __launch_bounds__(256) void transpose4(const float* __restrict__ s0, __half* __restrict__ d0p,
                                                  const float* __restrict__ s1, __half* __restrict__ d1p,
                                                  const float* __restrict__ s2, __half* __restrict__ d2p,
                                                  const float* __restrict__ s3, __half* __restrict__ d3p) {
    __shared__ float t[32][33];
    int id = blockIdx.x;
    const float* src; __half* dst; int R, C, bx, by;
    if (id < 256)       { src = s0; dst = d0p; R = Dn;      C = Dn;      bx = id & 15;        by = id >> 4; }
    else if (id < 512)  { id -= 256;  src = s1; dst = d1p; R = Dn;      C = Dn;      bx = id & 15; by = id >> 4; }
    else if (id < 1536) { id -= 512;  src = s2; dst = d2p; R = Dn;      C = LATENTn; bx = id & 63; by = id >> 6; }
    else                { id -= 1536; src = s3; dst = d3p; R = LATENTn; C = Dn;      bx = id & 15; by = id >> 4; }
    int tx = threadIdx.x & 31, ty = threadIdx.x >> 5;
    int c0 = bx*32, r0 = by*32;
#pragma unroll
    for (int i = 0; i < 4; i++)
        t[ty + i*8][tx] = src[(size_t)(r0 + ty + i*8)*C + c0 + tx];
    __syncthreads();
#pragma unroll
    for (int i = 0; i < 4; i++)
        dst[(size_t)(c0 + ty + i*8)*R + r0 + tx] = __float2half(t[tx][ty + i*8]);
}

// ---------------- fused FFT + top-8 + season + res1 ----------------
__global__ __launch_bounds__(256) void fftseason_kernel(const float* __restrict__ x,
                                                        float* __restrict__ out) {
    __shared__ float2 data[4][1024];
    __shared__ float2 tw[512];
    __shared__ float  mag[4][512];
    __shared__ int    chm[4][8];
    __shared__ float  chre[4][8], chim[4][8];

    int tid = threadIdx.x;
    int b   = blockIdx.x >> 7;
    int d0  = (blockIdx.x & 127) << 2;

    for (int k = tid; k < 512; k += 256) {
        float s, c;
        sincosf(-6.283185307179586f * (float)k / 1024.0f, &s, &c);
        tw[k] = make_float2(c, s);
    }
    const float* xb = x + (size_t)b * Tn * Dn;
    for (int i = tid; i < 4096; i += 256) {
        int t = i >> 2, j = i & 3;
        data[j][t] = make_float2(xb[(size_t)t*Dn + d0 + j], 0.f);
    }
    __syncthreads();

    int tmul = 1;
    for (int half = 512; half >= 1; half >>= 1, tmul <<= 1) {
        for (int i = tid; i < 2048; i += 256) {
            int s  = i >> 9;
            int bf = i & 511;
            int k  = bf & (half - 1);
            int pos = 2*bf - k;
            float2 u = data[s][pos], v = data[s][pos + half];
            data[s][pos] = make_float2(u.x + v.x, u.y + v.y);
            float2 t2 = make_float2(u.x - v.x, u.y - v.y);
            float2 w  = tw[k * tmul];
            data[s][pos + half] = make_float2(t2.x*w.x - t2.y*w.y,
                                              t2.x*w.y + t2.y*w.x);
        }
        __syncthreads();
    }

    for (int i = tid; i < 2048; i += 256) {
        int s = i >> 9, f = i & 511;
        if (f == 0) { mag[s][0] = -1e30f; continue; }
        int j = (int)(__brev((unsigned)f) >> 22);
        float2 v = data[s][j];
        mag[s][f] = v.x*v.x + v.y*v.y;
    }
    __syncthreads();

    int wid = tid >> 5, lane = tid & 31;
    if (wid < 4) {
        int s = wid;
#pragma unroll
        for (int it = 0; it < 8; it++) {
            float bestm = -1e29f; int bestf = 1 << 20;
            for (int f = lane; f < 512; f += 32) {
                float m2 = mag[s][f];
                if (m2 > bestm || (m2 == bestm && f < bestf)) { bestm = m2; bestf = f; }
            }
            for (int off = 16; off; off >>= 1) {
                float om = __shfl_xor_sync(0xffffffffu, bestm, off);
                int   of = __shfl_xor_sync(0xffffffffu, bestf, off);
                if (om > bestm || (om == bestm && of < bestf)) { bestm = om; bestf = of; }
            }
            if (lane == 0) {
                int j = (int)(__brev((unsigned)bestf) >> 22);
                float2 v = data[s][j];
                chm [s][it] = bestf;
                chre[s][it] = v.x * (2.0f / (float)Tn);
                chim[s][it] = v.y * (2.0f / (float)Tn);
                mag[s][bestf] = -1e30f;
            }
            __syncwarp();
        }
    }
    __syncthreads();

    float* ctab = &mag[0][0];
    for (int j = tid; j < 1024; j += 256)
        ctab[j] = (j < 512) ? tw[j].x : -tw[j - 512].x;
    __syncthreads();

    {
        int s = tid & 3;
        int ms[8]; float re[8], im[8];
#pragma unroll
        for (int k = 0; k < 8; k++) { ms[k] = chm[s][k]; re[k] = chre[s][k]; im[k] = chim[s][k]; }
        int d = d0 + s;
        float*       seas = out + OFF_SEASON + (size_t)b*TP*Dn + d;
        const float* rb   = x + (size_t)b*Tn*Dn + d;
        float*       r1   = RES1  + (size_t)b*Tn*Dn + d;
        __half*      r1h  = RES1H + (size_t)b*Tn*Dn + d;
        for (int t = tid >> 2; t < TP; t += 64) {
            float acc = 0.f;
#pragma unroll
            for (int k = 0; k < 8; k++) {
                int idx = (ms[k]*t) & 1023;
                acc += re[k]*ctab[idx] - im[k]*ctab[(idx + 768) & 1023];
            }
            seas[(size_t)t*Dn] = acc;
            if (t < Tn) {
                float v = rb[(size_t)t*Dn] - acc;
                r1 [(size_t)t*Dn] = v;
                r1h[(size_t)t*Dn] = __float2half(v);
            }
        }
    }
}

// ---------------- fp16 tensor-core GEMM, cp.async 3-stage ----------------
__device__ __forceinline__ void cp_async16(unsigned saddr, const void* gptr, bool valid) {
    int sz = valid ? 16 : 0;
    asm volatile("cp.async.cg.shared.global [%0], [%1], 16, %2;\n"
                 :: "r"(saddr), "l"(gptr), "r"(sz));
}

__global__ __launch_bounds__(256) void hgemm_kernel(const __half* __restrict__ A,
                                                    const __half* __restrict__ BT,
                                                    float* __restrict__ C,
                                                    __half* __restrict__ CH,
                                                    int M, int N, int K,
                                                    int dogelu, int outhalf) {
    extern __shared__ __half smh[];
    __half* Ash = smh;
    __half* Bsh = smh + STAGESH * STG_HALFS;
    unsigned As_base = (unsigned)__cvta_generic_to_shared(Ash);
    unsigned Bs_base = (unsigned)__cvta_generic_to_shared(Bsh);

    int tid = threadIdx.x;
    int row0 = blockIdx.y * 128, col0 = blockIdx.x * 128;
    int wid = tid >> 5, lane = tid & 31;
    int wm = (wid & 1) * 64, wn = (wid >> 1) * 32;
    int g = lane >> 2, tg = lane & 3;

    float acc[4][4][4];
#pragma unroll
    for (int i = 0; i < 4; i++)
#pragma unroll
        for (int j = 0; j < 4; j++)
#pragma unroll
            for (int q = 0; q < 4; q++) acc[i][j][q] = 0.f;

    const int NT = K / BKH;

    int ch0 = tid, ch1 = tid + 256;
    int ra0 = ch0 >> 2, ca0 = ch0 & 3;
    int ra1 = ch1 >> 2, ca1 = ch1 & 3;
    bool av0 = (row0 + ra0) < M, av1 = (row0 + ra1) < M;
    const __half* ag0 = A + (size_t)(row0 + ra0)*K + ca0*8;
    const __half* ag1 = A + (size_t)(row0 + ra1)*K + ca1*8;
    const __half* bg0 = BT + (size_t)(col0 + ra0)*K + ca0*8;
    const __half* bg1 = BT + (size_t)(col0 + ra1)*K + ca1*8;
    unsigned ad0 = (unsigned)(ra0*APADH + ca0*8)*2, ad1 = (unsigned)(ra1*APADH + ca1*8)*2;

#pragma unroll
    for (int s = 0; s < 2; s++) {
        unsigned ab = As_base + s*STG_HALFS*2, bb = Bs_base + s*STG_HALFS*2;
        int k0 = s * BKH;
        cp_async16(ab + ad0, ag0 + k0, av0);
        cp_async16(ab + ad1, ag1 + k0, av1);
        cp_async16(bb + ad0, bg0 + k0, true);
        cp_async16(bb + ad1, bg1 + k0, true);
        asm volatile("cp.async.commit_group;\n");
    }

    for (int it = 0; it < NT; it++) {
        if (it < NT - 1) asm volatile("cp.async.wait_group 1;\n");
        else             asm volatile("cp.async.wait_group 0;\n");
        __syncthreads();

        if (it + 2 < NT) {
            int s = (it + 2) % STAGESH, k0 = (it + 2) * BKH;
            unsigned ab = As_base + s*STG_HALFS*2, bb = Bs_base + s*STG_HALFS*2;
            cp_async16(ab + ad0, ag0 + k0, av0);
            cp_async16(ab + ad1, ag1 + k0, av1);
            cp_async16(bb + ad0, bg0 + k0, true);
            cp_async16(bb + ad1, bg1 + k0, true);
            asm volatile("cp.async.commit_group;\n");
        }

        const __half* Abuf = Ash + (it % STAGESH) * STG_HALFS;
        const __half* Bbuf = Bsh + (it % STAGESH) * STG_HALFS;

#pragma unroll
        for (int kk = 0; kk < BKH; kk += 16) {
            unsigned af[4][4], bf[4][2];
#pragma unroll
            for (int mt = 0; mt < 4; mt++) {
                int m = wm + mt*16 + g;
                af[mt][0] = *(const unsigned*)(Abuf + (m  )*APADH + kk + 2*tg);
                af[mt][1] = *(const unsigned*)(Abuf + (m+8)*APADH + kk + 2*tg);
                af[mt][2] = *(const unsigned*)(Abuf + (m  )*APADH + kk + 2*tg + 8);
                af[mt][3] = *(const unsigned*)(Abuf + (m+8)*APADH + kk + 2*tg + 8);
            }
#pragma unroll
            for (int nt = 0; nt < 4; nt++) {
                int n = wn + nt*8 + g;
                bf[nt][0] = *(const unsigned*)(Bbuf + n*APADH + kk + 2*tg);
                bf[nt][1] = *(const unsigned*)(Bbuf + n*APADH + kk + 2*tg + 8);
            }
#pragma unroll
            for (int mt = 0; mt < 4; mt++)
#pragma unroll
                for (int nt = 0; nt < 4; nt++)
                    asm volatile(
                        "mma.sync.aligned.m16n8k16.row.col.f32.f16.f16.f32 "
                        "{%0,%1,%2,%3}, {%4,%5,%6,%7}, {%8,%9}, {%0,%1,%2,%3};"
                        : "+f"(acc[mt][nt][0]), "+f"(acc[mt][nt][1]),
                          "+f"(acc[mt][nt][2]), "+f"(acc[mt][nt][3])
                        : "r"(af[mt][0]), "r"(af[mt][1]), "r"(af[mt][2]), "r"(af[mt][3]),
                          "r"(bf[nt][0]), "r"(bf[nt][1]));
        }
        __syncthreads();
    }

#pragma unroll
    for (int mt = 0; mt < 4; mt++) {
#pragma unroll
        for (int nt = 0; nt < 4; nt++) {
            int r0 = row0 + wm + mt*16 + g;
            int c  = col0 + wn + nt*8 + 2*tg;
            float v[4];
#pragma unroll
            for (int q = 0; q < 4; q++) {
                float u = acc[mt][nt][q];
                if (dogelu) u = 0.5f*u*(1.0f + erff(u*0.70710678118654752f));
                v[q] = u;
            }
            if (outhalf) {
                if (r0 < M)
                    *(__half2*)(CH + (size_t)r0*N + c) = __floats2half2_rn(v[0], v[1]);
                if (r0 + 8 < M)
                    *(__half2*)(CH + (size_t)(r0+8)*N + c) = __floats2half2_rn(v[2], v[3]);
            } else {
                if (r0 < M)     *(float2*)(C + (size_t)r0*N + c)     = make_float2(v[0], v[1]);
                if (r0 + 8 < M) *(float2*)(C + (size_t)(r0+8)*N + c) = make_float2(v[2], v[3]);
            }
        }
    }
}

// ---------------- growth EMA: fully fused blocked scan ----------------
// block = 16 segs x 16 channels; diffs held in registers; carry in smem
__global__ __launch_bounds__(256) void growth_fused(const float* __restrict__ sw,
                                                    const float* __restrict__ z0,
                                                    const float* __restrict__ v0) {
    __shared__ float zb[GSEG][17];
    __shared__ float cb[GSEG][17];
    int b  = blockIdx.x >> 5;
    int c0 = (blockIdx.x & 31) << 4;
    int seg = threadIdx.x >> 4, ci = threadIdx.x & 15;
    int c = c0 + ci;
    float w = 1.f/(1.f + expf(-sw[c >> 6]));
    float omw = 1.f - w;
    int t0 = seg * GSEGLEN;
    const float* vp = VBUF + (size_t)b*Tn*Dn + c;

    float dv[GSEGLEN];
    float prev = (t0 == 0) ? z0[c] : vp[(size_t)(t0-1)*Dn];
    float z = 0.f;
#pragma unroll
    for (int l = 0; l < GSEGLEN; l++) {
        float v = vp[(size_t)(t0+l)*Dn];
        dv[l] = v - prev;
        prev = v;
        z = w*z + dv[l];
    }
    zb[seg][ci] = z;
    __syncthreads();

    if (threadIdx.x < 16) {
        int cc = threadIdx.x;
        float wj = 1.f/(1.f + expf(-sw[(c0 + cc) >> 6]));
        float w64 = 1.f;
        { float p = wj; int e = GSEGLEN; while (e) { if (e & 1) w64 *= p; p *= p; e >>= 1; } }
        float y = v0[c0 + cc];
        float omwj = 1.f - wj;
#pragma unroll
        for (int s = 0; s < GSEG; s++) {
            cb[s][cc] = y;
            y = w64*y + omwj*zb[s][cc];
        }
    }
    __syncthreads();

    __half* gp = GBUFH + (size_t)b*T1*Dn + c;
    float y = cb[seg][ci];
    if (seg == 0) gp[0] = __float2half(v0[c]);
#pragma unroll
    for (int l = 0; l < GSEGLEN; l++) {
        y = w*y + omw*dv[l];
        gp[(size_t)(t0+l+1)*Dn] = __float2half(y);
    }
}

// ---------------- layernorm helpers ----------------
__device__ __forceinline__ float block_reduce_sum(float v, float* red) {
    for (int o = 16; o; o >>= 1) v += __shfl_xor_sync(0xffffffffu, v, o);
    int wid = threadIdx.x >> 5;
    if ((threadIdx.x & 31) == 0) red[wid] = v;
    __syncthreads();
    if (threadIdx.x < 32) {
        float s = (threadIdx.x < 4) ? red[threadIdx.x] : 0.f;
        for (int o = 2; o; o >>= 1) s += __shfl_xor_sync(0xffffffffu, s, o);
        if (threadIdx.x == 0) red[0] = s;
    }
    __syncthreads();
    float r = red[0];
    __syncthreads();
    return r;
}

__global__ __launch_bounds__(128) void res2_kernel(const float* __restrict__ out_all,
                                                   const float* __restrict__ ng,
                                                   const float* __restrict__ nb) {
    __shared__ float red[32];
    int r = blockIdx.x;
    int b = r >> 10, t = r & 1023;
    const float* x1 = RES1 + (size_t)r*Dn;
    const float* gw = out_all + OFF_GROWTH + (size_t)(b*T1 + t + 1)*Dn;
    float vals[4]; float s = 0.f;
#pragma unroll
    for (int i = 0; i < 4; i++) {
        int d = threadIdx.x + i*128;
        vals[i] = x1[d] - gw[d];
        s += vals[i];
    }
    float mu = block_reduce_sum(s, red) * (1.0f/512.0f);
    float vs = 0.f;
#pragma unroll
    for (int i = 0; i < 4; i++) { float c = vals[i]-mu; vs += c*c; }
    float var = block_reduce_sum(vs, red) * (1.0f/512.0f);
    float inv = rsqrtf(var + 1e-5f);
#pragma unroll
    for (int i = 0; i < 4; i++) {
        int d = threadIdx.x + i*128;
        float v = (vals[i]-mu)*inv*ng[d] + nb[d];
        R2B [(size_t)r*Dn + d] = v;
        R2BH[(size_t)r*Dn + d] = __float2half(v);
    }
}

__global__ __launch_bounds__(128) void res3_kernel(float* __restrict__ out_all,
                                                   const float* __restrict__ ng,
                                                   const float* __restrict__ nb) {
    __shared__ float red[32];
    int r = blockIdx.x;
    float vals[4]; float s = 0.f;
#pragma unroll
    for (int i = 0; i < 4; i++) {
        int d = threadIdx.x + i*128;
        vals[i] = R2B[(size_t)r*Dn + d] + FOUT[(size_t)r*Dn + d];
        s += vals[i];
    }
    float mu = block_reduce_sum(s, red) * (1.0f/512.0f);
    float vs = 0.f;
#pragma unroll
    for (int i = 0; i < 4; i++) { float c = vals[i]-mu; vs += c*c; }
    float var = block_reduce_sum(vs, red) * (1.0f/512.0f);
    float inv = rsqrtf(var + 1e-5f);
#pragma unroll
    for (int i = 0; i < 4; i++) {
        int d = threadIdx.x + i*128;
        out_all[OFF_RES3 + (size_t)r*Dn + d] = (vals[i]-mu)*inv*ng[d] + nb[d];
    }
}

// ---------------- level projections ----------------
__global__ __launch_bounds__(256) void levelproj_kernel(const float* __restrict__ out_all,
                                                        const float* __restrict__ gpw,
                                                        const float* __restrict__ spw) {
    int warp = (blockIdx.x*256 + threadIdx.x) >> 5;
    int lane = threadIdx.x & 31;
    if (warp >= Bn*Tn) return;
    int b = warp >> 10, t = warp & 1023;
    const float* gr = out_all + OFF_GROWTH + (size_t)(b*T1 + t)*Dn;
    const float* se = out_all + OFF_SEASON + (size_t)(b*TP + t)*Dn;
    float ag[7] = {}, as_[7] = {};
    for (int d = lane; d < 512; d += 32) {
        float g = gr[d], s = se[d];
#pragma unroll
        for (int c = 0; c < 7; c++) { ag[c] += g*gpw[d*7+c]; as_[c] += s*spw[d*7+c]; }
    }
#pragma unroll
    for (int c = 0; c < 7; c++) {
        for (int o = 16; o; o >>= 1) {
            ag[c]  += __shfl_xor_sync(0xffffffffu, ag[c],  o);
            as_[c] += __shfl_xor_sync(0xffffffffu, as_[c], o);
        }
    }
    if (lane == 0) {
#pragma unroll
        for (int c = 0; c < 7; c++) {
            GS_G[(size_t)warp*7 + c] = ag[c];
            GS_S[(size_t)warp*7 + c] = as_[c];
        }
    }
}

// ---------------- level EMA: fully fused blocked scan ----------------
// 7 blocks of 256: 16 segs x 16 channels (112 channels total)
__global__ __launch_bounds__(256) void level_fused(const float* __restrict__ level,
                                                   const float* __restrict__ lsw,
                                                   const float* __restrict__ lv0,
                                                   float* __restrict__ out_all) {
    __shared__ float zb[GSEG][17];
    __shared__ float cb[GSEG][17];
    int seg = threadIdx.x >> 4, ci = threadIdx.x & 15;
    int ch = blockIdx.x * 16 + ci;          // 0..111
    int b = ch / COUTn, c = ch % COUTn;
    float w = 1.f/(1.f + expf(-lsw[c]));
    float omw = 1.f - w;
    int t0 = seg * GSEGLEN;
    const float* lp = level + (size_t)b*Tn*COUTn + c;
    const float* gp = GS_G  + (size_t)b*Tn*COUTn + c;
    const float* sp = GS_S  + (size_t)b*Tn*COUTn + c;

    float uv[GSEGLEN];
    float z = 0.f;
#pragma unroll
    for (int l = 0; l < GSEGLEN; l++) {
        int t = t0 + l;
        uv[l] = omw*(lp[t*COUTn] - sp[t*COUTn]) + w*gp[t*COUTn];
        z = w*z + uv[l];
    }
    zb[seg][ci] = z;
    __syncthreads();

    if (threadIdx.x < 16) {
        int cc = threadIdx.x;
        int ch2 = blockIdx.x * 16 + cc;
        float wj = 1.f/(1.f + expf(-lsw[ch2 % COUTn]));
        float w64 = 1.f;
        { float p = wj; int e = GSEGLEN; while (e) { if (e & 1) w64 *= p; p *= p; e >>= 1; } }
        float y = lv0[ch2 % COUTn];
#pragma unroll
        for (int s = 0; s < GSEG; s++) {
            cb[s][cc] = y;
            y = w64*y + zb[s][cc];
        }
    }
    __syncthreads();

    float* op = out_all + OFF_LEVEL + (size_t)b*Tn*COUTn + c;
    float y = cb[seg][ci];
#pragma unroll
    for (int l = 0; l < GSEGLEN; l++) {
        y = w*y + uv[l];
        op[(t0+l)*COUTn] = y;
    }
}

// ---------------- launch ----------------
extern "C" void kernel_launch(void* const* d_in, const int* in_sizes, int n_in,
                              void* d_out, int out_size) {
    const float* res      = (const float*)d_in[0];
    const float* level    = (const float*)d_in[1];
    const float* in_w     = (const float*)d_in[2];
    const float* out_w    = (const float*)d_in[3];
    const float* z0       = (const float*)d_in[4];
    const float* gsw      = (const float*)d_in[5];
    const float* gv0      = (const float*)d_in[6];
    const float* ff_w1    = (const float*)d_in[7];
    const float* ff_w2    = (const float*)d_in[8];
    const float* n1g      = (const float*)d_in[9];
    const float* n1b      = (const float*)d_in[10];
    const float* n2g      = (const float*)d_in[11];
    const float* n2b      = (const float*)d_in[12];
    const float* gpw      = (const float*)d_in[13];
    const float* spw      = (const float*)d_in[14];
    const float* lsw      = (const float*)d_in[15];
    const float* lv0      = (const float*)d_in[16];
    float* out = (float*)d_out;

    float *pVBUF, *pFOUT;
    __half *pRES1H, *pGBUFH, *pR2H, *pFBUFH, *pWTIN, *pWTOUT, *pWT1, *pWT2;
    cudaGetSymbolAddress((void**)&pVBUF,  VBUF);
    cudaGetSymbolAddress((void**)&pFOUT,  FOUT);
    cudaGetSymbolAddress((void**)&pRES1H, RES1H);
    cudaGetSymbolAddress((void**)&pGBUFH, GBUFH);
    cudaGetSymbolAddress((void**)&pR2H,   R2BH);
    cudaGetSymbolAddress((void**)&pFBUFH, FBUFH);
    cudaGetSymbolAddress((void**)&pWTIN,  WT_IN);
    cudaGetSymbolAddress((void**)&pWTOUT, WT_OUT);
    cudaGetSymbolAddress((void**)&pWT1,   WT_1);
    cudaGetSymbolAddress((void**)&pWT2,   WT_2);

    static int attr_set = 0;
    if (!attr_set) {
        cudaFuncSetAttribute(hgemm_kernel,
                             cudaFuncAttributeMaxDynamicSharedMemorySize, HS_TOTAL);
        attr_set = 1;
    }

    // 0) all 4 weight transposes in one launch
    transpose4<<<2560, 256>>>(in_w, pWTIN, out_w, pWTOUT, ff_w1, pWT1, ff_w2, pWT2);
    // 1) fused FFT + topk + season + res1
    fftseason_kernel<<<Bn*(Dn/4), 256>>>(res, out);
    // 2) v = res1 @ in_proj_w
    hgemm_kernel<<<dim3(Dn/128, (Bn*Tn)/128), 256, HS_TOTAL>>>(pRES1H, pWTIN,
                                                               pVBUF, 0,
                                                               Bn*Tn, Dn, Dn, 0, 0);
    // 3) fused diffs + EMA scan -> GBUFH
    growth_fused<<<Bn*32, 256>>>(gsw, z0, gv0);
    // 4) growth = GBUFH @ out_proj_w -> d_out
    hgemm_kernel<<<dim3(Dn/128, (Bn*T1 + 127)/128), 256, HS_TOTAL>>>(pGBUFH, pWTOUT,
                                                                     out + OFF_GROWTH, 0,
                                                                     Bn*T1, Dn, Dn, 0, 0);
    // 5) res2 = LN(res1 - growth[:,1:])
    res2_kernel<<<Bn*Tn, 128>>>(out, n1g, n1b);
    // 6) ffn1 = gelu(res2 @ ff_w1) -> half
    hgemm_kernel<<<dim3(LATENTn/128, (Bn*Tn)/128), 256, HS_TOTAL>>>(pR2H, pWT1,
                                                                    0, pFBUFH,
                                                                    Bn*Tn, LATENTn, Dn, 1, 1);
    // 7) ffn2 = ffn1 @ ff_w2 -> f32
    hgemm_kernel<<<dim3(Dn/128, (Bn*Tn)/128), 256, HS_TOTAL>>>(pFBUFH, pWT2,
                                                               pFOUT, 0,
                                                               Bn*Tn, Dn, LATENTn, 0, 0);
    // 8) res3 = LN(res2 + ffn2) -> d_out
    res3_kernel<<<Bn*Tn, 128>>>(out, n2g, n2b);
    // 9) level projections
    levelproj_kernel<<<(Bn*Tn*32)/256, 256>>>(out, gpw, spw);
    // 10) fused level EMA -> d_out
    level_fused<<<7, 256>>>(level, lsw, lv0, out);
}

// round 11
// speedup vs baseline: 2.2112x; 1.0232x over previous
#include <cuda_runtime.h>
#include <cuda_fp16.h>
#include <math.h>
#include <stdint.h>

#define Bn 16
#define Tn 1024
#define Dn 512
#define COUTn 7
#define PREDn 96
#define Kn 8
#define LATENTn 2048
#define TP (Tn + PREDn)
#define T1 (Tn + 1)

#define OFF_RES3   0
#define OFF_LEVEL  (Bn*Tn*Dn)
#define OFF_GROWTH (OFF_LEVEL + Bn*Tn*COUTn)
#define OFF_SEASON (OFF_GROWTH + Bn*T1*Dn)

#define GSEG 16
#define GSEGLEN 64

// fp16 GEMM tiling: 4 stages, single barrier per K-iter
#define STAGESH 4
#define BKH 32
#define APADH 40
#define STG_HALFS (128*APADH)
#define HS_TOTAL (STAGESH*2*STG_HALFS*2)   /* 81920 B */

// ---------------- scratch ----------------
__device__ float RES1 [Bn*Tn*Dn];
__device__ __align__(256) __half RES1H[Bn*Tn*Dn];
__device__ float VBUF[Bn*Tn*Dn];
__device__ __align__(256) __half GBUFH[Bn*T1*Dn];
__device__ float R2B [Bn*Tn*Dn];
__device__ __align__(256) __half R2BH[Bn*Tn*Dn];
__device__ __align__(256) __half FBUFH[Bn*Tn*LATENTn];
__device__ float FOUT[Bn*Tn*Dn];
__device__ __align__(256) __half WT_IN [Dn*Dn];
__device__ __align__(256) __half WT_OUT[Dn*Dn];
__device__ __align__(256) __half WT_1  [LATENTn*Dn];
__device__ __align__(256) __half WT_2  [Dn*LATENTn];
__device__ float GS_G[Bn*Tn*COUTn];
__device__ float GS_S[Bn*Tn*COUTn];

// ---------------- fused transpose of all 4 weight matrices ----------------
__global__ __launch_bounds__(256) void transpose4(const float* __restrict__ s0, __half* __restrict__ d0p,
                                                  const float* __restrict__ s1, __half* __restrict__ d1p,
                                                  const float* __restrict__ s2, __half* __restrict__ d2p,
                                                  const float* __restrict__ s3, __half* __restrict__ d3p) {
    __shared__ float t[32][33];
    int id = blockIdx.x;
    const float* src; __half* dst; int R, C, bx, by;
    if (id < 256)       { src = s0; dst = d0p; R = Dn;      C = Dn;      bx = id & 15;        by = id >> 4; }
    else if (id < 512)  { id -= 256;  src = s1; dst = d1p; R = Dn;      C = Dn;      bx = id & 15; by = id >> 4; }
    else if (id < 1536) { id -= 512;  src = s2; dst = d2p; R = Dn;      C = LATENTn; bx = id & 63; by = id >> 6; }
    else                { id -= 1536; src = s3; dst = d3p; R = LATENTn; C = Dn;      bx = id & 15; by = id >> 4; }
    int tx = threadIdx.x & 31, ty = threadIdx.x >> 5;
    int c0 = bx*32, r0 = by*32;
#pragma unroll
    for (int i = 0; i < 4; i++)
        t[ty + i*8][tx] = src[(size_t)(r0 + ty + i*8)*C + c0 + tx];
    __syncthreads();
#pragma unroll
    for (int i = 0; i < 4; i++)
        dst[(size_t)(c0 + ty + i*8)*R + r0 + tx] = __float2half(t[tx][ty + i*8]);
}

// ---------------- fused FFT + top-8 + season + res1 ----------------
__global__ __launch_bounds__(256) void fftseason_kernel(const float* __restrict__ x,
                                                        float* __restrict__ out) {
    __shared__ float2 data[4][1024];
    __shared__ float2 tw[512];
    __shared__ float  mag[4][512];
    __shared__ int    chm[4][8];
    __shared__ float  chre[4][8], chim[4][8];

    int tid = threadIdx.x;
    int b   = blockIdx.x >> 7;
    int d0  = (blockIdx.x & 127) << 2;

    for (int k = tid; k < 512; k += 256) {
        float s, c;
        sincosf(-6.283185307179586f * (float)k / 1024.0f, &s, &c);
        tw[k] = make_float2(c, s);
    }
    const float* xb = x + (size_t)b * Tn * Dn;
    for (int i = tid; i < 4096; i += 256) {
        int t = i >> 2, j = i & 3;
        data[j][t] = make_float2(xb[(size_t)t*Dn + d0 + j], 0.f);
    }
    __syncthreads();

    int tmul = 1;
    for (int half = 512; half >= 1; half >>= 1, tmul <<= 1) {
        for (int i = tid; i < 2048; i += 256) {
            int s  = i >> 9;
            int bf = i & 511;
            int k  = bf & (half - 1);
            int pos = 2*bf - k;
            float2 u = data[s][pos], v = data[s][pos + half];
            data[s][pos] = make_float2(u.x + v.x, u.y + v.y);
            float2 t2 = make_float2(u.x - v.x, u.y - v.y);
            float2 w  = tw[k * tmul];
            data[s][pos + half] = make_float2(t2.x*w.x - t2.y*w.y,
                                              t2.x*w.y + t2.y*w.x);
        }
        __syncthreads();
    }

    for (int i = tid; i < 2048; i += 256) {
        int s = i >> 9, f = i & 511;
        if (f == 0) { mag[s][0] = -1e30f; continue; }
        int j = (int)(__brev((unsigned)f) >> 22);
        float2 v = data[s][j];
        mag[s][f] = v.x*v.x + v.y*v.y;
    }
    __syncthreads();

    int wid = tid >> 5, lane = tid & 31;
    if (wid < 4) {
        int s = wid;
#pragma unroll
        for (int it = 0; it < 8; it++) {
            float bestm = -1e29f; int bestf = 1 << 20;
            for (int f = lane; f < 512; f += 32) {
                float m2 = mag[s][f];
                if (m2 > bestm || (m2 == bestm && f < bestf)) { bestm = m2; bestf = f; }
            }
            for (int off = 16; off; off >>= 1) {
                float om = __shfl_xor_sync(0xffffffffu, bestm, off);
                int   of = __shfl_xor_sync(0xffffffffu, bestf, off);
                if (om > bestm || (om == bestm && of < bestf)) { bestm = om; bestf = of; }
            }
            if (lane == 0) {
                int j = (int)(__brev((unsigned)bestf) >> 22);
                float2 v = data[s][j];
                chm [s][it] = bestf;
                chre[s][it] = v.x * (2.0f / (float)Tn);
                chim[s][it] = v.y * (2.0f / (float)Tn);
                mag[s][bestf] = -1e30f;
            }
            __syncwarp();
        }
    }
    __syncthreads();

    float* ctab = &mag[0][0];
    for (int j = tid; j < 1024; j += 256)
        ctab[j] = (j < 512) ? tw[j].x : -tw[j - 512].x;
    __syncthreads();

    {
        int s = tid & 3;
        int ms[8]; float re[8], im[8];
#pragma unroll
        for (int k = 0; k < 8; k++) { ms[k] = chm[s][k]; re[k] = chre[s][k]; im[k] = chim[s][k]; }
        int d = d0 + s;
        float*       seas = out + OFF_SEASON + (size_t)b*TP*Dn + d;
        const float* rb   = x + (size_t)b*Tn*Dn + d;
        float*       r1   = RES1  + (size_t)b*Tn*Dn + d;
        __half*      r1h  = RES1H + (size_t)b*Tn*Dn + d;
        for (int t = tid >> 2; t < TP; t += 64) {
            float acc = 0.f;
#pragma unroll
            for (int k = 0; k < 8; k++) {
                int idx = (ms[k]*t) & 1023;
                acc += re[k]*ctab[idx] - im[k]*ctab[(idx + 768) & 1023];
            }
            seas[(size_t)t*Dn] = acc;
            if (t < Tn) {
                float v = rb[(size_t)t*Dn] - acc;
                r1 [(size_t)t*Dn] = v;
                r1h[(size_t)t*Dn] = __float2half(v);
            }
        }
    }
}

// ---------------- fp16 tensor-core GEMM, cp.async 4-stage, 1 barrier/iter ----------------
__device__ __forceinline__ void cp_async16(unsigned saddr, const void* gptr, bool valid) {
    int sz = valid ? 16 : 0;
    asm volatile("cp.async.cg.shared.global [%0], [%1], 16, %2;\n"
                 :: "r"(saddr), "l"(gptr), "r"(sz));
}

__global__ __launch_bounds__(256) void hgemm_kernel(const __half* __restrict__ A,
                                                    const __half* __restrict__ BT,
                                                    float* __restrict__ C,
                                                    __half* __restrict__ CH,
                                                    int M, int N, int K,
                                                    int dogelu, int outhalf) {
    extern __shared__ __half smh[];
    __half* Ash = smh;
    __half* Bsh = smh + STAGESH * STG_HALFS;
    unsigned As_base = (unsigned)__cvta_generic_to_shared(Ash);
    unsigned Bs_base = (unsigned)__cvta_generic_to_shared(Bsh);

    int tid = threadIdx.x;
    int row0 = blockIdx.y * 128, col0 = blockIdx.x * 128;
    int wid = tid >> 5, lane = tid & 31;
    int wm = (wid & 1) * 64, wn = (wid >> 1) * 32;
    int g = lane >> 2, tg = lane & 3;

    float acc[4][4][4];
#pragma unroll
    for (int i = 0; i < 4; i++)
#pragma unroll
        for (int j = 0; j < 4; j++)
#pragma unroll
            for (int q = 0; q < 4; q++) acc[i][j][q] = 0.f;

    const int NT = K / BKH;

    int ch0 = tid, ch1 = tid + 256;
    int ra0 = ch0 >> 2, ca0 = ch0 & 3;
    int ra1 = ch1 >> 2, ca1 = ch1 & 3;
    bool av0 = (row0 + ra0) < M, av1 = (row0 + ra1) < M;
    const __half* ag0 = A + (size_t)(row0 + ra0)*K + ca0*8;
    const __half* ag1 = A + (size_t)(row0 + ra1)*K + ca1*8;
    const __half* bg0 = BT + (size_t)(col0 + ra0)*K + ca0*8;
    const __half* bg1 = BT + (size_t)(col0 + ra1)*K + ca1*8;
    unsigned ad0 = (unsigned)(ra0*APADH + ca0*8)*2, ad1 = (unsigned)(ra1*APADH + ca1*8)*2;

    // prologue: issue 3 stages ahead
#pragma unroll
    for (int s = 0; s < 3; s++) {
        unsigned ab = As_base + s*STG_HALFS*2, bb = Bs_base + s*STG_HALFS*2;
        int k0 = s * BKH;
        cp_async16(ab + ad0, ag0 + k0, av0);
        cp_async16(ab + ad1, ag1 + k0, av1);
        cp_async16(bb + ad0, bg0 + k0, true);
        cp_async16(bb + ad1, bg1 + k0, true);
        asm volatile("cp.async.commit_group;\n");
    }

    for (int it = 0; it < NT; it++) {
        int ahead = NT - 1 - it;
        if (ahead >= 2)      asm volatile("cp.async.wait_group 2;\n");
        else if (ahead == 1) asm volatile("cp.async.wait_group 1;\n");
        else                 asm volatile("cp.async.wait_group 0;\n");
        __syncthreads();

        if (it + 3 < NT) {
            int s = (it + 3) % STAGESH, k0 = (it + 3) * BKH;
            unsigned ab = As_base + s*STG_HALFS*2, bb = Bs_base + s*STG_HALFS*2;
            cp_async16(ab + ad0, ag0 + k0, av0);
            cp_async16(ab + ad1, ag1 + k0, av1);
            cp_async16(bb + ad0, bg0 + k0, true);
            cp_async16(bb + ad1, bg1 + k0, true);
            asm volatile("cp.async.commit_group;\n");
        }

        const __half* Abuf = Ash + (it % STAGESH) * STG_HALFS;
        const __half* Bbuf = Bsh + (it % STAGESH) * STG_HALFS;

#pragma unroll
        for (int kk = 0; kk < BKH; kk += 16) {
            unsigned af[4][4], bf[4][2];
#pragma unroll
            for (int mt = 0; mt < 4; mt++) {
                int m = wm + mt*16 + g;
                af[mt][0] = *(const unsigned*)(Abuf + (m  )*APADH + kk + 2*tg);
                af[mt][1] = *(const unsigned*)(Abuf + (m+8)*APADH + kk + 2*tg);
                af[mt][2] = *(const unsigned*)(Abuf + (m  )*APADH + kk + 2*tg + 8);
                af[mt][3] = *(const unsigned*)(Abuf + (m+8)*APADH + kk + 2*tg + 8);
            }
#pragma unroll
            for (int nt = 0; nt < 4; nt++) {
                int n = wn + nt*8 + g;
                bf[nt][0] = *(const unsigned*)(Bbuf + n*APADH + kk + 2*tg);
                bf[nt][1] = *(const unsigned*)(Bbuf + n*APADH + kk + 2*tg + 8);
            }
#pragma unroll
            for (int mt = 0; mt < 4; mt++)
#pragma unroll
                for (int nt = 0; nt < 4; nt++)
                    asm volatile(
                        "mma.sync.aligned.m16n8k16.row.col.f32.f16.f16.f32 "
                        "{%0,%1,%2,%3}, {%4,%5,%6,%7}, {%8,%9}, {%0,%1,%2,%3};"
                        : "+f"(acc[mt][nt][0]), "+f"(acc[mt][nt][1]),
                          "+f"(acc[mt][nt][2]), "+f"(acc[mt][nt][3])
                        : "r"(af[mt][0]), "r"(af[mt][1]), "r"(af[mt][2]), "r"(af[mt][3]),
                          "r"(bf[nt][0]), "r"(bf[nt][1]));
        }
        // no trailing barrier: with 4 stages, the next write target (it+4)%4
        // was last read at iteration it, and every thread passes the top
        // barrier of iteration it+1 before any thread can issue that write.
    }

#pragma unroll
    for (int mt = 0; mt < 4; mt++) {
#pragma unroll
        for (int nt = 0; nt < 4; nt++) {
            int r0 = row0 + wm + mt*16 + g;
            int c  = col0 + wn + nt*8 + 2*tg;
            float v[4];
#pragma unroll
            for (int q = 0; q < 4; q++) {
                float u = acc[mt][nt][q];
                if (dogelu) u = 0.5f*u*(1.0f + erff(u*0.70710678118654752f));
                v[q] = u;
            }
            if (outhalf) {
                if (r0 < M)
                    *(__half2*)(CH + (size_t)r0*N + c) = __floats2half2_rn(v[0], v[1]);
                if (r0 + 8 < M)
                    *(__half2*)(CH + (size_t)(r0+8)*N + c) = __floats2half2_rn(v[2], v[3]);
            } else {
                if (r0 < M)     *(float2*)(C + (size_t)r0*N + c)     = make_float2(v[0], v[1]);
                if (r0 + 8 < M) *(float2*)(C + (size_t)(r0+8)*N + c) = make_float2(v[2], v[3]);
            }
        }
    }
}

// ---------------- growth EMA: fully fused blocked scan ----------------
__global__ __launch_bounds__(256) void growth_fused(const float* __restrict__ sw,
                                                    const float* __restrict__ z0,
                                                    const float* __restrict__ v0) {
    __shared__ float zb[GSEG][17];
    __shared__ float cb[GSEG][17];
    int b  = blockIdx.x >> 5;
    int c0 = (blockIdx.x & 31) << 4;
    int seg = threadIdx.x >> 4, ci = threadIdx.x & 15;
    int c = c0 + ci;
    float w = 1.f/(1.f + expf(-sw[c >> 6]));
    float omw = 1.f - w;
    int t0 = seg * GSEGLEN;
    const float* vp = VBUF + (size_t)b*Tn*Dn + c;

    float dv[GSEGLEN];
    float prev = (t0 == 0) ? z0[c] : vp[(size_t)(t0-1)*Dn];
    float z = 0.f;
#pragma unroll
    for (int l = 0; l < GSEGLEN; l++) {
        float v = vp[(size_t)(t0+l)*Dn];
        dv[l] = v - prev;
        prev = v;
        z = w*z + dv[l];
    }
    zb[seg][ci] = z;
    __syncthreads();

    if (threadIdx.x < 16) {
        int cc = threadIdx.x;
        float wj = 1.f/(1.f + expf(-sw[(c0 + cc) >> 6]));
        float w64 = 1.f;
        { float p = wj; int e = GSEGLEN; while (e) { if (e & 1) w64 *= p; p *= p; e >>= 1; } }
        float y = v0[c0 + cc];
        float omwj = 1.f - wj;
#pragma unroll
        for (int s = 0; s < GSEG; s++) {
            cb[s][cc] = y;
            y = w64*y + omwj*zb[s][cc];
        }
    }
    __syncthreads();

    __half* gp = GBUFH + (size_t)b*T1*Dn + c;
    float y = cb[seg][ci];
    if (seg == 0) gp[0] = __float2half(v0[c]);
#pragma unroll
    for (int l = 0; l < GSEGLEN; l++) {
        y = w*y + omw*dv[l];
        gp[(size_t)(t0+l+1)*Dn] = __float2half(y);
    }
}

// ---------------- layernorm helpers ----------------
__device__ __forceinline__ float block_reduce_sum(float v, float* red) {
    for (int o = 16; o; o >>= 1) v += __shfl_xor_sync(0xffffffffu, v, o);
    int wid = threadIdx.x >> 5;
    if ((threadIdx.x & 31) == 0) red[wid] = v;
    __syncthreads();
    if (threadIdx.x < 32) {
        float s = (threadIdx.x < 4) ? red[threadIdx.x] : 0.f;
        for (int o = 2; o; o >>= 1) s += __shfl_xor_sync(0xffffffffu, s, o);
        if (threadIdx.x == 0) red[0] = s;
    }
    __syncthreads();
    float r = red[0];
    __syncthreads();
    return r;
}

__global__ __launch_bounds__(128) void res2_kernel(const float* __restrict__ out_all,
                                                   const float* __restrict__ ng,
                                                   const float* __restrict__ nb) {
    __shared__ float red[32];
    int r = blockIdx.x;
    int b = r >> 10, t = r & 1023;
    const float* x1 = RES1 + (size_t)r*Dn;
    const float* gw = out_all + OFF_GROWTH + (size_t)(b*T1 + t + 1)*Dn;
    float vals[4]; float s = 0.f;
#pragma unroll
    for (int i = 0; i < 4; i++) {
        int d = threadIdx.x + i*128;
        vals[i] = x1[d] - gw[d];
        s += vals[i];
    }
    float mu = block_reduce_sum(s, red) * (1.0f/512.0f);
    float vs = 0.f;
#pragma unroll
    for (int i = 0; i < 4; i++) { float c = vals[i]-mu; vs += c*c; }
    float var = block_reduce_sum(vs, red) * (1.0f/512.0f);
    float inv = rsqrtf(var + 1e-5f);
#pragma unroll
    for (int i = 0; i < 4; i++) {
        int d = threadIdx.x + i*128;
        float v = (vals[i]-mu)*inv*ng[d] + nb[d];
        R2B [(size_t)r*Dn + d] = v;
        R2BH[(size_t)r*Dn + d] = __float2half(v);
    }
}

__global__ __launch_bounds__(128) void res3_kernel(float* __restrict__ out_all,
                                                   const float* __restrict__ ng,
                                                   const float* __restrict__ nb) {
    __shared__ float red[32];
    int r = blockIdx.x;
    float vals[4]; float s = 0.f;
#pragma unroll
    for (int i = 0; i < 4; i++) {
        int d = threadIdx.x + i*128;
        vals[i] = R2B[(size_t)r*Dn + d] + FOUT[(size_t)r*Dn + d];
        s += vals[i];
    }
    float mu = block_reduce_sum(s, red) * (1.0f/512.0f);
    float vs = 0.f;
#pragma unroll
    for (int i = 0; i < 4; i++) { float c = vals[i]-mu; vs += c*c; }
    float var = block_reduce_sum(vs, red) * (1.0f/512.0f);
    float inv = rsqrtf(var + 1e-5f);
#pragma unroll
    for (int i = 0; i < 4; i++) {
        int d = threadIdx.x + i*128;
        out_all[OFF_RES3 + (size_t)r*Dn + d] = (vals[i]-mu)*inv*ng[d] + nb[d];
    }
}

// ---------------- level projections ----------------
__global__ __launch_bounds__(256) void levelproj_kernel(const float* __restrict__ out_all,
                                                        const float* __restrict__ gpw,
                                                        const float* __restrict__ spw) {
    int warp = (blockIdx.x*256 + threadIdx.x) >> 5;
    int lane = threadIdx.x & 31;
    if (warp >= Bn*Tn) return;
    int b = warp >> 10, t = warp & 1023;
    const float* gr = out_all + OFF_GROWTH + (size_t)(b*T1 + t)*Dn;
    const float* se = out_all + OFF_SEASON + (size_t)(b*TP + t)*Dn;
    float ag[7] = {}, as_[7] = {};
    for (int d = lane; d < 512; d += 32) {
        float g = gr[d], s = se[d];
#pragma unroll
        for (int c = 0; c < 7; c++) { ag[c] += g*gpw[d*7+c]; as_[c] += s*spw[d*7+c]; }
    }
#pragma unroll
    for (int c = 0; c < 7; c++) {
        for (int o = 16; o; o >>= 1) {
            ag[c]  += __shfl_xor_sync(0xffffffffu, ag[c],  o);
            as_[c] += __shfl_xor_sync(0xffffffffu, as_[c], o);
        }
    }
    if (lane == 0) {
#pragma unroll
        for (int c = 0; c < 7; c++) {
            GS_G[(size_t)warp*7 + c] = ag[c];
            GS_S[(size_t)warp*7 + c] = as_[c];
        }
    }
}

// ---------------- level EMA: fully fused blocked scan ----------------
__global__ __launch_bounds__(256) void level_fused(const float* __restrict__ level,
                                                   const float* __restrict__ lsw,
                                                   const float* __restrict__ lv0,
                                                   float* __restrict__ out_all) {
    __shared__ float zb[GSEG][17];
    __shared__ float cb[GSEG][17];
    int seg = threadIdx.x >> 4, ci = threadIdx.x & 15;
    int ch = blockIdx.x * 16 + ci;
    int b = ch / COUTn, c = ch % COUTn;
    float w = 1.f/(1.f + expf(-lsw[c]));
    float omw = 1.f - w;
    int t0 = seg * GSEGLEN;
    const float* lp = level + (size_t)b*Tn*COUTn + c;
    const float* gp = GS_G  + (size_t)b*Tn*COUTn + c;
    const float* sp = GS_S  + (size_t)b*Tn*COUTn + c;

    float uv[GSEGLEN];
    float z = 0.f;
#pragma unroll
    for (int l = 0; l < GSEGLEN; l++) {
        int t = t0 + l;
        uv[l] = omw*(lp[t*COUTn] - sp[t*COUTn]) + w*gp[t*COUTn];
        z = w*z + uv[l];
    }
    zb[seg][ci] = z;
    __syncthreads();

    if (threadIdx.x < 16) {
        int cc = threadIdx.x;
        int ch2 = blockIdx.x * 16 + cc;
        float wj = 1.f/(1.f + expf(-lsw[ch2 % COUTn]));
        float w64 = 1.f;
        { float p = wj; int e = GSEGLEN; while (e) { if (e & 1) w64 *= p; p *= p; e >>= 1; } }
        float y = lv0[ch2 % COUTn];
#pragma unroll
        for (int s = 0; s < GSEG; s++) {
            cb[s][cc] = y;
            y = w64*y + zb[s][cc];
        }
    }
    __syncthreads();

    float* op = out_all + OFF_LEVEL + (size_t)b*Tn*COUTn + c;
    float y = cb[seg][ci];
#pragma unroll
    for (int l = 0; l < GSEGLEN; l++) {
        y = w*y + uv[l];
        op[(t0+l)*COUTn] = y;
    }
}

// ---------------- launch ----------------
extern "C" void kernel_launch(void* const* d_in, const int* in_sizes, int n_in,
                              void* d_out, int out_size) {
    const float* res      = (const float*)d_in[0];
    const float* level    = (const float*)d_in[1];
    const float* in_w     = (const float*)d_in[2];
    const float* out_w    = (const float*)d_in[3];
    const float* z0       = (const float*)d_in[4];
    const float* gsw      = (const float*)d_in[5];
    const float* gv0      = (const float*)d_in[6];
    const float* ff_w1    = (const float*)d_in[7];
    const float* ff_w2    = (const float*)d_in[8];
    const float* n1g      = (const float*)d_in[9];
    const float* n1b      = (const float*)d_in[10];
    const float* n2g      = (const float*)d_in[11];
    const float* n2b      = (const float*)d_in[12];
    const float* gpw      = (const float*)d_in[13];
    const float* spw      = (const float*)d_in[14];
    const float* lsw      = (const float*)d_in[15];
    const float* lv0      = (const float*)d_in[16];
    float* out = (float*)d_out;

    float *pVBUF, *pFOUT;
    __half *pRES1H, *pGBUFH, *pR2H, *pFBUFH, *pWTIN, *pWTOUT, *pWT1, *pWT2;
    cudaGetSymbolAddress((void**)&pVBUF,  VBUF);
    cudaGetSymbolAddress((void**)&pFOUT,  FOUT);
    cudaGetSymbolAddress((void**)&pRES1H, RES1H);
    cudaGetSymbolAddress((void**)&pGBUFH, GBUFH);
    cudaGetSymbolAddress((void**)&pR2H,   R2BH);
    cudaGetSymbolAddress((void**)&pFBUFH, FBUFH);
    cudaGetSymbolAddress((void**)&pWTIN,  WT_IN);
    cudaGetSymbolAddress((void**)&pWTOUT, WT_OUT);
    cudaGetSymbolAddress((void**)&pWT1,   WT_1);
    cudaGetSymbolAddress((void**)&pWT2,   WT_2);

    static int attr_set = 0;
    if (!attr_set) {
        cudaFuncSetAttribute(hgemm_kernel,
                             cudaFuncAttributeMaxDynamicSharedMemorySize, HS_TOTAL);
        attr_set = 1;
    }

    // 0) all 4 weight transposes in one launch
    transpose4<<<2560, 256>>>(in_w, pWTIN, out_w, pWTOUT, ff_w1, pWT1, ff_w2, pWT2);
    // 1) fused FFT + topk + season + res1
    fftseason_kernel<<<Bn*(Dn/4), 256>>>(res, out);
    // 2) v = res1 @ in_proj_w
    hgemm_kernel<<<dim3(Dn/128, (Bn*Tn)/128), 256, HS_TOTAL>>>(pRES1H, pWTIN,
                                                               pVBUF, 0,
                                                               Bn*Tn, Dn, Dn, 0, 0);
    // 3) fused diffs + EMA scan -> GBUFH
    growth_fused<<<Bn*32, 256>>>(gsw, z0, gv0);
    // 4) growth = GBUFH @ out_proj_w -> d_out
    hgemm_kernel<<<dim3(Dn/128, (Bn*T1 + 127)/128), 256, HS_TOTAL>>>(pGBUFH, pWTOUT,
                                                                     out + OFF_GROWTH, 0,
                                                                     Bn*T1, Dn, Dn, 0, 0);
    // 5) res2 = LN(res1 - growth[:,1:])
    res2_kernel<<<Bn*Tn, 128>>>(out, n1g, n1b);
    // 6) ffn1 = gelu(res2 @ ff_w1) -> half
    hgemm_kernel<<<dim3(LATENTn/128, (Bn*Tn)/128), 256, HS_TOTAL>>>(pR2H, pWT1,
                                                                    0, pFBUFH,
                                                                    Bn*Tn, LATENTn, Dn, 1, 1);
    // 7) ffn2 = ffn1 @ ff_w2 -> f32
    hgemm_kernel<<<dim3(Dn/128, (Bn*Tn)/128), 256, HS_TOTAL>>>(pFBUFH, pWT2,
                                                               pFOUT, 0,
                                                               Bn*Tn, Dn, LATENTn, 0, 0);
    // 8) res3 = LN(res2 + ffn2) -> d_out
    res3_kernel<<<Bn*Tn, 128>>>(out, n2g, n2b);
    // 9) level projections
    levelproj_kernel<<<(Bn*Tn*32)/256, 256>>>(out, gpw, spw);
    // 10) fused level EMA -> d_out
    level_fused<<<7, 256>>>(level, lsw, lv0, out);
}

// round 12
// speedup vs baseline: 2.2782x; 1.0303x over previous
#include <cuda_runtime.h>
#include <cuda_fp16.h>
#include <math.h>
#include <stdint.h>

#define Bn 16
#define Tn 1024
#define Dn 512
#define COUTn 7
#define PREDn 96
#define Kn 8
#define LATENTn 2048
#define TP (Tn + PREDn)
#define T1 (Tn + 1)

#define OFF_RES3   0
#define OFF_LEVEL  (Bn*Tn*Dn)
#define OFF_GROWTH (OFF_LEVEL + Bn*Tn*COUTn)
#define OFF_SEASON (OFF_GROWTH + Bn*T1*Dn)

#define GSEG 16
#define GSEGLEN 64

// fp16 GEMM tiling: 4 stages, single barrier per K-iter
#define STAGESH 4
#define BKH 32
#define APADH 40
#define STG_HALFS (128*APADH)
#define HS_TOTAL (STAGESH*2*STG_HALFS*2)   /* 81920 B */

// ---------------- scratch ----------------
__device__ float RES1 [Bn*Tn*Dn];
__device__ __align__(256) __half RES1H[Bn*Tn*Dn];
__device__ float VBUF[Bn*Tn*Dn];
__device__ __align__(256) __half GBUFH[Bn*T1*Dn];
__device__ float R2B [Bn*Tn*Dn];
__device__ __align__(256) __half R2BH[Bn*Tn*Dn];
__device__ __align__(256) __half FBUFH[Bn*Tn*LATENTn];
__device__ float FOUT[Bn*Tn*Dn];
__device__ __align__(256) __half WT_IN [Dn*Dn];
__device__ __align__(256) __half WT_OUT[Dn*Dn];
__device__ __align__(256) __half WT_1  [LATENTn*Dn];
__device__ __align__(256) __half WT_2  [Dn*LATENTn];
__device__ float GS_G[Bn*Tn*COUTn];
__device__ float GS_S[Bn*Tn*COUTn];

// ---------------- fused transpose of all 4 weight matrices ----------------
__global__ __launch_bounds__(256) void transpose4(const float* __restrict__ s0, __half* __restrict__ d0p,
                                                  const float* __restrict__ s1, __half* __restrict__ d1p,
                                                  const float* __restrict__ s2, __half* __restrict__ d2p,
                                                  const float* __restrict__ s3, __half* __restrict__ d3p) {
    __shared__ float t[32][33];
    int id = blockIdx.x;
    const float* src; __half* dst; int R, C, bx, by;
    if (id < 256)       { src = s0; dst = d0p; R = Dn;      C = Dn;      bx = id & 15;        by = id >> 4; }
    else if (id < 512)  { id -= 256;  src = s1; dst = d1p; R = Dn;      C = Dn;      bx = id & 15; by = id >> 4; }
    else if (id < 1536) { id -= 512;  src = s2; dst = d2p; R = Dn;      C = LATENTn; bx = id & 63; by = id >> 6; }
    else                { id -= 1536; src = s3; dst = d3p; R = LATENTn; C = Dn;      bx = id & 15; by = id >> 4; }
    int tx = threadIdx.x & 31, ty = threadIdx.x >> 5;
    int c0 = bx*32, r0 = by*32;
#pragma unroll
    for (int i = 0; i < 4; i++)
        t[ty + i*8][tx] = src[(size_t)(r0 + ty + i*8)*C + c0 + tx];
    __syncthreads();
#pragma unroll
    for (int i = 0; i < 4; i++)
        dst[(size_t)(c0 + ty + i*8)*R + r0 + tx] = __float2half(t[tx][ty + i*8]);
}

// ---------------- fused FFT + top-8 + season + res1 ----------------
__global__ __launch_bounds__(256) void fftseason_kernel(const float* __restrict__ x,
                                                        float* __restrict__ out) {
    __shared__ float2 data[4][1024];
    __shared__ float2 tw[512];
    __shared__ float  mag[4][512];
    __shared__ int    chm[4][8];
    __shared__ float  chre[4][8], chim[4][8];

    int tid = threadIdx.x;
    int b   = blockIdx.x >> 7;
    int d0  = (blockIdx.x & 127) << 2;

    for (int k = tid; k < 512; k += 256) {
        float s, c;
        sincosf(-6.283185307179586f * (float)k / 1024.0f, &s, &c);
        tw[k] = make_float2(c, s);
    }
    const float* xb = x + (size_t)b * Tn * Dn;
    for (int i = tid; i < 4096; i += 256) {
        int t = i >> 2, j = i & 3;
        data[j][t] = make_float2(xb[(size_t)t*Dn + d0 + j], 0.f);
    }
    __syncthreads();

    int tmul = 1;
    for (int half = 512; half >= 1; half >>= 1, tmul <<= 1) {
        for (int i = tid; i < 2048; i += 256) {
            int s  = i >> 9;
            int bf = i & 511;
            int k  = bf & (half - 1);
            int pos = 2*bf - k;
            float2 u = data[s][pos], v = data[s][pos + half];
            data[s][pos] = make_float2(u.x + v.x, u.y + v.y);
            float2 t2 = make_float2(u.x - v.x, u.y - v.y);
            float2 w  = tw[k * tmul];
            data[s][pos + half] = make_float2(t2.x*w.x - t2.y*w.y,
                                              t2.x*w.y + t2.y*w.x);
        }
        __syncthreads();
    }

    for (int i = tid; i < 2048; i += 256) {
        int s = i >> 9, f = i & 511;
        if (f == 0) { mag[s][0] = -1e30f; continue; }
        int j = (int)(__brev((unsigned)f) >> 22);
        float2 v = data[s][j];
        mag[s][f] = v.x*v.x + v.y*v.y;
    }
    __syncthreads();

    int wid = tid >> 5, lane = tid & 31;
    if (wid < 4) {
        int s = wid;
#pragma unroll
        for (int it = 0; it < 8; it++) {
            float bestm = -1e29f; int bestf = 1 << 20;
            for (int f = lane; f < 512; f += 32) {
                float m2 = mag[s][f];
                if (m2 > bestm || (m2 == bestm && f < bestf)) { bestm = m2; bestf = f; }
            }
            for (int off = 16; off; off >>= 1) {
                float om = __shfl_xor_sync(0xffffffffu, bestm, off);
                int   of = __shfl_xor_sync(0xffffffffu, bestf, off);
                if (om > bestm || (om == bestm && of < bestf)) { bestm = om; bestf = of; }
            }
            if (lane == 0) {
                int j = (int)(__brev((unsigned)bestf) >> 22);
                float2 v = data[s][j];
                chm [s][it] = bestf;
                chre[s][it] = v.x * (2.0f / (float)Tn);
                chim[s][it] = v.y * (2.0f / (float)Tn);
                mag[s][bestf] = -1e30f;
            }
            __syncwarp();
        }
    }
    __syncthreads();

    float* ctab = &mag[0][0];
    for (int j = tid; j < 1024; j += 256)
        ctab[j] = (j < 512) ? tw[j].x : -tw[j - 512].x;
    __syncthreads();

    {
        int s = tid & 3;
        int ms[8]; float re[8], im[8];
#pragma unroll
        for (int k = 0; k < 8; k++) { ms[k] = chm[s][k]; re[k] = chre[s][k]; im[k] = chim[s][k]; }
        int d = d0 + s;
        float*       seas = out + OFF_SEASON + (size_t)b*TP*Dn + d;
        const float* rb   = x + (size_t)b*Tn*Dn + d;
        float*       r1   = RES1  + (size_t)b*Tn*Dn + d;
        __half*      r1h  = RES1H + (size_t)b*Tn*Dn + d;
        for (int t = tid >> 2; t < TP; t += 64) {
            float acc = 0.f;
#pragma unroll
            for (int k = 0; k < 8; k++) {
                int idx = (ms[k]*t) & 1023;
                acc += re[k]*ctab[idx] - im[k]*ctab[(idx + 768) & 1023];
            }
            seas[(size_t)t*Dn] = acc;
            if (t < Tn) {
                float v = rb[(size_t)t*Dn] - acc;
                r1 [(size_t)t*Dn] = v;
                r1h[(size_t)t*Dn] = __float2half(v);
            }
        }
    }
}

// ---------------- fp16 tensor-core GEMM, cp.async 4-stage, 1 barrier/iter ----------------
__device__ __forceinline__ void cp_async16(unsigned saddr, const void* gptr, bool valid) {
    int sz = valid ? 16 : 0;
    asm volatile("cp.async.cg.shared.global [%0], [%1], 16, %2;\n"
                 :: "r"(saddr), "l"(gptr), "r"(sz));
}

__global__ __launch_bounds__(256) void hgemm_kernel(const __half* __restrict__ A,
                                                    const __half* __restrict__ BT,
                                                    float* __restrict__ C,
                                                    __half* __restrict__ CH,
                                                    int M, int N, int K,
                                                    int dogelu, int outhalf) {
    extern __shared__ __half smh[];
    __half* Ash = smh;
    __half* Bsh = smh + STAGESH * STG_HALFS;
    unsigned As_base = (unsigned)__cvta_generic_to_shared(Ash);
    unsigned Bs_base = (unsigned)__cvta_generic_to_shared(Bsh);

    int tid = threadIdx.x;
    int row0 = blockIdx.y * 128, col0 = blockIdx.x * 128;
    int wid = tid >> 5, lane = tid & 31;
    int wm = (wid & 1) * 64, wn = (wid >> 1) * 32;
    int g = lane >> 2, tg = lane & 3;

    float acc[4][4][4];
#pragma unroll
    for (int i = 0; i < 4; i++)
#pragma unroll
        for (int j = 0; j < 4; j++)
#pragma unroll
            for (int q = 0; q < 4; q++) acc[i][j][q] = 0.f;

    const int NT = K / BKH;

    int ch0 = tid, ch1 = tid + 256;
    int ra0 = ch0 >> 2, ca0 = ch0 & 3;
    int ra1 = ch1 >> 2, ca1 = ch1 & 3;
    bool av0 = (row0 + ra0) < M, av1 = (row0 + ra1) < M;
    const __half* ag0 = A + (size_t)(row0 + ra0)*K + ca0*8;
    const __half* ag1 = A + (size_t)(row0 + ra1)*K + ca1*8;
    const __half* bg0 = BT + (size_t)(col0 + ra0)*K + ca0*8;
    const __half* bg1 = BT + (size_t)(col0 + ra1)*K + ca1*8;
    unsigned ad0 = (unsigned)(ra0*APADH + ca0*8)*2, ad1 = (unsigned)(ra1*APADH + ca1*8)*2;

#pragma unroll
    for (int s = 0; s < 3; s++) {
        unsigned ab = As_base + s*STG_HALFS*2, bb = Bs_base + s*STG_HALFS*2;
        int k0 = s * BKH;
        cp_async16(ab + ad0, ag0 + k0, av0);
        cp_async16(ab + ad1, ag1 + k0, av1);
        cp_async16(bb + ad0, bg0 + k0, true);
        cp_async16(bb + ad1, bg1 + k0, true);
        asm volatile("cp.async.commit_group;\n");
    }

    for (int it = 0; it < NT; it++) {
        int ahead = NT - 1 - it;
        if (ahead >= 2)      asm volatile("cp.async.wait_group 2;\n");
        else if (ahead == 1) asm volatile("cp.async.wait_group 1;\n");
        else                 asm volatile("cp.async.wait_group 0;\n");
        __syncthreads();

        if (it + 3 < NT) {
            int s = (it + 3) % STAGESH, k0 = (it + 3) * BKH;
            unsigned ab = As_base + s*STG_HALFS*2, bb = Bs_base + s*STG_HALFS*2;
            cp_async16(ab + ad0, ag0 + k0, av0);
            cp_async16(ab + ad1, ag1 + k0, av1);
            cp_async16(bb + ad0, bg0 + k0, true);
            cp_async16(bb + ad1, bg1 + k0, true);
            asm volatile("cp.async.commit_group;\n");
        }

        const __half* Abuf = Ash + (it % STAGESH) * STG_HALFS;
        const __half* Bbuf = Bsh + (it % STAGESH) * STG_HALFS;

#pragma unroll
        for (int kk = 0; kk < BKH; kk += 16) {
            unsigned af[4][4], bf[4][2];
#pragma unroll
            for (int mt = 0; mt < 4; mt++) {
                int m = wm + mt*16 + g;
                af[mt][0] = *(const unsigned*)(Abuf + (m  )*APADH + kk + 2*tg);
                af[mt][1] = *(const unsigned*)(Abuf + (m+8)*APADH + kk + 2*tg);
                af[mt][2] = *(const unsigned*)(Abuf + (m  )*APADH + kk + 2*tg + 8);
                af[mt][3] = *(const unsigned*)(Abuf + (m+8)*APADH + kk + 2*tg + 8);
            }
#pragma unroll
            for (int nt = 0; nt < 4; nt++) {
                int n = wn + nt*8 + g;
                bf[nt][0] = *(const unsigned*)(Bbuf + n*APADH + kk + 2*tg);
                bf[nt][1] = *(const unsigned*)(Bbuf + n*APADH + kk + 2*tg + 8);
            }
#pragma unroll
            for (int mt = 0; mt < 4; mt++)
#pragma unroll
                for (int nt = 0; nt < 4; nt++)
                    asm volatile(
                        "mma.sync.aligned.m16n8k16.row.col.f32.f16.f16.f32 "
                        "{%0,%1,%2,%3}, {%4,%5,%6,%7}, {%8,%9}, {%0,%1,%2,%3};"
                        : "+f"(acc[mt][nt][0]), "+f"(acc[mt][nt][1]),
                          "+f"(acc[mt][nt][2]), "+f"(acc[mt][nt][3])
                        : "r"(af[mt][0]), "r"(af[mt][1]), "r"(af[mt][2]), "r"(af[mt][3]),
                          "r"(bf[nt][0]), "r"(bf[nt][1]));
        }
    }

#pragma unroll
    for (int mt = 0; mt < 4; mt++) {
#pragma unroll
        for (int nt = 0; nt < 4; nt++) {
            int r0 = row0 + wm + mt*16 + g;
            int c  = col0 + wn + nt*8 + 2*tg;
            float v[4];
#pragma unroll
            for (int q = 0; q < 4; q++) {
                float u = acc[mt][nt][q];
                if (dogelu) u = 0.5f*u*(1.0f + erff(u*0.70710678118654752f));
                v[q] = u;
            }
            if (outhalf) {
                if (r0 < M)
                    *(__half2*)(CH + (size_t)r0*N + c) = __floats2half2_rn(v[0], v[1]);
                if (r0 + 8 < M)
                    *(__half2*)(CH + (size_t)(r0+8)*N + c) = __floats2half2_rn(v[2], v[3]);
            } else {
                if (r0 < M)     *(float2*)(C + (size_t)r0*N + c)     = make_float2(v[0], v[1]);
                if (r0 + 8 < M) *(float2*)(C + (size_t)(r0+8)*N + c) = make_float2(v[2], v[3]);
            }
        }
    }
}

// ---------------- growth EMA: fused blocked scan, 512 threads (coalesced) ----------------
__global__ __launch_bounds__(512) void growth_fused(const float* __restrict__ sw,
                                                    const float* __restrict__ z0,
                                                    const float* __restrict__ v0) {
    __shared__ float zb[GSEG][33];
    __shared__ float cb[GSEG][33];
    int b  = blockIdx.x >> 4;
    int c0 = (blockIdx.x & 15) << 5;
    int seg = threadIdx.x >> 5, ci = threadIdx.x & 31;
    int c = c0 + ci;
    float w = 1.f/(1.f + expf(-sw[c >> 6]));
    float omw = 1.f - w;
    int t0 = seg * GSEGLEN;
    const float* vp = VBUF + (size_t)b*Tn*Dn + c;

    float dv[GSEGLEN];
    float prev = (t0 == 0) ? z0[c] : vp[(size_t)(t0-1)*Dn];
    float z = 0.f;
#pragma unroll
    for (int l = 0; l < GSEGLEN; l++) {
        float v = vp[(size_t)(t0+l)*Dn];
        dv[l] = v - prev;
        prev = v;
        z = w*z + dv[l];
    }
    zb[seg][ci] = z;
    __syncthreads();

    if (threadIdx.x < 32) {
        int cc = threadIdx.x;
        float wj = 1.f/(1.f + expf(-sw[(c0 + cc) >> 6]));
        float w64 = 1.f;
        { float p = wj; int e = GSEGLEN; while (e) { if (e & 1) w64 *= p; p *= p; e >>= 1; } }
        float y = v0[c0 + cc];
        float omwj = 1.f - wj;
#pragma unroll
        for (int s = 0; s < GSEG; s++) {
            cb[s][cc] = y;
            y = w64*y + omwj*zb[s][cc];
        }
    }
    __syncthreads();

    __half* gp = GBUFH + (size_t)b*T1*Dn + c;
    float y = cb[seg][ci];
    if (seg == 0) gp[0] = __float2half(v0[c]);
#pragma unroll
    for (int l = 0; l < GSEGLEN; l++) {
        y = w*y + omw*dv[l];
        gp[(size_t)(t0+l+1)*Dn] = __float2half(y);
    }
}

// ---------------- layernorm helpers ----------------
__device__ __forceinline__ float block_reduce_sum(float v, float* red) {
    for (int o = 16; o; o >>= 1) v += __shfl_xor_sync(0xffffffffu, v, o);
    int wid = threadIdx.x >> 5;
    if ((threadIdx.x & 31) == 0) red[wid] = v;
    __syncthreads();
    if (threadIdx.x < 32) {
        float s = (threadIdx.x < 4) ? red[threadIdx.x] : 0.f;
        for (int o = 2; o; o >>= 1) s += __shfl_xor_sync(0xffffffffu, s, o);
        if (threadIdx.x == 0) red[0] = s;
    }
    __syncthreads();
    float r = red[0];
    __syncthreads();
    return r;
}

__global__ __launch_bounds__(128) void res2_kernel(const float* __restrict__ out_all,
                                                   const float* __restrict__ ng,
                                                   const float* __restrict__ nb) {
    __shared__ float red[32];
    int r = blockIdx.x;
    int b = r >> 10, t = r & 1023;
    const float* x1 = RES1 + (size_t)r*Dn;
    const float* gw = out_all + OFF_GROWTH + (size_t)(b*T1 + t + 1)*Dn;
    float vals[4]; float s = 0.f;
#pragma unroll
    for (int i = 0; i < 4; i++) {
        int d = threadIdx.x + i*128;
        vals[i] = x1[d] - gw[d];
        s += vals[i];
    }
    float mu = block_reduce_sum(s, red) * (1.0f/512.0f);
    float vs = 0.f;
#pragma unroll
    for (int i = 0; i < 4; i++) { float c = vals[i]-mu; vs += c*c; }
    float var = block_reduce_sum(vs, red) * (1.0f/512.0f);
    float inv = rsqrtf(var + 1e-5f);
#pragma unroll
    for (int i = 0; i < 4; i++) {
        int d = threadIdx.x + i*128;
        float v = (vals[i]-mu)*inv*ng[d] + nb[d];
        R2B [(size_t)r*Dn + d] = v;
        R2BH[(size_t)r*Dn + d] = __float2half(v);
    }
}

__global__ __launch_bounds__(128) void res3_kernel(float* __restrict__ out_all,
                                                   const float* __restrict__ ng,
                                                   const float* __restrict__ nb) {
    __shared__ float red[32];
    int r = blockIdx.x;
    float vals[4]; float s = 0.f;
#pragma unroll
    for (int i = 0; i < 4; i++) {
        int d = threadIdx.x + i*128;
        vals[i] = R2B[(size_t)r*Dn + d] + FOUT[(size_t)r*Dn + d];
        s += vals[i];
    }
    float mu = block_reduce_sum(s, red) * (1.0f/512.0f);
    float vs = 0.f;
#pragma unroll
    for (int i = 0; i < 4; i++) { float c = vals[i]-mu; vs += c*c; }
    float var = block_reduce_sum(vs, red) * (1.0f/512.0f);
    float inv = rsqrtf(var + 1e-5f);
#pragma unroll
    for (int i = 0; i < 4; i++) {
        int d = threadIdx.x + i*128;
        out_all[OFF_RES3 + (size_t)r*Dn + d] = (vals[i]-mu)*inv*ng[d] + nb[d];
    }
}

// ---------------- level projections ----------------
__global__ __launch_bounds__(256) void levelproj_kernel(const float* __restrict__ out_all,
                                                        const float* __restrict__ gpw,
                                                        const float* __restrict__ spw) {
    int warp = (blockIdx.x*256 + threadIdx.x) >> 5;
    int lane = threadIdx.x & 31;
    if (warp >= Bn*Tn) return;
    int b = warp >> 10, t = warp & 1023;
    const float* gr = out_all + OFF_GROWTH + (size_t)(b*T1 + t)*Dn;
    const float* se = out_all + OFF_SEASON + (size_t)(b*TP + t)*Dn;
    float ag[7] = {}, as_[7] = {};
    for (int d = lane; d < 512; d += 32) {
        float g = gr[d], s = se[d];
#pragma unroll
        for (int c = 0; c < 7; c++) { ag[c] += g*gpw[d*7+c]; as_[c] += s*spw[d*7+c]; }
    }
#pragma unroll
    for (int c = 0; c < 7; c++) {
        for (int o = 16; o; o >>= 1) {
            ag[c]  += __shfl_xor_sync(0xffffffffu, ag[c],  o);
            as_[c] += __shfl_xor_sync(0xffffffffu, as_[c], o);
        }
    }
    if (lane == 0) {
#pragma unroll
        for (int c = 0; c < 7; c++) {
            GS_G[(size_t)warp*7 + c] = ag[c];
            GS_S[(size_t)warp*7 + c] = as_[c];
        }
    }
}

// ---------------- level EMA: fully fused blocked scan ----------------
__global__ __launch_bounds__(256) void level_fused(const float* __restrict__ level,
                                                   const float* __restrict__ lsw,
                                                   const float* __restrict__ lv0,
                                                   float* __restrict__ out_all) {
    __shared__ float zb[GSEG][17];
    __shared__ float cb[GSEG][17];
    int seg = threadIdx.x >> 4, ci = threadIdx.x & 15;
    int ch = blockIdx.x * 16 + ci;
    int b = ch / COUTn, c = ch % COUTn;
    float w = 1.f/(1.f + expf(-lsw[c]));
    float omw = 1.f - w;
    int t0 = seg * GSEGLEN;
    const float* lp = level + (size_t)b*Tn*COUTn + c;
    const float* gp = GS_G  + (size_t)b*Tn*COUTn + c;
    const float* sp = GS_S  + (size_t)b*Tn*COUTn + c;

    float uv[GSEGLEN];
    float z = 0.f;
#pragma unroll
    for (int l = 0; l < GSEGLEN; l++) {
        int t = t0 + l;
        uv[l] = omw*(lp[t*COUTn] - sp[t*COUTn]) + w*gp[t*COUTn];
        z = w*z + uv[l];
    }
    zb[seg][ci] = z;
    __syncthreads();

    if (threadIdx.x < 16) {
        int cc = threadIdx.x;
        int ch2 = blockIdx.x * 16 + cc;
        float wj = 1.f/(1.f + expf(-lsw[ch2 % COUTn]));
        float w64 = 1.f;
        { float p = wj; int e = GSEGLEN; while (e) { if (e & 1) w64 *= p; p *= p; e >>= 1; } }
        float y = lv0[ch2 % COUTn];
#pragma unroll
        for (int s = 0; s < GSEG; s++) {
            cb[s][cc] = y;
            y = w64*y + zb[s][cc];
        }
    }
    __syncthreads();

    float* op = out_all + OFF_LEVEL + (size_t)b*Tn*COUTn + c;
    float y = cb[seg][ci];
#pragma unroll
    for (int l = 0; l < GSEGLEN; l++) {
        y = w*y + uv[l];
        op[(t0+l)*COUTn] = y;
    }
}

// ---------------- launch ----------------
extern "C" void kernel_launch(void* const* d_in, const int* in_sizes, int n_in,
                              void* d_out, int out_size) {
    const float* res      = (const float*)d_in[0];
    const float* level    = (const float*)d_in[1];
    const float* in_w     = (const float*)d_in[2];
    const float* out_w    = (const float*)d_in[3];
    const float* z0       = (const float*)d_in[4];
    const float* gsw      = (const float*)d_in[5];
    const float* gv0      = (const float*)d_in[6];
    const float* ff_w1    = (const float*)d_in[7];
    const float* ff_w2    = (const float*)d_in[8];
    const float* n1g      = (const float*)d_in[9];
    const float* n1b      = (const float*)d_in[10];
    const float* n2g      = (const float*)d_in[11];
    const float* n2b      = (const float*)d_in[12];
    const float* gpw      = (const float*)d_in[13];
    const float* spw      = (const float*)d_in[14];
    const float* lsw      = (const float*)d_in[15];
    const float* lv0      = (const float*)d_in[16];
    float* out = (float*)d_out;

    float *pVBUF, *pFOUT;
    __half *pRES1H, *pGBUFH, *pR2H, *pFBUFH, *pWTIN, *pWTOUT, *pWT1, *pWT2;
    cudaGetSymbolAddress((void**)&pVBUF,  VBUF);
    cudaGetSymbolAddress((void**)&pFOUT,  FOUT);
    cudaGetSymbolAddress((void**)&pRES1H, RES1H);
    cudaGetSymbolAddress((void**)&pGBUFH, GBUFH);
    cudaGetSymbolAddress((void**)&pR2H,   R2BH);
    cudaGetSymbolAddress((void**)&pFBUFH, FBUFH);
    cudaGetSymbolAddress((void**)&pWTIN,  WT_IN);
    cudaGetSymbolAddress((void**)&pWTOUT, WT_OUT);
    cudaGetSymbolAddress((void**)&pWT1,   WT_1);
    cudaGetSymbolAddress((void**)&pWT2,   WT_2);

    static int init_done = 0;
    static cudaStream_t s2;
    static cudaEvent_t evA, evB, evC, evD;
    if (!init_done) {
        cudaFuncSetAttribute(hgemm_kernel,
                             cudaFuncAttributeMaxDynamicSharedMemorySize, HS_TOTAL);
        cudaStreamCreateWithFlags(&s2, cudaStreamNonBlocking);
        cudaEventCreateWithFlags(&evA, cudaEventDisableTiming);
        cudaEventCreateWithFlags(&evB, cudaEventDisableTiming);
        cudaEventCreateWithFlags(&evC, cudaEventDisableTiming);
        cudaEventCreateWithFlags(&evD, cudaEventDisableTiming);
        init_done = 1;
    }

    // fork: transpose4 on s2, concurrent with fftseason on main stream
    cudaEventRecord(evA, 0);
    cudaStreamWaitEvent(s2, evA, 0);
    transpose4<<<2560, 256, 0, s2>>>(in_w, pWTIN, out_w, pWTOUT, ff_w1, pWT1, ff_w2, pWT2);
    cudaEventRecord(evB, s2);

    // fused FFT + topk + season + res1 (main stream)
    fftseason_kernel<<<Bn*(Dn/4), 256>>>(res, out);

    // join before GEMM1 (needs WT_IN)
    cudaStreamWaitEvent(0, evB, 0);

    // GEMM1: v = res1 @ in_proj_w
    hgemm_kernel<<<dim3(Dn/128, (Bn*Tn)/128), 256, HS_TOTAL>>>(pRES1H, pWTIN,
                                                               pVBUF, 0,
                                                               Bn*Tn, Dn, Dn, 0, 0);
    // fused diffs + EMA scan -> GBUFH
    growth_fused<<<Bn*16, 512>>>(gsw, z0, gv0);
    // GEMM2: growth = GBUFH @ out_proj_w -> d_out
    hgemm_kernel<<<dim3(Dn/128, (Bn*T1 + 127)/128), 256, HS_TOTAL>>>(pGBUFH, pWTOUT,
                                                                     out + OFF_GROWTH, 0,
                                                                     Bn*T1, Dn, Dn, 0, 0);

    // fork: level path (depends on growth + season only) runs on s2,
    // concurrent with res2 -> GEMM3 -> GEMM4 -> res3 on main stream
    cudaEventRecord(evC, 0);
    cudaStreamWaitEvent(s2, evC, 0);
    levelproj_kernel<<<(Bn*Tn*32)/256, 256, 0, s2>>>(out, gpw, spw);
    level_fused<<<7, 256, 0, s2>>>(level, lsw, lv0, out);
    cudaEventRecord(evD, s2);

    // main chain
    res2_kernel<<<Bn*Tn, 128>>>(out, n1g, n1b);
    hgemm_kernel<<<dim3(LATENTn/128, (Bn*Tn)/128), 256, HS_TOTAL>>>(pR2H, pWT1,
                                                                    0, pFBUFH,
                                                                    Bn*Tn, LATENTn, Dn, 1, 1);
    hgemm_kernel<<<dim3(Dn/128, (Bn*Tn)/128), 256, HS_TOTAL>>>(pFBUFH, pWT2,
                                                               pFOUT, 0,
                                                               Bn*Tn, Dn, LATENTn, 0, 0);
    res3_kernel<<<Bn*Tn, 128>>>(out, n2g, n2b);

    // join level path before graph end
    cudaStreamWaitEvent(0, evD, 0);
}

// round 13
// speedup vs baseline: 2.3131x; 1.0153x over previous
#include <cuda_runtime.h>
#include <cuda_fp16.h>
#include <math.h>
#include <stdint.h>

#define Bn 16
#define Tn 1024
#define Dn 512
#define COUTn 7
#define PREDn 96
#define Kn 8
#define LATENTn 2048
#define TP (Tn + PREDn)
#define T1 (Tn + 1)

#define OFF_RES3   0
#define OFF_LEVEL  (Bn*Tn*Dn)
#define OFF_GROWTH (OFF_LEVEL + Bn*Tn*COUTn)
#define OFF_SEASON (OFF_GROWTH + Bn*T1*Dn)

#define GSEG 16
#define GSEGLEN 64

// fp16 GEMM tiling: 4 stages, single barrier per K-iter
#define STAGESH 4
#define BKH 32
#define APADH 40
#define STG_HALFS (128*APADH)
#define HS_TOTAL (STAGESH*2*STG_HALFS*2)   /* 81920 B */

// ---------------- scratch ----------------
__device__ __align__(256) __half RES1H[Bn*Tn*Dn];
__device__ float VBUF[Bn*Tn*Dn];
__device__ __align__(256) __half GBUFH[Bn*T1*Dn];
__device__ __align__(256) __half R2BH[Bn*Tn*Dn];
__device__ __align__(256) __half FBUFH[Bn*Tn*LATENTn];
__device__ __align__(256) __half FOUTH[Bn*Tn*Dn];
__device__ __align__(256) __half WT_IN [Dn*Dn];
__device__ __align__(256) __half WT_OUT[Dn*Dn];
__device__ __align__(256) __half WT_1  [LATENTn*Dn];
__device__ __align__(256) __half WT_2  [Dn*LATENTn];
__device__ float GS_G[Bn*Tn*COUTn];
__device__ float GS_S[Bn*Tn*COUTn];

// ---------------- fused transpose of all 4 weight matrices ----------------
__global__ __launch_bounds__(256) void transpose4(const float* __restrict__ s0, __half* __restrict__ d0p,
                                                  const float* __restrict__ s1, __half* __restrict__ d1p,
                                                  const float* __restrict__ s2, __half* __restrict__ d2p,
                                                  const float* __restrict__ s3, __half* __restrict__ d3p) {
    __shared__ float t[32][33];
    int id = blockIdx.x;
    const float* src; __half* dst; int R, C, bx, by;
    if (id < 256)       { src = s0; dst = d0p; R = Dn;      C = Dn;      bx = id & 15;        by = id >> 4; }
    else if (id < 512)  { id -= 256;  src = s1; dst = d1p; R = Dn;      C = Dn;      bx = id & 15; by = id >> 4; }
    else if (id < 1536) { id -= 512;  src = s2; dst = d2p; R = Dn;      C = LATENTn; bx = id & 63; by = id >> 6; }
    else                { id -= 1536; src = s3; dst = d3p; R = LATENTn; C = Dn;      bx = id & 15; by = id >> 4; }
    int tx = threadIdx.x & 31, ty = threadIdx.x >> 5;
    int c0 = bx*32, r0 = by*32;
#pragma unroll
    for (int i = 0; i < 4; i++)
        t[ty + i*8][tx] = src[(size_t)(r0 + ty + i*8)*C + c0 + tx];
    __syncthreads();
#pragma unroll
    for (int i = 0; i < 4; i++)
        dst[(size_t)(c0 + ty + i*8)*R + r0 + tx] = __float2half(t[tx][ty + i*8]);
}

// ---------------- fused FFT + top-8 + season + res1(half) ----------------
__global__ __launch_bounds__(256) void fftseason_kernel(const float* __restrict__ x,
                                                        float* __restrict__ out) {
    __shared__ float2 data[4][1024];
    __shared__ float2 tw[512];
    __shared__ float  mag[4][512];
    __shared__ int    chm[4][8];
    __shared__ float  chre[4][8], chim[4][8];

    int tid = threadIdx.x;
    int b   = blockIdx.x >> 7;
    int d0  = (blockIdx.x & 127) << 2;

    for (int k = tid; k < 512; k += 256) {
        float s, c;
        sincosf(-6.283185307179586f * (float)k / 1024.0f, &s, &c);
        tw[k] = make_float2(c, s);
    }
    const float* xb = x + (size_t)b * Tn * Dn;
    for (int i = tid; i < 4096; i += 256) {
        int t = i >> 2, j = i & 3;
        data[j][t] = make_float2(xb[(size_t)t*Dn + d0 + j], 0.f);
    }
    __syncthreads();

    int tmul = 1;
    for (int half = 512; half >= 1; half >>= 1, tmul <<= 1) {
        for (int i = tid; i < 2048; i += 256) {
            int s  = i >> 9;
            int bf = i & 511;
            int k  = bf & (half - 1);
            int pos = 2*bf - k;
            float2 u = data[s][pos], v = data[s][pos + half];
            data[s][pos] = make_float2(u.x + v.x, u.y + v.y);
            float2 t2 = make_float2(u.x - v.x, u.y - v.y);
            float2 w  = tw[k * tmul];
            data[s][pos + half] = make_float2(t2.x*w.x - t2.y*w.y,
                                              t2.x*w.y + t2.y*w.x);
        }
        __syncthreads();
    }

    for (int i = tid; i < 2048; i += 256) {
        int s = i >> 9, f = i & 511;
        if (f == 0) { mag[s][0] = -1e30f; continue; }
        int j = (int)(__brev((unsigned)f) >> 22);
        float2 v = data[s][j];
        mag[s][f] = v.x*v.x + v.y*v.y;
    }
    __syncthreads();

    int wid = tid >> 5, lane = tid & 31;
    if (wid < 4) {
        int s = wid;
#pragma unroll
        for (int it = 0; it < 8; it++) {
            float bestm = -1e29f; int bestf = 1 << 20;
            for (int f = lane; f < 512; f += 32) {
                float m2 = mag[s][f];
                if (m2 > bestm || (m2 == bestm && f < bestf)) { bestm = m2; bestf = f; }
            }
            for (int off = 16; off; off >>= 1) {
                float om = __shfl_xor_sync(0xffffffffu, bestm, off);
                int   of = __shfl_xor_sync(0xffffffffu, bestf, off);
                if (om > bestm || (om == bestm && of < bestf)) { bestm = om; bestf = of; }
            }
            if (lane == 0) {
                int j = (int)(__brev((unsigned)bestf) >> 22);
                float2 v = data[s][j];
                chm [s][it] = bestf;
                chre[s][it] = v.x * (2.0f / (float)Tn);
                chim[s][it] = v.y * (2.0f / (float)Tn);
                mag[s][bestf] = -1e30f;
            }
            __syncwarp();
        }
    }
    __syncthreads();

    float* ctab = &mag[0][0];
    for (int j = tid; j < 1024; j += 256)
        ctab[j] = (j < 512) ? tw[j].x : -tw[j - 512].x;
    __syncthreads();

    {
        int s = tid & 3;
        int ms[8]; float re[8], im[8];
#pragma unroll
        for (int k = 0; k < 8; k++) { ms[k] = chm[s][k]; re[k] = chre[s][k]; im[k] = chim[s][k]; }
        int d = d0 + s;
        float*       seas = out + OFF_SEASON + (size_t)b*TP*Dn + d;
        const float* rb   = x + (size_t)b*Tn*Dn + d;
        __half*      r1h  = RES1H + (size_t)b*Tn*Dn + d;
        for (int t = tid >> 2; t < TP; t += 64) {
            float acc = 0.f;
#pragma unroll
            for (int k = 0; k < 8; k++) {
                int idx = (ms[k]*t) & 1023;
                acc += re[k]*ctab[idx] - im[k]*ctab[(idx + 768) & 1023];
            }
            seas[(size_t)t*Dn] = acc;
            if (t < Tn)
                r1h[(size_t)t*Dn] = __float2half(rb[(size_t)t*Dn] - acc);
        }
    }
}

// ---------------- fp16 tensor-core GEMM, cp.async 4-stage, 1 barrier/iter ----------------
__device__ __forceinline__ void cp_async16(unsigned saddr, const void* gptr, bool valid) {
    int sz = valid ? 16 : 0;
    asm volatile("cp.async.cg.shared.global [%0], [%1], 16, %2;\n"
                 :: "r"(saddr), "l"(gptr), "r"(sz));
}

__global__ __launch_bounds__(256) void hgemm_kernel(const __half* __restrict__ A,
                                                    const __half* __restrict__ BT,
                                                    float* __restrict__ C,
                                                    __half* __restrict__ CH,
                                                    int M, int N, int K,
                                                    int dogelu, int outhalf) {
    extern __shared__ __half smh[];
    __half* Ash = smh;
    __half* Bsh = smh + STAGESH * STG_HALFS;
    unsigned As_base = (unsigned)__cvta_generic_to_shared(Ash);
    unsigned Bs_base = (unsigned)__cvta_generic_to_shared(Bsh);

    int tid = threadIdx.x;
    int row0 = blockIdx.y * 128, col0 = blockIdx.x * 128;
    int wid = tid >> 5, lane = tid & 31;
    int wm = (wid & 1) * 64, wn = (wid >> 1) * 32;
    int g = lane >> 2, tg = lane & 3;

    float acc[4][4][4];
#pragma unroll
    for (int i = 0; i < 4; i++)
#pragma unroll
        for (int j = 0; j < 4; j++)
#pragma unroll
            for (int q = 0; q < 4; q++) acc[i][j][q] = 0.f;

    const int NT = K / BKH;

    int ch0 = tid, ch1 = tid + 256;
    int ra0 = ch0 >> 2, ca0 = ch0 & 3;
    int ra1 = ch1 >> 2, ca1 = ch1 & 3;
    bool av0 = (row0 + ra0) < M, av1 = (row0 + ra1) < M;
    const __half* ag0 = A + (size_t)(row0 + ra0)*K + ca0*8;
    const __half* ag1 = A + (size_t)(row0 + ra1)*K + ca1*8;
    const __half* bg0 = BT + (size_t)(col0 + ra0)*K + ca0*8;
    const __half* bg1 = BT + (size_t)(col0 + ra1)*K + ca1*8;
    unsigned ad0 = (unsigned)(ra0*APADH + ca0*8)*2, ad1 = (unsigned)(ra1*APADH + ca1*8)*2;

#pragma unroll
    for (int s = 0; s < 3; s++) {
        unsigned ab = As_base + s*STG_HALFS*2, bb = Bs_base + s*STG_HALFS*2;
        int k0 = s * BKH;
        cp_async16(ab + ad0, ag0 + k0, av0);
        cp_async16(ab + ad1, ag1 + k0, av1);
        cp_async16(bb + ad0, bg0 + k0, true);
        cp_async16(bb + ad1, bg1 + k0, true);
        asm volatile("cp.async.commit_group;\n");
    }

    for (int it = 0; it < NT; it++) {
        int ahead = NT - 1 - it;
        if (ahead >= 2)      asm volatile("cp.async.wait_group 2;\n");
        else if (ahead == 1) asm volatile("cp.async.wait_group 1;\n");
        else                 asm volatile("cp.async.wait_group 0;\n");
        __syncthreads();

        if (it + 3 < NT) {
            int s = (it + 3) % STAGESH, k0 = (it + 3) * BKH;
            unsigned ab = As_base + s*STG_HALFS*2, bb = Bs_base + s*STG_HALFS*2;
            cp_async16(ab + ad0, ag0 + k0, av0);
            cp_async16(ab + ad1, ag1 + k0, av1);
            cp_async16(bb + ad0, bg0 + k0, true);
            cp_async16(bb + ad1, bg1 + k0, true);
            asm volatile("cp.async.commit_group;\n");
        }

        const __half* Abuf = Ash + (it % STAGESH) * STG_HALFS;
        const __half* Bbuf = Bsh + (it % STAGESH) * STG_HALFS;

#pragma unroll
        for (int kk = 0; kk < BKH; kk += 16) {
            unsigned af[4][4], bf[4][2];
#pragma unroll
            for (int mt = 0; mt < 4; mt++) {
                int m = wm + mt*16 + g;
                af[mt][0] = *(const unsigned*)(Abuf + (m  )*APADH + kk + 2*tg);
                af[mt][1] = *(const unsigned*)(Abuf + (m+8)*APADH + kk + 2*tg);
                af[mt][2] = *(const unsigned*)(Abuf + (m  )*APADH + kk + 2*tg + 8);
                af[mt][3] = *(const unsigned*)(Abuf + (m+8)*APADH + kk + 2*tg + 8);
            }
#pragma unroll
            for (int nt = 0; nt < 4; nt++) {
                int n = wn + nt*8 + g;
                bf[nt][0] = *(const unsigned*)(Bbuf + n*APADH + kk + 2*tg);
                bf[nt][1] = *(const unsigned*)(Bbuf + n*APADH + kk + 2*tg + 8);
            }
#pragma unroll
            for (int mt = 0; mt < 4; mt++)
#pragma unroll
                for (int nt = 0; nt < 4; nt++)
                    asm volatile(
                        "mma.sync.aligned.m16n8k16.row.col.f32.f16.f16.f32 "
                        "{%0,%1,%2,%3}, {%4,%5,%6,%7}, {%8,%9}, {%0,%1,%2,%3};"
                        : "+f"(acc[mt][nt][0]), "+f"(acc[mt][nt][1]),
                          "+f"(acc[mt][nt][2]), "+f"(acc[mt][nt][3])
                        : "r"(af[mt][0]), "r"(af[mt][1]), "r"(af[mt][2]), "r"(af[mt][3]),
                          "r"(bf[nt][0]), "r"(bf[nt][1]));
        }
    }

#pragma unroll
    for (int mt = 0; mt < 4; mt++) {
#pragma unroll
        for (int nt = 0; nt < 4; nt++) {
            int r0 = row0 + wm + mt*16 + g;
            int c  = col0 + wn + nt*8 + 2*tg;
            float v[4];
#pragma unroll
            for (int q = 0; q < 4; q++) {
                float u = acc[mt][nt][q];
                if (dogelu) u = 0.5f*u*(1.0f + erff(u*0.70710678118654752f));
                v[q] = u;
            }
            if (outhalf) {
                if (r0 < M)
                    *(__half2*)(CH + (size_t)r0*N + c) = __floats2half2_rn(v[0], v[1]);
                if (r0 + 8 < M)
                    *(__half2*)(CH + (size_t)(r0+8)*N + c) = __floats2half2_rn(v[2], v[3]);
            } else {
                if (r0 < M)     *(float2*)(C + (size_t)r0*N + c)     = make_float2(v[0], v[1]);
                if (r0 + 8 < M) *(float2*)(C + (size_t)(r0+8)*N + c) = make_float2(v[2], v[3]);
            }
        }
    }
}

// ---------------- growth EMA: fused blocked scan, 512 threads ----------------
__global__ __launch_bounds__(512) void growth_fused(const float* __restrict__ sw,
                                                    const float* __restrict__ z0,
                                                    const float* __restrict__ v0) {
    __shared__ float zb[GSEG][33];
    __shared__ float cb[GSEG][33];
    int b  = blockIdx.x >> 4;
    int c0 = (blockIdx.x & 15) << 5;
    int seg = threadIdx.x >> 5, ci = threadIdx.x & 31;
    int c = c0 + ci;
    float w = 1.f/(1.f + expf(-sw[c >> 6]));
    float omw = 1.f - w;
    int t0 = seg * GSEGLEN;
    const float* vp = VBUF + (size_t)b*Tn*Dn + c;

    float dv[GSEGLEN];
    float prev = (t0 == 0) ? z0[c] : vp[(size_t)(t0-1)*Dn];
    float z = 0.f;
#pragma unroll
    for (int l = 0; l < GSEGLEN; l++) {
        float v = vp[(size_t)(t0+l)*Dn];
        dv[l] = v - prev;
        prev = v;
        z = w*z + dv[l];
    }
    zb[seg][ci] = z;
    __syncthreads();

    if (threadIdx.x < 32) {
        int cc = threadIdx.x;
        float wj = 1.f/(1.f + expf(-sw[(c0 + cc) >> 6]));
        float w64 = 1.f;
        { float p = wj; int e = GSEGLEN; while (e) { if (e & 1) w64 *= p; p *= p; e >>= 1; } }
        float y = v0[c0 + cc];
        float omwj = 1.f - wj;
#pragma unroll
        for (int s = 0; s < GSEG; s++) {
            cb[s][cc] = y;
            y = w64*y + omwj*zb[s][cc];
        }
    }
    __syncthreads();

    __half* gp = GBUFH + (size_t)b*T1*Dn + c;
    float y = cb[seg][ci];
    if (seg == 0) gp[0] = __float2half(v0[c]);
#pragma unroll
    for (int l = 0; l < GSEGLEN; l++) {
        y = w*y + omw*dv[l];
        gp[(size_t)(t0+l+1)*Dn] = __float2half(y);
    }
}

// ---------------- layernorm helpers ----------------
__device__ __forceinline__ float block_reduce_sum(float v, float* red) {
    for (int o = 16; o; o >>= 1) v += __shfl_xor_sync(0xffffffffu, v, o);
    int wid = threadIdx.x >> 5;
    if ((threadIdx.x & 31) == 0) red[wid] = v;
    __syncthreads();
    if (threadIdx.x < 32) {
        float s = (threadIdx.x < 4) ? red[threadIdx.x] : 0.f;
        for (int o = 2; o; o >>= 1) s += __shfl_xor_sync(0xffffffffu, s, o);
        if (threadIdx.x == 0) red[0] = s;
    }
    __syncthreads();
    float r = red[0];
    __syncthreads();
    return r;
}

__global__ __launch_bounds__(128) void res2_kernel(const float* __restrict__ out_all,
                                                   const float* __restrict__ ng,
                                                   const float* __restrict__ nb) {
    __shared__ float red[32];
    int r = blockIdx.x;
    int b = r >> 10, t = r & 1023;
    const __half* x1 = RES1H + (size_t)r*Dn;
    const float*  gw = out_all + OFF_GROWTH + (size_t)(b*T1 + t + 1)*Dn;
    float vals[4]; float s = 0.f;
#pragma unroll
    for (int i = 0; i < 4; i++) {
        int d = threadIdx.x + i*128;
        vals[i] = __half2float(x1[d]) - gw[d];
        s += vals[i];
    }
    float mu = block_reduce_sum(s, red) * (1.0f/512.0f);
    float vs = 0.f;
#pragma unroll
    for (int i = 0; i < 4; i++) { float c = vals[i]-mu; vs += c*c; }
    float var = block_reduce_sum(vs, red) * (1.0f/512.0f);
    float inv = rsqrtf(var + 1e-5f);
#pragma unroll
    for (int i = 0; i < 4; i++) {
        int d = threadIdx.x + i*128;
        R2BH[(size_t)r*Dn + d] = __float2half((vals[i]-mu)*inv*ng[d] + nb[d]);
    }
}

__global__ __launch_bounds__(128) void res3_kernel(float* __restrict__ out_all,
                                                   const float* __restrict__ ng,
                                                   const float* __restrict__ nb) {
    __shared__ float red[32];
    int r = blockIdx.x;
    float vals[4]; float s = 0.f;
#pragma unroll
    for (int i = 0; i < 4; i++) {
        int d = threadIdx.x + i*128;
        vals[i] = __half2float(R2BH[(size_t)r*Dn + d]) +
                  __half2float(FOUTH[(size_t)r*Dn + d]);
        s += vals[i];
    }
    float mu = block_reduce_sum(s, red) * (1.0f/512.0f);
    float vs = 0.f;
#pragma unroll
    for (int i = 0; i < 4; i++) { float c = vals[i]-mu; vs += c*c; }
    float var = block_reduce_sum(vs, red) * (1.0f/512.0f);
    float inv = rsqrtf(var + 1e-5f);
#pragma unroll
    for (int i = 0; i < 4; i++) {
        int d = threadIdx.x + i*128;
        out_all[OFF_RES3 + (size_t)r*Dn + d] = (vals[i]-mu)*inv*ng[d] + nb[d];
    }
}

// ---------------- level projections ----------------
__global__ __launch_bounds__(256) void levelproj_kernel(const float* __restrict__ out_all,
                                                        const float* __restrict__ gpw,
                                                        const float* __restrict__ spw) {
    int warp = (blockIdx.x*256 + threadIdx.x) >> 5;
    int lane = threadIdx.x & 31;
    if (warp >= Bn*Tn) return;
    int b = warp >> 10, t = warp & 1023;
    const float* gr = out_all + OFF_GROWTH + (size_t)(b*T1 + t)*Dn;
    const float* se = out_all + OFF_SEASON + (size_t)(b*TP + t)*Dn;
    float ag[7] = {}, as_[7] = {};
    for (int d = lane; d < 512; d += 32) {
        float g = gr[d], s = se[d];
#pragma unroll
        for (int c = 0; c < 7; c++) { ag[c] += g*gpw[d*7+c]; as_[c] += s*spw[d*7+c]; }
    }
#pragma unroll
    for (int c = 0; c < 7; c++) {
        for (int o = 16; o; o >>= 1) {
            ag[c]  += __shfl_xor_sync(0xffffffffu, ag[c],  o);
            as_[c] += __shfl_xor_sync(0xffffffffu, as_[c], o);
        }
    }
    if (lane == 0) {
#pragma unroll
        for (int c = 0; c < 7; c++) {
            GS_G[(size_t)warp*7 + c] = ag[c];
            GS_S[(size_t)warp*7 + c] = as_[c];
        }
    }
}

// ---------------- level EMA: fully fused blocked scan ----------------
__global__ __launch_bounds__(256) void level_fused(const float* __restrict__ level,
                                                   const float* __restrict__ lsw,
                                                   const float* __restrict__ lv0,
                                                   float* __restrict__ out_all) {
    __shared__ float zb[GSEG][17];
    __shared__ float cb[GSEG][17];
    int seg = threadIdx.x >> 4, ci = threadIdx.x & 15;
    int ch = blockIdx.x * 16 + ci;
    int b = ch / COUTn, c = ch % COUTn;
    float w = 1.f/(1.f + expf(-lsw[c]));
    float omw = 1.f - w;
    int t0 = seg * GSEGLEN;
    const float* lp = level + (size_t)b*Tn*COUTn + c;
    const float* gp = GS_G  + (size_t)b*Tn*COUTn + c;
    const float* sp = GS_S  + (size_t)b*Tn*COUTn + c;

    float uv[GSEGLEN];
    float z = 0.f;
#pragma unroll
    for (int l = 0; l < GSEGLEN; l++) {
        int t = t0 + l;
        uv[l] = omw*(lp[t*COUTn] - sp[t*COUTn]) + w*gp[t*COUTn];
        z = w*z + uv[l];
    }
    zb[seg][ci] = z;
    __syncthreads();

    if (threadIdx.x < 16) {
        int cc = threadIdx.x;
        int ch2 = blockIdx.x * 16 + cc;
        float wj = 1.f/(1.f + expf(-lsw[ch2 % COUTn]));
        float w64 = 1.f;
        { float p = wj; int e = GSEGLEN; while (e) { if (e & 1) w64 *= p; p *= p; e >>= 1; } }
        float y = lv0[ch2 % COUTn];
#pragma unroll
        for (int s = 0; s < GSEG; s++) {
            cb[s][cc] = y;
            y = w64*y + zb[s][cc];
        }
    }
    __syncthreads();

    float* op = out_all + OFF_LEVEL + (size_t)b*Tn*COUTn + c;
    float y = cb[seg][ci];
#pragma unroll
    for (int l = 0; l < GSEGLEN; l++) {
        y = w*y + uv[l];
        op[(t0+l)*COUTn] = y;
    }
}

// ---------------- launch ----------------
extern "C" void kernel_launch(void* const* d_in, const int* in_sizes, int n_in,
                              void* d_out, int out_size) {
    const float* res      = (const float*)d_in[0];
    const float* level    = (const float*)d_in[1];
    const float* in_w     = (const float*)d_in[2];
    const float* out_w    = (const float*)d_in[3];
    const float* z0       = (const float*)d_in[4];
    const float* gsw      = (const float*)d_in[5];
    const float* gv0      = (const float*)d_in[6];
    const float* ff_w1    = (const float*)d_in[7];
    const float* ff_w2    = (const float*)d_in[8];
    const float* n1g      = (const float*)d_in[9];
    const float* n1b      = (const float*)d_in[10];
    const float* n2g      = (const float*)d_in[11];
    const float* n2b      = (const float*)d_in[12];
    const float* gpw      = (const float*)d_in[13];
    const float* spw      = (const float*)d_in[14];
    const float* lsw      = (const float*)d_in[15];
    const float* lv0      = (const float*)d_in[16];
    float* out = (float*)d_out;

    float *pVBUF;
    __half *pRES1H, *pGBUFH, *pR2H, *pFBUFH, *pFOUTH, *pWTIN, *pWTOUT, *pWT1, *pWT2;
    cudaGetSymbolAddress((void**)&pVBUF,  VBUF);
    cudaGetSymbolAddress((void**)&pRES1H, RES1H);
    cudaGetSymbolAddress((void**)&pGBUFH, GBUFH);
    cudaGetSymbolAddress((void**)&pR2H,   R2BH);
    cudaGetSymbolAddress((void**)&pFBUFH, FBUFH);
    cudaGetSymbolAddress((void**)&pFOUTH, FOUTH);
    cudaGetSymbolAddress((void**)&pWTIN,  WT_IN);
    cudaGetSymbolAddress((void**)&pWTOUT, WT_OUT);
    cudaGetSymbolAddress((void**)&pWT1,   WT_1);
    cudaGetSymbolAddress((void**)&pWT2,   WT_2);

    static int init_done = 0;
    static cudaStream_t s2;
    static cudaEvent_t evA, evB, evC, evD;
    if (!init_done) {
        cudaFuncSetAttribute(hgemm_kernel,
                             cudaFuncAttributeMaxDynamicSharedMemorySize, HS_TOTAL);
        cudaStreamCreateWithFlags(&s2, cudaStreamNonBlocking);
        cudaEventCreateWithFlags(&evA, cudaEventDisableTiming);
        cudaEventCreateWithFlags(&evB, cudaEventDisableTiming);
        cudaEventCreateWithFlags(&evC, cudaEventDisableTiming);
        cudaEventCreateWithFlags(&evD, cudaEventDisableTiming);
        init_done = 1;
    }

    // fork: transpose4 on s2, concurrent with fftseason on main stream
    cudaEventRecord(evA, 0);
    cudaStreamWaitEvent(s2, evA, 0);
    transpose4<<<2560, 256, 0, s2>>>(in_w, pWTIN, out_w, pWTOUT, ff_w1, pWT1, ff_w2, pWT2);
    cudaEventRecord(evB, s2);

    fftseason_kernel<<<Bn*(Dn/4), 256>>>(res, out);

    cudaStreamWaitEvent(0, evB, 0);

    // GEMM1: v = res1 @ in_proj_w
    hgemm_kernel<<<dim3(Dn/128, (Bn*Tn)/128), 256, HS_TOTAL>>>(pRES1H, pWTIN,
                                                               pVBUF, 0,
                                                               Bn*Tn, Dn, Dn, 0, 0);
    growth_fused<<<Bn*16, 512>>>(gsw, z0, gv0);
    // GEMM2: growth -> d_out
    hgemm_kernel<<<dim3(Dn/128, (Bn*T1 + 127)/128), 256, HS_TOTAL>>>(pGBUFH, pWTOUT,
                                                                     out + OFF_GROWTH, 0,
                                                                     Bn*T1, Dn, Dn, 0, 0);

    // fork: level path on s2
    cudaEventRecord(evC, 0);
    cudaStreamWaitEvent(s2, evC, 0);
    levelproj_kernel<<<(Bn*Tn*32)/256, 256, 0, s2>>>(out, gpw, spw);
    level_fused<<<7, 256, 0, s2>>>(level, lsw, lv0, out);
    cudaEventRecord(evD, s2);

    // main chain
    res2_kernel<<<Bn*Tn, 128>>>(out, n1g, n1b);
    hgemm_kernel<<<dim3(LATENTn/128, (Bn*Tn)/128), 256, HS_TOTAL>>>(pR2H, pWT1,
                                                                    0, pFBUFH,
                                                                    Bn*Tn, LATENTn, Dn, 1, 1);
    hgemm_kernel<<<dim3(Dn/128, (Bn*Tn)/128), 256, HS_TOTAL>>>(pFBUFH, pWT2,
                                                               0, pFOUTH,
                                                               Bn*Tn, Dn, LATENTn, 0, 1);
    res3_kernel<<<Bn*Tn, 128>>>(out, n2g, n2b);

    cudaStreamWaitEvent(0, evD, 0);
}

// round 14
// speedup vs baseline: 2.3200x; 1.0030x over previous
#include <cuda_runtime.h>
#include <cuda_fp16.h>
#include <math.h>
#include <stdint.h>

#define Bn 16
#define Tn 1024
#define Dn 512
#define COUTn 7
#define PREDn 96
#define Kn 8
#define LATENTn 2048
#define TP (Tn + PREDn)
#define T1 (Tn + 1)

#define OFF_RES3   0
#define OFF_LEVEL  (Bn*Tn*Dn)
#define OFF_GROWTH (OFF_LEVEL + Bn*Tn*COUTn)
#define OFF_SEASON (OFF_GROWTH + Bn*T1*Dn)

#define GSEG 16
#define GSEGLEN 64

// fp16 GEMM tiling: 4 stages, single barrier per K-iter
#define STAGESH 4
#define BKH 32
#define APADH 40
#define STG_HALFS (128*APADH)
#define HS_TOTAL (STAGESH*2*STG_HALFS*2)   /* 81920 B */

// ---------------- scratch ----------------
__device__ __align__(256) __half RES1H[Bn*Tn*Dn];
__device__ __align__(256) __half VBUFH[Bn*Tn*Dn];
__device__ __align__(256) __half GBUFH[Bn*T1*Dn];
__device__ __align__(256) __half R2BH[Bn*Tn*Dn];
__device__ __align__(256) __half FBUFH[Bn*Tn*LATENTn];
__device__ __align__(256) __half FOUTH[Bn*Tn*Dn];
__device__ __align__(256) __half WT_IN [Dn*Dn];
__device__ __align__(256) __half WT_OUT[Dn*Dn];
__device__ __align__(256) __half WT_1  [LATENTn*Dn];
__device__ __align__(256) __half WT_2  [Dn*LATENTn];
__device__ float GS_G[Bn*Tn*COUTn];
__device__ float GS_S[Bn*Tn*COUTn];

// ---------------- fused transpose of all 4 weight matrices ----------------
__global__ __launch_bounds__(256) void transpose4(const float* __restrict__ s0, __half* __restrict__ d0p,
                                                  const float* __restrict__ s1, __half* __restrict__ d1p,
                                                  const float* __restrict__ s2, __half* __restrict__ d2p,
                                                  const float* __restrict__ s3, __half* __restrict__ d3p) {
    __shared__ float t[32][33];
    int id = blockIdx.x;
    const float* src; __half* dst; int R, C, bx, by;
    if (id < 256)       { src = s0; dst = d0p; R = Dn;      C = Dn;      bx = id & 15;        by = id >> 4; }
    else if (id < 512)  { id -= 256;  src = s1; dst = d1p; R = Dn;      C = Dn;      bx = id & 15; by = id >> 4; }
    else if (id < 1536) { id -= 512;  src = s2; dst = d2p; R = Dn;      C = LATENTn; bx = id & 63; by = id >> 6; }
    else                { id -= 1536; src = s3; dst = d3p; R = LATENTn; C = Dn;      bx = id & 15; by = id >> 4; }
    int tx = threadIdx.x & 31, ty = threadIdx.x >> 5;
    int c0 = bx*32, r0 = by*32;
#pragma unroll
    for (int i = 0; i < 4; i++)
        t[ty + i*8][tx] = src[(size_t)(r0 + ty + i*8)*C + c0 + tx];
    __syncthreads();
#pragma unroll
    for (int i = 0; i < 4; i++)
        dst[(size_t)(c0 + ty + i*8)*R + r0 + tx] = __float2half(t[tx][ty + i*8]);
}

// ---------------- fused FFT + top-8 + season + res1(half) ----------------
__global__ __launch_bounds__(256) void fftseason_kernel(const float* __restrict__ x,
                                                        float* __restrict__ out) {
    __shared__ float2 data[4][1024];
    __shared__ float2 tw[512];
    __shared__ float  mag[4][512];
    __shared__ int    chm[4][8];
    __shared__ float  chre[4][8], chim[4][8];

    int tid = threadIdx.x;
    int b   = blockIdx.x >> 7;
    int d0  = (blockIdx.x & 127) << 2;

    for (int k = tid; k < 512; k += 256) {
        float s, c;
        sincosf(-6.283185307179586f * (float)k / 1024.0f, &s, &c);
        tw[k] = make_float2(c, s);
    }
    const float* xb = x + (size_t)b * Tn * Dn;
    for (int i = tid; i < 4096; i += 256) {
        int t = i >> 2, j = i & 3;
        data[j][t] = make_float2(xb[(size_t)t*Dn + d0 + j], 0.f);
    }
    __syncthreads();

    int tmul = 1;
    for (int half = 512; half >= 1; half >>= 1, tmul <<= 1) {
        for (int i = tid; i < 2048; i += 256) {
            int s  = i >> 9;
            int bf = i & 511;
            int k  = bf & (half - 1);
            int pos = 2*bf - k;
            float2 u = data[s][pos], v = data[s][pos + half];
            data[s][pos] = make_float2(u.x + v.x, u.y + v.y);
            float2 t2 = make_float2(u.x - v.x, u.y - v.y);
            float2 w  = tw[k * tmul];
            data[s][pos + half] = make_float2(t2.x*w.x - t2.y*w.y,
                                              t2.x*w.y + t2.y*w.x);
        }
        __syncthreads();
    }

    for (int i = tid; i < 2048; i += 256) {
        int s = i >> 9, f = i & 511;
        if (f == 0) { mag[s][0] = -1e30f; continue; }
        int j = (int)(__brev((unsigned)f) >> 22);
        float2 v = data[s][j];
        mag[s][f] = v.x*v.x + v.y*v.y;
    }
    __syncthreads();

    int wid = tid >> 5, lane = tid & 31;
    if (wid < 4) {
        int s = wid;
#pragma unroll
        for (int it = 0; it < 8; it++) {
            float bestm = -1e29f; int bestf = 1 << 20;
            for (int f = lane; f < 512; f += 32) {
                float m2 = mag[s][f];
                if (m2 > bestm || (m2 == bestm && f < bestf)) { bestm = m2; bestf = f; }
            }
            for (int off = 16; off; off >>= 1) {
                float om = __shfl_xor_sync(0xffffffffu, bestm, off);
                int   of = __shfl_xor_sync(0xffffffffu, bestf, off);
                if (om > bestm || (om == bestm && of < bestf)) { bestm = om; bestf = of; }
            }
            if (lane == 0) {
                int j = (int)(__brev((unsigned)bestf) >> 22);
                float2 v = data[s][j];
                chm [s][it] = bestf;
                chre[s][it] = v.x * (2.0f / (float)Tn);
                chim[s][it] = v.y * (2.0f / (float)Tn);
                mag[s][bestf] = -1e30f;
            }
            __syncwarp();
        }
    }
    __syncthreads();

    float* ctab = &mag[0][0];
    for (int j = tid; j < 1024; j += 256)
        ctab[j] = (j < 512) ? tw[j].x : -tw[j - 512].x;
    __syncthreads();

    {
        int s = tid & 3;
        int ms[8]; float re[8], im[8];
#pragma unroll
        for (int k = 0; k < 8; k++) { ms[k] = chm[s][k]; re[k] = chre[s][k]; im[k] = chim[s][k]; }
        int d = d0 + s;
        float*       seas = out + OFF_SEASON + (size_t)b*TP*Dn + d;
        const float* rb   = x + (size_t)b*Tn*Dn + d;
        __half*      r1h  = RES1H + (size_t)b*Tn*Dn + d;
        for (int t = tid >> 2; t < TP; t += 64) {
            float acc = 0.f;
#pragma unroll
            for (int k = 0; k < 8; k++) {
                int idx = (ms[k]*t) & 1023;
                acc += re[k]*ctab[idx] - im[k]*ctab[(idx + 768) & 1023];
            }
            seas[(size_t)t*Dn] = acc;
            if (t < Tn)
                r1h[(size_t)t*Dn] = __float2half(rb[(size_t)t*Dn] - acc);
        }
    }
}

// ---------------- fp16 tensor-core GEMM, cp.async 4-stage, 1 barrier/iter ----------------
__device__ __forceinline__ void cp_async16(unsigned saddr, const void* gptr, bool valid) {
    int sz = valid ? 16 : 0;
    asm volatile("cp.async.cg.shared.global [%0], [%1], 16, %2;\n"
                 :: "r"(saddr), "l"(gptr), "r"(sz));
}

__global__ __launch_bounds__(256) void hgemm_kernel(const __half* __restrict__ A,
                                                    const __half* __restrict__ BT,
                                                    float* __restrict__ C,
                                                    __half* __restrict__ CH,
                                                    int M, int N, int K,
                                                    int dogelu, int outhalf) {
    extern __shared__ __half smh[];
    __half* Ash = smh;
    __half* Bsh = smh + STAGESH * STG_HALFS;
    unsigned As_base = (unsigned)__cvta_generic_to_shared(Ash);
    unsigned Bs_base = (unsigned)__cvta_generic_to_shared(Bsh);

    int tid = threadIdx.x;
    int row0 = blockIdx.y * 128, col0 = blockIdx.x * 128;
    int wid = tid >> 5, lane = tid & 31;
    int wm = (wid & 1) * 64, wn = (wid >> 1) * 32;
    int g = lane >> 2, tg = lane & 3;

    float acc[4][4][4];
#pragma unroll
    for (int i = 0; i < 4; i++)
#pragma unroll
        for (int j = 0; j < 4; j++)
#pragma unroll
            for (int q = 0; q < 4; q++) acc[i][j][q] = 0.f;

    const int NT = K / BKH;

    int ch0 = tid, ch1 = tid + 256;
    int ra0 = ch0 >> 2, ca0 = ch0 & 3;
    int ra1 = ch1 >> 2, ca1 = ch1 & 3;
    bool av0 = (row0 + ra0) < M, av1 = (row0 + ra1) < M;
    const __half* ag0 = A + (size_t)(row0 + ra0)*K + ca0*8;
    const __half* ag1 = A + (size_t)(row0 + ra1)*K + ca1*8;
    const __half* bg0 = BT + (size_t)(col0 + ra0)*K + ca0*8;
    const __half* bg1 = BT + (size_t)(col0 + ra1)*K + ca1*8;
    unsigned ad0 = (unsigned)(ra0*APADH + ca0*8)*2, ad1 = (unsigned)(ra1*APADH + ca1*8)*2;

#pragma unroll
    for (int s = 0; s < 3; s++) {
        unsigned ab = As_base + s*STG_HALFS*2, bb = Bs_base + s*STG_HALFS*2;
        int k0 = s * BKH;
        cp_async16(ab + ad0, ag0 + k0, av0);
        cp_async16(ab + ad1, ag1 + k0, av1);
        cp_async16(bb + ad0, bg0 + k0, true);
        cp_async16(bb + ad1, bg1 + k0, true);
        asm volatile("cp.async.commit_group;\n");
    }

    for (int it = 0; it < NT; it++) {
        int ahead = NT - 1 - it;
        if (ahead >= 2)      asm volatile("cp.async.wait_group 2;\n");
        else if (ahead == 1) asm volatile("cp.async.wait_group 1;\n");
        else                 asm volatile("cp.async.wait_group 0;\n");
        __syncthreads();

        if (it + 3 < NT) {
            int s = (it + 3) % STAGESH, k0 = (it + 3) * BKH;
            unsigned ab = As_base + s*STG_HALFS*2, bb = Bs_base + s*STG_HALFS*2;
            cp_async16(ab + ad0, ag0 + k0, av0);
            cp_async16(ab + ad1, ag1 + k0, av1);
            cp_async16(bb + ad0, bg0 + k0, true);
            cp_async16(bb + ad1, bg1 + k0, true);
            asm volatile("cp.async.commit_group;\n");
        }

        const __half* Abuf = Ash + (it % STAGESH) * STG_HALFS;
        const __half* Bbuf = Bsh + (it % STAGESH) * STG_HALFS;

#pragma unroll
        for (int kk = 0; kk < BKH; kk += 16) {
            unsigned af[4][4], bf[4][2];
#pragma unroll
            for (int mt = 0; mt < 4; mt++) {
                int m = wm + mt*16 + g;
                af[mt][0] = *(const unsigned*)(Abuf + (m  )*APADH + kk + 2*tg);
                af[mt][1] = *(const unsigned*)(Abuf + (m+8)*APADH + kk + 2*tg);
                af[mt][2] = *(const unsigned*)(Abuf + (m  )*APADH + kk + 2*tg + 8);
                af[mt][3] = *(const unsigned*)(Abuf + (m+8)*APADH + kk + 2*tg + 8);
            }
#pragma unroll
            for (int nt = 0; nt < 4; nt++) {
                int n = wn + nt*8 + g;
                bf[nt][0] = *(const unsigned*)(Bbuf + n*APADH + kk + 2*tg);
                bf[nt][1] = *(const unsigned*)(Bbuf + n*APADH + kk + 2*tg + 8);
            }
#pragma unroll
            for (int mt = 0; mt < 4; mt++)
#pragma unroll
                for (int nt = 0; nt < 4; nt++)
                    asm volatile(
                        "mma.sync.aligned.m16n8k16.row.col.f32.f16.f16.f32 "
                        "{%0,%1,%2,%3}, {%4,%5,%6,%7}, {%8,%9}, {%0,%1,%2,%3};"
                        : "+f"(acc[mt][nt][0]), "+f"(acc[mt][nt][1]),
                          "+f"(acc[mt][nt][2]), "+f"(acc[mt][nt][3])
                        : "r"(af[mt][0]), "r"(af[mt][1]), "r"(af[mt][2]), "r"(af[mt][3]),
                          "r"(bf[nt][0]), "r"(bf[nt][1]));
        }
    }

#pragma unroll
    for (int mt = 0; mt < 4; mt++) {
#pragma unroll
        for (int nt = 0; nt < 4; nt++) {
            int r0 = row0 + wm + mt*16 + g;
            int c  = col0 + wn + nt*8 + 2*tg;
            float v[4];
#pragma unroll
            for (int q = 0; q < 4; q++) {
                float u = acc[mt][nt][q];
                if (dogelu) u = 0.5f*u*(1.0f + erff(u*0.70710678118654752f));
                v[q] = u;
            }
            if (outhalf) {
                if (r0 < M)
                    *(__half2*)(CH + (size_t)r0*N + c) = __floats2half2_rn(v[0], v[1]);
                if (r0 + 8 < M)
                    *(__half2*)(CH + (size_t)(r0+8)*N + c) = __floats2half2_rn(v[2], v[3]);
            } else {
                if (r0 < M)     *(float2*)(C + (size_t)r0*N + c)     = make_float2(v[0], v[1]);
                if (r0 + 8 < M) *(float2*)(C + (size_t)(r0+8)*N + c) = make_float2(v[2], v[3]);
            }
        }
    }
}

// ---------------- growth EMA: fused blocked scan, half input ----------------
__global__ __launch_bounds__(512) void growth_fused(const float* __restrict__ sw,
                                                    const float* __restrict__ z0,
                                                    const float* __restrict__ v0) {
    __shared__ float zb[GSEG][33];
    __shared__ float cb[GSEG][33];
    int b  = blockIdx.x >> 4;
    int c0 = (blockIdx.x & 15) << 5;
    int seg = threadIdx.x >> 5, ci = threadIdx.x & 31;
    int c = c0 + ci;
    float w = 1.f/(1.f + expf(-sw[c >> 6]));
    float omw = 1.f - w;
    int t0 = seg * GSEGLEN;
    const __half* vp = VBUFH + (size_t)b*Tn*Dn + c;

    float dv[GSEGLEN];
    float prev = (t0 == 0) ? z0[c] : __half2float(vp[(size_t)(t0-1)*Dn]);
    float z = 0.f;
#pragma unroll
    for (int l = 0; l < GSEGLEN; l++) {
        float v = __half2float(vp[(size_t)(t0+l)*Dn]);
        dv[l] = v - prev;
        prev = v;
        z = w*z + dv[l];
    }
    zb[seg][ci] = z;
    __syncthreads();

    if (threadIdx.x < 32) {
        int cc = threadIdx.x;
        float wj = 1.f/(1.f + expf(-sw[(c0 + cc) >> 6]));
        float w64 = 1.f;
        { float p = wj; int e = GSEGLEN; while (e) { if (e & 1) w64 *= p; p *= p; e >>= 1; } }
        float y = v0[c0 + cc];
        float omwj = 1.f - wj;
#pragma unroll
        for (int s = 0; s < GSEG; s++) {
            cb[s][cc] = y;
            y = w64*y + omwj*zb[s][cc];
        }
    }
    __syncthreads();

    __half* gp = GBUFH + (size_t)b*T1*Dn + c;
    float y = cb[seg][ci];
    if (seg == 0) gp[0] = __float2half(v0[c]);
#pragma unroll
    for (int l = 0; l < GSEGLEN; l++) {
        y = w*y + omw*dv[l];
        gp[(size_t)(t0+l+1)*Dn] = __float2half(y);
    }
}

// ---------------- layernorm helpers ----------------
__device__ __forceinline__ float block_reduce_sum(float v, float* red) {
    for (int o = 16; o; o >>= 1) v += __shfl_xor_sync(0xffffffffu, v, o);
    int wid = threadIdx.x >> 5;
    if ((threadIdx.x & 31) == 0) red[wid] = v;
    __syncthreads();
    if (threadIdx.x < 32) {
        float s = (threadIdx.x < 4) ? red[threadIdx.x] : 0.f;
        for (int o = 2; o; o >>= 1) s += __shfl_xor_sync(0xffffffffu, s, o);
        if (threadIdx.x == 0) red[0] = s;
    }
    __syncthreads();
    float r = red[0];
    __syncthreads();
    return r;
}

__global__ __launch_bounds__(128) void res2_kernel(const float* __restrict__ out_all,
                                                   const float* __restrict__ ng,
                                                   const float* __restrict__ nb) {
    __shared__ float red[32];
    int r = blockIdx.x;
    int b = r >> 10, t = r & 1023;
    const __half* x1 = RES1H + (size_t)r*Dn;
    const float*  gw = out_all + OFF_GROWTH + (size_t)(b*T1 + t + 1)*Dn;
    float vals[4]; float s = 0.f;
#pragma unroll
    for (int i = 0; i < 4; i++) {
        int d = threadIdx.x + i*128;
        vals[i] = __half2float(x1[d]) - gw[d];
        s += vals[i];
    }
    float mu = block_reduce_sum(s, red) * (1.0f/512.0f);
    float vs = 0.f;
#pragma unroll
    for (int i = 0; i < 4; i++) { float c = vals[i]-mu; vs += c*c; }
    float var = block_reduce_sum(vs, red) * (1.0f/512.0f);
    float inv = rsqrtf(var + 1e-5f);
#pragma unroll
    for (int i = 0; i < 4; i++) {
        int d = threadIdx.x + i*128;
        R2BH[(size_t)r*Dn + d] = __float2half((vals[i]-mu)*inv*ng[d] + nb[d]);
    }
}

__global__ __launch_bounds__(128) void res3_kernel(float* __restrict__ out_all,
                                                   const float* __restrict__ ng,
                                                   const float* __restrict__ nb) {
    __shared__ float red[32];
    int r = blockIdx.x;
    float vals[4]; float s = 0.f;
#pragma unroll
    for (int i = 0; i < 4; i++) {
        int d = threadIdx.x + i*128;
        vals[i] = __half2float(R2BH[(size_t)r*Dn + d]) +
                  __half2float(FOUTH[(size_t)r*Dn + d]);
        s += vals[i];
    }
    float mu = block_reduce_sum(s, red) * (1.0f/512.0f);
    float vs = 0.f;
#pragma unroll
    for (int i = 0; i < 4; i++) { float c = vals[i]-mu; vs += c*c; }
    float var = block_reduce_sum(vs, red) * (1.0f/512.0f);
    float inv = rsqrtf(var + 1e-5f);
#pragma unroll
    for (int i = 0; i < 4; i++) {
        int d = threadIdx.x + i*128;
        out_all[OFF_RES3 + (size_t)r*Dn + d] = (vals[i]-mu)*inv*ng[d] + nb[d];
    }
}

// ---------------- level projections ----------------
__global__ __launch_bounds__(256) void levelproj_kernel(const float* __restrict__ out_all,
                                                        const float* __restrict__ gpw,
                                                        const float* __restrict__ spw) {
    int warp = (blockIdx.x*256 + threadIdx.x) >> 5;
    int lane = threadIdx.x & 31;
    if (warp >= Bn*Tn) return;
    int b = warp >> 10, t = warp & 1023;
    const float* gr = out_all + OFF_GROWTH + (size_t)(b*T1 + t)*Dn;
    const float* se = out_all + OFF_SEASON + (size_t)(b*TP + t)*Dn;
    float ag[7] = {}, as_[7] = {};
    for (int d = lane; d < 512; d += 32) {
        float g = gr[d], s = se[d];
#pragma unroll
        for (int c = 0; c < 7; c++) { ag[c] += g*gpw[d*7+c]; as_[c] += s*spw[d*7+c]; }
    }
#pragma unroll
    for (int c = 0; c < 7; c++) {
        for (int o = 16; o; o >>= 1) {
            ag[c]  += __shfl_xor_sync(0xffffffffu, ag[c],  o);
            as_[c] += __shfl_xor_sync(0xffffffffu, as_[c], o);
        }
    }
    if (lane == 0) {
#pragma unroll
        for (int c = 0; c < 7; c++) {
            GS_G[(size_t)warp*7 + c] = ag[c];
            GS_S[(size_t)warp*7 + c] = as_[c];
        }
    }
}

// ---------------- level EMA: fully fused blocked scan ----------------
__global__ __launch_bounds__(256) void level_fused(const float* __restrict__ level,
                                                   const float* __restrict__ lsw,
                                                   const float* __restrict__ lv0,
                                                   float* __restrict__ out_all) {
    __shared__ float zb[GSEG][17];
    __shared__ float cb[GSEG][17];
    int seg = threadIdx.x >> 4, ci = threadIdx.x & 15;
    int ch = blockIdx.x * 16 + ci;
    int b = ch / COUTn, c = ch % COUTn;
    float w = 1.f/(1.f + expf(-lsw[c]));
    float omw = 1.f - w;
    int t0 = seg * GSEGLEN;
    const float* lp = level + (size_t)b*Tn*COUTn + c;
    const float* gp = GS_G  + (size_t)b*Tn*COUTn + c;
    const float* sp = GS_S  + (size_t)b*Tn*COUTn + c;

    float uv[GSEGLEN];
    float z = 0.f;
#pragma unroll
    for (int l = 0; l < GSEGLEN; l++) {
        int t = t0 + l;
        uv[l] = omw*(lp[t*COUTn] - sp[t*COUTn]) + w*gp[t*COUTn];
        z = w*z + uv[l];
    }
    zb[seg][ci] = z;
    __syncthreads();

    if (threadIdx.x < 16) {
        int cc = threadIdx.x;
        int ch2 = blockIdx.x * 16 + cc;
        float wj = 1.f/(1.f + expf(-lsw[ch2 % COUTn]));
        float w64 = 1.f;
        { float p = wj; int e = GSEGLEN; while (e) { if (e & 1) w64 *= p; p *= p; e >>= 1; } }
        float y = lv0[ch2 % COUTn];
#pragma unroll
        for (int s = 0; s < GSEG; s++) {
            cb[s][cc] = y;
            y = w64*y + zb[s][cc];
        }
    }
    __syncthreads();

    float* op = out_all + OFF_LEVEL + (size_t)b*Tn*COUTn + c;
    float y = cb[seg][ci];
#pragma unroll
    for (int l = 0; l < GSEGLEN; l++) {
        y = w*y + uv[l];
        op[(t0+l)*COUTn] = y;
    }
}

// ---------------- launch ----------------
extern "C" void kernel_launch(void* const* d_in, const int* in_sizes, int n_in,
                              void* d_out, int out_size) {
    const float* res      = (const float*)d_in[0];
    const float* level    = (const float*)d_in[1];
    const float* in_w     = (const float*)d_in[2];
    const float* out_w    = (const float*)d_in[3];
    const float* z0       = (const float*)d_in[4];
    const float* gsw      = (const float*)d_in[5];
    const float* gv0      = (const float*)d_in[6];
    const float* ff_w1    = (const float*)d_in[7];
    const float* ff_w2    = (const float*)d_in[8];
    const float* n1g      = (const float*)d_in[9];
    const float* n1b      = (const float*)d_in[10];
    const float* n2g      = (const float*)d_in[11];
    const float* n2b      = (const float*)d_in[12];
    const float* gpw      = (const float*)d_in[13];
    const float* spw      = (const float*)d_in[14];
    const float* lsw      = (const float*)d_in[15];
    const float* lv0      = (const float*)d_in[16];
    float* out = (float*)d_out;

    __half *pRES1H, *pVBUFH, *pGBUFH, *pR2H, *pFBUFH, *pFOUTH, *pWTIN, *pWTOUT, *pWT1, *pWT2;
    cudaGetSymbolAddress((void**)&pRES1H, RES1H);
    cudaGetSymbolAddress((void**)&pVBUFH, VBUFH);
    cudaGetSymbolAddress((void**)&pGBUFH, GBUFH);
    cudaGetSymbolAddress((void**)&pR2H,   R2BH);
    cudaGetSymbolAddress((void**)&pFBUFH, FBUFH);
    cudaGetSymbolAddress((void**)&pFOUTH, FOUTH);
    cudaGetSymbolAddress((void**)&pWTIN,  WT_IN);
    cudaGetSymbolAddress((void**)&pWTOUT, WT_OUT);
    cudaGetSymbolAddress((void**)&pWT1,   WT_1);
    cudaGetSymbolAddress((void**)&pWT2,   WT_2);

    static int init_done = 0;
    static cudaStream_t s2;
    static cudaEvent_t evA, evB, evC, evD;
    if (!init_done) {
        cudaFuncSetAttribute(hgemm_kernel,
                             cudaFuncAttributeMaxDynamicSharedMemorySize, HS_TOTAL);
        cudaStreamCreateWithFlags(&s2, cudaStreamNonBlocking);
        cudaEventCreateWithFlags(&evA, cudaEventDisableTiming);
        cudaEventCreateWithFlags(&evB, cudaEventDisableTiming);
        cudaEventCreateWithFlags(&evC, cudaEventDisableTiming);
        cudaEventCreateWithFlags(&evD, cudaEventDisableTiming);
        init_done = 1;
    }

    // fork: transpose4 on s2, concurrent with fftseason on main stream
    cudaEventRecord(evA, 0);
    cudaStreamWaitEvent(s2, evA, 0);
    transpose4<<<2560, 256, 0, s2>>>(in_w, pWTIN, out_w, pWTOUT, ff_w1, pWT1, ff_w2, pWT2);
    cudaEventRecord(evB, s2);

    fftseason_kernel<<<Bn*(Dn/4), 256>>>(res, out);

    cudaStreamWaitEvent(0, evB, 0);

    // GEMM1: v = res1 @ in_proj_w -> half
    hgemm_kernel<<<dim3(Dn/128, (Bn*Tn)/128), 256, HS_TOTAL>>>(pRES1H, pWTIN,
                                                               0, pVBUFH,
                                                               Bn*Tn, Dn, Dn, 0, 1);
    growth_fused<<<Bn*16, 512>>>(gsw, z0, gv0);
    // GEMM2: growth -> d_out
    hgemm_kernel<<<dim3(Dn/128, (Bn*T1 + 127)/128), 256, HS_TOTAL>>>(pGBUFH, pWTOUT,
                                                                     out + OFF_GROWTH, 0,
                                                                     Bn*T1, Dn, Dn, 0, 0);

    // fork: level path on s2
    cudaEventRecord(evC, 0);
    cudaStreamWaitEvent(s2, evC, 0);
    levelproj_kernel<<<(Bn*Tn*32)/256, 256, 0, s2>>>(out, gpw, spw);
    level_fused<<<7, 256, 0, s2>>>(level, lsw, lv0, out);
    cudaEventRecord(evD, s2);

    // main chain
    res2_kernel<<<Bn*Tn, 128>>>(out, n1g, n1b);
    hgemm_kernel<<<dim3(LATENTn/128, (Bn*Tn)/128), 256, HS_TOTAL>>>(pR2H, pWT1,
                                                                    0, pFBUFH,
                                                                    Bn*Tn, LATENTn, Dn, 1, 1);
    hgemm_kernel<<<dim3(Dn/128, (Bn*Tn)/128), 256, HS_TOTAL>>>(pFBUFH, pWT2,
                                                               0, pFOUTH,
                                                               Bn*Tn, Dn, LATENTn, 0, 1);
    res3_kernel<<<Bn*Tn, 128>>>(out, n2g, n2b);

    cudaStreamWaitEvent(0, evD, 0);
}

// round 15
// speedup vs baseline: 2.4769x; 1.0676x over previous
#include <cuda_runtime.h>
#include <cuda_fp16.h>
#include <math.h>
#include <stdint.h>

#define Bn 16
#define Tn 1024
#define Dn 512
#define COUTn 7
#define PREDn 96
#define Kn 8
#define LATENTn 2048
#define TP (Tn + PREDn)
#define T1 (Tn + 1)

#define OFF_RES3   0
#define OFF_LEVEL  (Bn*Tn*Dn)
#define OFF_GROWTH (OFF_LEVEL + Bn*Tn*COUTn)
#define OFF_SEASON (OFF_GROWTH + Bn*T1*Dn)

#define GSEG 16
#define GSEGLEN 64
#define NBH 8                     /* batches per half */

// fp16 GEMM tiling: 4 stages, single barrier per K-iter
#define STAGESH 4
#define BKH 32
#define APADH 40
#define STG_HALFS (128*APADH)
#define HS_TOTAL (STAGESH*2*STG_HALFS*2)   /* 81920 B */

// ---------------- scratch ----------------
__device__ __align__(256) __half RES1H[Bn*Tn*Dn];
__device__ __align__(256) __half VBUFH[Bn*Tn*Dn];
__device__ __align__(256) __half GBUFH[Bn*T1*Dn];
__device__ __align__(256) __half R2BH[Bn*Tn*Dn];
__device__ __align__(256) __half FBUFH[Bn*Tn*LATENTn];
__device__ __align__(256) __half FOUTH[Bn*Tn*Dn];
__device__ __align__(256) __half WT_IN [Dn*Dn];
__device__ __align__(256) __half WT_OUT[Dn*Dn];
__device__ __align__(256) __half WT_1  [LATENTn*Dn];
__device__ __align__(256) __half WT_2  [Dn*LATENTn];
__device__ float GS_G[Bn*Tn*COUTn];
__device__ float GS_S[Bn*Tn*COUTn];

// ---------------- fused transpose of all 4 weight matrices ----------------
__global__ __launch_bounds__(256) void transpose4(const float* __restrict__ s0, __half* __restrict__ d0p,
                                                  const float* __restrict__ s1, __half* __restrict__ d1p,
                                                  const float* __restrict__ s2, __half* __restrict__ d2p,
                                                  const float* __restrict__ s3, __half* __restrict__ d3p) {
    __shared__ float t[32][33];
    int id = blockIdx.x;
    const float* src; __half* dst; int R, C, bx, by;
    if (id < 256)       { src = s0; dst = d0p; R = Dn;      C = Dn;      bx = id & 15;        by = id >> 4; }
    else if (id < 512)  { id -= 256;  src = s1; dst = d1p; R = Dn;      C = Dn;      bx = id & 15; by = id >> 4; }
    else if (id < 1536) { id -= 512;  src = s2; dst = d2p; R = Dn;      C = LATENTn; bx = id & 63; by = id >> 6; }
    else                { id -= 1536; src = s3; dst = d3p; R = LATENTn; C = Dn;      bx = id & 15; by = id >> 4; }
    int tx = threadIdx.x & 31, ty = threadIdx.x >> 5;
    int c0 = bx*32, r0 = by*32;
#pragma unroll
    for (int i = 0; i < 4; i++)
        t[ty + i*8][tx] = src[(size_t)(r0 + ty + i*8)*C + c0 + tx];
    __syncthreads();
#pragma unroll
    for (int i = 0; i < 4; i++)
        dst[(size_t)(c0 + ty + i*8)*R + r0 + tx] = __float2half(t[tx][ty + i*8]);
}

// ---------------- fused FFT + top-8 + season + res1(half), batch-offset ----------------
__global__ __launch_bounds__(256) void fftseason_kernel(const float* __restrict__ x,
                                                        float* __restrict__ out, int b0) {
    __shared__ float2 data[4][1024];
    __shared__ float2 tw[512];
    __shared__ float  mag[4][512];
    __shared__ int    chm[4][8];
    __shared__ float  chre[4][8], chim[4][8];

    int tid = threadIdx.x;
    int b   = b0 + (blockIdx.x >> 7);
    int d0  = (blockIdx.x & 127) << 2;

    for (int k = tid; k < 512; k += 256) {
        float s, c;
        sincosf(-6.283185307179586f * (float)k / 1024.0f, &s, &c);
        tw[k] = make_float2(c, s);
    }
    const float* xb = x + (size_t)b * Tn * Dn;
    for (int i = tid; i < 4096; i += 256) {
        int t = i >> 2, j = i & 3;
        data[j][t] = make_float2(xb[(size_t)t*Dn + d0 + j], 0.f);
    }
    __syncthreads();

    int tmul = 1;
    for (int half = 512; half >= 1; half >>= 1, tmul <<= 1) {
        for (int i = tid; i < 2048; i += 256) {
            int s  = i >> 9;
            int bf = i & 511;
            int k  = bf & (half - 1);
            int pos = 2*bf - k;
            float2 u = data[s][pos], v = data[s][pos + half];
            data[s][pos] = make_float2(u.x + v.x, u.y + v.y);
            float2 t2 = make_float2(u.x - v.x, u.y - v.y);
            float2 w  = tw[k * tmul];
            data[s][pos + half] = make_float2(t2.x*w.x - t2.y*w.y,
                                              t2.x*w.y + t2.y*w.x);
        }
        __syncthreads();
    }

    for (int i = tid; i < 2048; i += 256) {
        int s = i >> 9, f = i & 511;
        if (f == 0) { mag[s][0] = -1e30f; continue; }
        int j = (int)(__brev((unsigned)f) >> 22);
        float2 v = data[s][j];
        mag[s][f] = v.x*v.x + v.y*v.y;
    }
    __syncthreads();

    int wid = tid >> 5, lane = tid & 31;
    if (wid < 4) {
        int s = wid;
#pragma unroll
        for (int it = 0; it < 8; it++) {
            float bestm = -1e29f; int bestf = 1 << 20;
            for (int f = lane; f < 512; f += 32) {
                float m2 = mag[s][f];
                if (m2 > bestm || (m2 == bestm && f < bestf)) { bestm = m2; bestf = f; }
            }
            for (int off = 16; off; off >>= 1) {
                float om = __shfl_xor_sync(0xffffffffu, bestm, off);
                int   of = __shfl_xor_sync(0xffffffffu, bestf, off);
                if (om > bestm || (om == bestm && of < bestf)) { bestm = om; bestf = of; }
            }
            if (lane == 0) {
                int j = (int)(__brev((unsigned)bestf) >> 22);
                float2 v = data[s][j];
                chm [s][it] = bestf;
                chre[s][it] = v.x * (2.0f / (float)Tn);
                chim[s][it] = v.y * (2.0f / (float)Tn);
                mag[s][bestf] = -1e30f;
            }
            __syncwarp();
        }
    }
    __syncthreads();

    float* ctab = &mag[0][0];
    for (int j = tid; j < 1024; j += 256)
        ctab[j] = (j < 512) ? tw[j].x : -tw[j - 512].x;
    __syncthreads();

    {
        int s = tid & 3;
        int ms[8]; float re[8], im[8];
#pragma unroll
        for (int k = 0; k < 8; k++) { ms[k] = chm[s][k]; re[k] = chre[s][k]; im[k] = chim[s][k]; }
        int d = d0 + s;
        float*       seas = out + OFF_SEASON + (size_t)b*TP*Dn + d;
        const float* rb   = x + (size_t)b*Tn*Dn + d;
        __half*      r1h  = RES1H + (size_t)b*Tn*Dn + d;
        for (int t = tid >> 2; t < TP; t += 64) {
            float acc = 0.f;
#pragma unroll
            for (int k = 0; k < 8; k++) {
                int idx = (ms[k]*t) & 1023;
                acc += re[k]*ctab[idx] - im[k]*ctab[(idx + 768) & 1023];
            }
            seas[(size_t)t*Dn] = acc;
            if (t < Tn)
                r1h[(size_t)t*Dn] = __float2half(rb[(size_t)t*Dn] - acc);
        }
    }
}

// ---------------- fp16 tensor-core GEMM, cp.async 4-stage, 1 barrier/iter ----------------
__device__ __forceinline__ void cp_async16(unsigned saddr, const void* gptr, bool valid) {
    int sz = valid ? 16 : 0;
    asm volatile("cp.async.cg.shared.global [%0], [%1], 16, %2;\n"
                 :: "r"(saddr), "l"(gptr), "r"(sz));
}

__global__ __launch_bounds__(256) void hgemm_kernel(const __half* __restrict__ A,
                                                    const __half* __restrict__ BT,
                                                    float* __restrict__ C,
                                                    __half* __restrict__ CH,
                                                    int M, int N, int K,
                                                    int dogelu, int outhalf) {
    extern __shared__ __half smh[];
    __half* Ash = smh;
    __half* Bsh = smh + STAGESH * STG_HALFS;
    unsigned As_base = (unsigned)__cvta_generic_to_shared(Ash);
    unsigned Bs_base = (unsigned)__cvta_generic_to_shared(Bsh);

    int tid = threadIdx.x;
    int row0 = blockIdx.y * 128, col0 = blockIdx.x * 128;
    int wid = tid >> 5, lane = tid & 31;
    int wm = (wid & 1) * 64, wn = (wid >> 1) * 32;
    int g = lane >> 2, tg = lane & 3;

    float acc[4][4][4];
#pragma unroll
    for (int i = 0; i < 4; i++)
#pragma unroll
        for (int j = 0; j < 4; j++)
#pragma unroll
            for (int q = 0; q < 4; q++) acc[i][j][q] = 0.f;

    const int NT = K / BKH;

    int ch0 = tid, ch1 = tid + 256;
    int ra0 = ch0 >> 2, ca0 = ch0 & 3;
    int ra1 = ch1 >> 2, ca1 = ch1 & 3;
    bool av0 = (row0 + ra0) < M, av1 = (row0 + ra1) < M;
    const __half* ag0 = A + (size_t)(row0 + ra0)*K + ca0*8;
    const __half* ag1 = A + (size_t)(row0 + ra1)*K + ca1*8;
    const __half* bg0 = BT + (size_t)(col0 + ra0)*K + ca0*8;
    const __half* bg1 = BT + (size_t)(col0 + ra1)*K + ca1*8;
    unsigned ad0 = (unsigned)(ra0*APADH + ca0*8)*2, ad1 = (unsigned)(ra1*APADH + ca1*8)*2;

#pragma unroll
    for (int s = 0; s < 3; s++) {
        unsigned ab = As_base + s*STG_HALFS*2, bb = Bs_base + s*STG_HALFS*2;
        int k0 = s * BKH;
        cp_async16(ab + ad0, ag0 + k0, av0);
        cp_async16(ab + ad1, ag1 + k0, av1);
        cp_async16(bb + ad0, bg0 + k0, true);
        cp_async16(bb + ad1, bg1 + k0, true);
        asm volatile("cp.async.commit_group;\n");
    }

    for (int it = 0; it < NT; it++) {
        int ahead = NT - 1 - it;
        if (ahead >= 2)      asm volatile("cp.async.wait_group 2;\n");
        else if (ahead == 1) asm volatile("cp.async.wait_group 1;\n");
        else                 asm volatile("cp.async.wait_group 0;\n");
        __syncthreads();

        if (it + 3 < NT) {
            int s = (it + 3) % STAGESH, k0 = (it + 3) * BKH;
            unsigned ab = As_base + s*STG_HALFS*2, bb = Bs_base + s*STG_HALFS*2;
            cp_async16(ab + ad0, ag0 + k0, av0);
            cp_async16(ab + ad1, ag1 + k0, av1);
            cp_async16(bb + ad0, bg0 + k0, true);
            cp_async16(bb + ad1, bg1 + k0, true);
            asm volatile("cp.async.commit_group;\n");
        }

        const __half* Abuf = Ash + (it % STAGESH) * STG_HALFS;
        const __half* Bbuf = Bsh + (it % STAGESH) * STG_HALFS;

#pragma unroll
        for (int kk = 0; kk < BKH; kk += 16) {
            unsigned af[4][4], bf[4][2];
#pragma unroll
            for (int mt = 0; mt < 4; mt++) {
                int m = wm + mt*16 + g;
                af[mt][0] = *(const unsigned*)(Abuf + (m  )*APADH + kk + 2*tg);
                af[mt][1] = *(const unsigned*)(Abuf + (m+8)*APADH + kk + 2*tg);
                af[mt][2] = *(const unsigned*)(Abuf + (m  )*APADH + kk + 2*tg + 8);
                af[mt][3] = *(const unsigned*)(Abuf + (m+8)*APADH + kk + 2*tg + 8);
            }
#pragma unroll
            for (int nt = 0; nt < 4; nt++) {
                int n = wn + nt*8 + g;
                bf[nt][0] = *(const unsigned*)(Bbuf + n*APADH + kk + 2*tg);
                bf[nt][1] = *(const unsigned*)(Bbuf + n*APADH + kk + 2*tg + 8);
            }
#pragma unroll
            for (int mt = 0; mt < 4; mt++)
#pragma unroll
                for (int nt = 0; nt < 4; nt++)
                    asm volatile(
                        "mma.sync.aligned.m16n8k16.row.col.f32.f16.f16.f32 "
                        "{%0,%1,%2,%3}, {%4,%5,%6,%7}, {%8,%9}, {%0,%1,%2,%3};"
                        : "+f"(acc[mt][nt][0]), "+f"(acc[mt][nt][1]),
                          "+f"(acc[mt][nt][2]), "+f"(acc[mt][nt][3])
                        : "r"(af[mt][0]), "r"(af[mt][1]), "r"(af[mt][2]), "r"(af[mt][3]),
                          "r"(bf[nt][0]), "r"(bf[nt][1]));
        }
    }

#pragma unroll
    for (int mt = 0; mt < 4; mt++) {
#pragma unroll
        for (int nt = 0; nt < 4; nt++) {
            int r0 = row0 + wm + mt*16 + g;
            int c  = col0 + wn + nt*8 + 2*tg;
            float v[4];
#pragma unroll
            for (int q = 0; q < 4; q++) {
                float u = acc[mt][nt][q];
                if (dogelu) u = 0.5f*u*(1.0f + erff(u*0.70710678118654752f));
                v[q] = u;
            }
            if (outhalf) {
                if (r0 < M)
                    *(__half2*)(CH + (size_t)r0*N + c) = __floats2half2_rn(v[0], v[1]);
                if (r0 + 8 < M)
                    *(__half2*)(CH + (size_t)(r0+8)*N + c) = __floats2half2_rn(v[2], v[3]);
            } else {
                if (r0 < M)     *(float2*)(C + (size_t)r0*N + c)     = make_float2(v[0], v[1]);
                if (r0 + 8 < M) *(float2*)(C + (size_t)(r0+8)*N + c) = make_float2(v[2], v[3]);
            }
        }
    }
}

// ---------------- growth EMA: fused blocked scan, half input, batch-offset ----------------
__global__ __launch_bounds__(512) void growth_fused(const float* __restrict__ sw,
                                                    const float* __restrict__ z0,
                                                    const float* __restrict__ v0, int b0) {
    __shared__ float zb[GSEG][33];
    __shared__ float cb[GSEG][33];
    int b  = b0 + (blockIdx.x >> 4);
    int c0 = (blockIdx.x & 15) << 5;
    int seg = threadIdx.x >> 5, ci = threadIdx.x & 31;
    int c = c0 + ci;
    float w = 1.f/(1.f + expf(-sw[c >> 6]));
    float omw = 1.f - w;
    int t0 = seg * GSEGLEN;
    const __half* vp = VBUFH + (size_t)b*Tn*Dn + c;

    float dv[GSEGLEN];
    float prev = (t0 == 0) ? z0[c] : __half2float(vp[(size_t)(t0-1)*Dn]);
    float z = 0.f;
#pragma unroll
    for (int l = 0; l < GSEGLEN; l++) {
        float v = __half2float(vp[(size_t)(t0+l)*Dn]);
        dv[l] = v - prev;
        prev = v;
        z = w*z + dv[l];
    }
    zb[seg][ci] = z;
    __syncthreads();

    if (threadIdx.x < 32) {
        int cc = threadIdx.x;
        float wj = 1.f/(1.f + expf(-sw[(c0 + cc) >> 6]));
        float w64 = 1.f;
        { float p = wj; int e = GSEGLEN; while (e) { if (e & 1) w64 *= p; p *= p; e >>= 1; } }
        float y = v0[c0 + cc];
        float omwj = 1.f - wj;
#pragma unroll
        for (int s = 0; s < GSEG; s++) {
            cb[s][cc] = y;
            y = w64*y + omwj*zb[s][cc];
        }
    }
    __syncthreads();

    __half* gp = GBUFH + (size_t)b*T1*Dn + c;
    float y = cb[seg][ci];
    if (seg == 0) gp[0] = __float2half(v0[c]);
#pragma unroll
    for (int l = 0; l < GSEGLEN; l++) {
        y = w*y + omw*dv[l];
        gp[(size_t)(t0+l+1)*Dn] = __float2half(y);
    }
}

// ---------------- layernorm helpers ----------------
__device__ __forceinline__ float block_reduce_sum(float v, float* red) {
    for (int o = 16; o; o >>= 1) v += __shfl_xor_sync(0xffffffffu, v, o);
    int wid = threadIdx.x >> 5;
    if ((threadIdx.x & 31) == 0) red[wid] = v;
    __syncthreads();
    if (threadIdx.x < 32) {
        float s = (threadIdx.x < 4) ? red[threadIdx.x] : 0.f;
        for (int o = 2; o; o >>= 1) s += __shfl_xor_sync(0xffffffffu, s, o);
        if (threadIdx.x == 0) red[0] = s;
    }
    __syncthreads();
    float r = red[0];
    __syncthreads();
    return r;
}

__global__ __launch_bounds__(128) void res2_kernel(const float* __restrict__ out_all,
                                                   const float* __restrict__ ng,
                                                   const float* __restrict__ nb, int r0off) {
    __shared__ float red[32];
    int r = r0off + blockIdx.x;
    int b = r >> 10, t = r & 1023;
    const __half* x1 = RES1H + (size_t)r*Dn;
    const float*  gw = out_all + OFF_GROWTH + (size_t)(b*T1 + t + 1)*Dn;
    float vals[4]; float s = 0.f;
#pragma unroll
    for (int i = 0; i < 4; i++) {
        int d = threadIdx.x + i*128;
        vals[i] = __half2float(x1[d]) - gw[d];
        s += vals[i];
    }
    float mu = block_reduce_sum(s, red) * (1.0f/512.0f);
    float vs = 0.f;
#pragma unroll
    for (int i = 0; i < 4; i++) { float c = vals[i]-mu; vs += c*c; }
    float var = block_reduce_sum(vs, red) * (1.0f/512.0f);
    float inv = rsqrtf(var + 1e-5f);
#pragma unroll
    for (int i = 0; i < 4; i++) {
        int d = threadIdx.x + i*128;
        R2BH[(size_t)r*Dn + d] = __float2half((vals[i]-mu)*inv*ng[d] + nb[d]);
    }
}

__global__ __launch_bounds__(128) void res3_kernel(float* __restrict__ out_all,
                                                   const float* __restrict__ ng,
                                                   const float* __restrict__ nb, int r0off) {
    __shared__ float red[32];
    int r = r0off + blockIdx.x;
    float vals[4]; float s = 0.f;
#pragma unroll
    for (int i = 0; i < 4; i++) {
        int d = threadIdx.x + i*128;
        vals[i] = __half2float(R2BH[(size_t)r*Dn + d]) +
                  __half2float(FOUTH[(size_t)r*Dn + d]);
        s += vals[i];
    }
    float mu = block_reduce_sum(s, red) * (1.0f/512.0f);
    float vs = 0.f;
#pragma unroll
    for (int i = 0; i < 4; i++) { float c = vals[i]-mu; vs += c*c; }
    float var = block_reduce_sum(vs, red) * (1.0f/512.0f);
    float inv = rsqrtf(var + 1e-5f);
#pragma unroll
    for (int i = 0; i < 4; i++) {
        int d = threadIdx.x + i*128;
        out_all[OFF_RES3 + (size_t)r*Dn + d] = (vals[i]-mu)*inv*ng[d] + nb[d];
    }
}

// ---------------- level projections, batch-offset ----------------
__global__ __launch_bounds__(256) void levelproj_kernel(const float* __restrict__ out_all,
                                                        const float* __restrict__ gpw,
                                                        const float* __restrict__ spw, int b0) {
    int lwarp = (blockIdx.x*256 + threadIdx.x) >> 5;
    int lane = threadIdx.x & 31;
    if (lwarp >= NBH*Tn) return;
    int warp = b0*Tn + lwarp;
    int b = warp >> 10, t = warp & 1023;
    const float* gr = out_all + OFF_GROWTH + (size_t)(b*T1 + t)*Dn;
    const float* se = out_all + OFF_SEASON + (size_t)(b*TP + t)*Dn;
    float ag[7] = {}, as_[7] = {};
    for (int d = lane; d < 512; d += 32) {
        float g = gr[d], s = se[d];
#pragma unroll
        for (int c = 0; c < 7; c++) { ag[c] += g*gpw[d*7+c]; as_[c] += s*spw[d*7+c]; }
    }
#pragma unroll
    for (int c = 0; c < 7; c++) {
        for (int o = 16; o; o >>= 1) {
            ag[c]  += __shfl_xor_sync(0xffffffffu, ag[c],  o);
            as_[c] += __shfl_xor_sync(0xffffffffu, as_[c], o);
        }
    }
    if (lane == 0) {
#pragma unroll
        for (int c = 0; c < 7; c++) {
            GS_G[(size_t)warp*7 + c] = ag[c];
            GS_S[(size_t)warp*7 + c] = as_[c];
        }
    }
}

// ---------------- level EMA: fused blocked scan, batch-offset (56 ch/half) ----------------
__global__ __launch_bounds__(256) void level_fused(const float* __restrict__ level,
                                                   const float* __restrict__ lsw,
                                                   const float* __restrict__ lv0,
                                                   float* __restrict__ out_all, int b0) {
    __shared__ float zb[GSEG][17];
    __shared__ float cb[GSEG][17];
    int seg = threadIdx.x >> 4, ci = threadIdx.x & 15;
    int lch = blockIdx.x * 16 + ci;
    bool valid = (lch < NBH*COUTn);
    int lchc = valid ? lch : 0;
    int ch = b0*COUTn + lchc;
    int b = ch / COUTn, c = ch % COUTn;
    float w = 1.f/(1.f + expf(-lsw[c]));
    float omw = 1.f - w;
    int t0 = seg * GSEGLEN;
    const float* lp = level + (size_t)b*Tn*COUTn + c;
    const float* gp = GS_G  + (size_t)b*Tn*COUTn + c;
    const float* sp = GS_S  + (size_t)b*Tn*COUTn + c;

    float uv[GSEGLEN];
    float z = 0.f;
#pragma unroll
    for (int l = 0; l < GSEGLEN; l++) {
        int t = t0 + l;
        uv[l] = omw*(lp[t*COUTn] - sp[t*COUTn]) + w*gp[t*COUTn];
        z = w*z + uv[l];
    }
    zb[seg][ci] = z;
    __syncthreads();

    if (threadIdx.x < 16) {
        int cc = threadIdx.x;
        int lch2 = blockIdx.x * 16 + cc;
        int lch2c = (lch2 < NBH*COUTn) ? lch2 : 0;
        int ch2 = b0*COUTn + lch2c;
        float wj = 1.f/(1.f + expf(-lsw[ch2 % COUTn]));
        float w64 = 1.f;
        { float p = wj; int e = GSEGLEN; while (e) { if (e & 1) w64 *= p; p *= p; e >>= 1; } }
        float y = lv0[ch2 % COUTn];
#pragma unroll
        for (int s = 0; s < GSEG; s++) {
            cb[s][cc] = y;
            y = w64*y + zb[s][cc];
        }
    }
    __syncthreads();

    if (valid) {
        float* op = out_all + OFF_LEVEL + (size_t)b*Tn*COUTn + c;
        float y = cb[seg][ci];
#pragma unroll
        for (int l = 0; l < GSEGLEN; l++) {
            y = w*y + uv[l];
            op[(t0+l)*COUTn] = y;
        }
    }
}

// ---------------- launch ----------------
extern "C" void kernel_launch(void* const* d_in, const int* in_sizes, int n_in,
                              void* d_out, int out_size) {
    const float* res      = (const float*)d_in[0];
    const float* level    = (const float*)d_in[1];
    const float* in_w     = (const float*)d_in[2];
    const float* out_w    = (const float*)d_in[3];
    const float* z0       = (const float*)d_in[4];
    const float* gsw      = (const float*)d_in[5];
    const float* gv0      = (const float*)d_in[6];
    const float* ff_w1    = (const float*)d_in[7];
    const float* ff_w2    = (const float*)d_in[8];
    const float* n1g      = (const float*)d_in[9];
    const float* n1b      = (const float*)d_in[10];
    const float* n2g      = (const float*)d_in[11];
    const float* n2b      = (const float*)d_in[12];
    const float* gpw      = (const float*)d_in[13];
    const float* spw      = (const float*)d_in[14];
    const float* lsw      = (const float*)d_in[15];
    const float* lv0      = (const float*)d_in[16];
    float* out = (float*)d_out;

    __half *pRES1H, *pVBUFH, *pGBUFH, *pR2H, *pFBUFH, *pFOUTH, *pWTIN, *pWTOUT, *pWT1, *pWT2;
    cudaGetSymbolAddress((void**)&pRES1H, RES1H);
    cudaGetSymbolAddress((void**)&pVBUFH, VBUFH);
    cudaGetSymbolAddress((void**)&pGBUFH, GBUFH);
    cudaGetSymbolAddress((void**)&pR2H,   R2BH);
    cudaGetSymbolAddress((void**)&pFBUFH, FBUFH);
    cudaGetSymbolAddress((void**)&pFOUTH, FOUTH);
    cudaGetSymbolAddress((void**)&pWTIN,  WT_IN);
    cudaGetSymbolAddress((void**)&pWTOUT, WT_OUT);
    cudaGetSymbolAddress((void**)&pWT1,   WT_1);
    cudaGetSymbolAddress((void**)&pWT2,   WT_2);

    static int init_done = 0;
    static cudaStream_t s2, s3;
    static cudaEvent_t evA, evB, evC0, evC1, evL, evE;
    if (!init_done) {
        cudaFuncSetAttribute(hgemm_kernel,
                             cudaFuncAttributeMaxDynamicSharedMemorySize, HS_TOTAL);
        cudaStreamCreateWithFlags(&s2, cudaStreamNonBlocking);
        cudaStreamCreateWithFlags(&s3, cudaStreamNonBlocking);
        cudaEventCreateWithFlags(&evA,  cudaEventDisableTiming);
        cudaEventCreateWithFlags(&evB,  cudaEventDisableTiming);
        cudaEventCreateWithFlags(&evC0, cudaEventDisableTiming);
        cudaEventCreateWithFlags(&evC1, cudaEventDisableTiming);
        cudaEventCreateWithFlags(&evL,  cudaEventDisableTiming);
        cudaEventCreateWithFlags(&evE,  cudaEventDisableTiming);
        init_done = 1;
    }

    const int MH  = NBH*Tn;    // 8192 rows per half
    const int MH2 = NBH*T1;    // 8200 rows per half (growth)
    const size_t o1h = (size_t)NBH*Tn*Dn;        // row offset (elems) for half1 D-wide bufs
    const size_t o2h = (size_t)NBH*T1*Dn;
    const size_t o3h = (size_t)NBH*Tn*LATENTn;

    // origin fork
    cudaEventRecord(evA, 0);
    cudaStreamWaitEvent(s2, evA, 0);
    cudaStreamWaitEvent(s3, evA, 0);

    // weights on s2
    transpose4<<<2560, 256, 0, s2>>>(in_w, pWTIN, out_w, pWTOUT, ff_w1, pWT1, ff_w2, pWT2);
    cudaEventRecord(evB, s2);

    // fft for both halves (independent of weights)
    fftseason_kernel<<<NBH*128, 256, 0, 0>>>(res, out, 0);
    fftseason_kernel<<<NBH*128, 256, 0, s3>>>(res, out, NBH);

    // both halves need weights before GEMM1
    cudaStreamWaitEvent(0,  evB, 0);
    cudaStreamWaitEvent(s3, evB, 0);

    // ---- half 0 on stream 0 ----
    hgemm_kernel<<<dim3(Dn/128, MH/128), 256, HS_TOTAL, 0>>>(pRES1H, pWTIN, 0, pVBUFH,
                                                             MH, Dn, Dn, 0, 1);
    growth_fused<<<NBH*16, 512, 0, 0>>>(gsw, z0, gv0, 0);
    hgemm_kernel<<<dim3(Dn/128, (MH2+127)/128), 256, HS_TOTAL, 0>>>(pGBUFH, pWTOUT,
                                                                    out + OFF_GROWTH, 0,
                                                                    MH2, Dn, Dn, 0, 0);
    cudaEventRecord(evC0, 0);
    res2_kernel<<<MH, 128, 0, 0>>>(out, n1g, n1b, 0);
    hgemm_kernel<<<dim3(LATENTn/128, MH/128), 256, HS_TOTAL, 0>>>(pR2H, pWT1, 0, pFBUFH,
                                                                  MH, LATENTn, Dn, 1, 1);
    hgemm_kernel<<<dim3(Dn/128, MH/128), 256, HS_TOTAL, 0>>>(pFBUFH, pWT2, 0, pFOUTH,
                                                             MH, Dn, LATENTn, 0, 1);
    res3_kernel<<<MH, 128, 0, 0>>>(out, n2g, n2b, 0);

    // ---- half 1 on s3 ----
    hgemm_kernel<<<dim3(Dn/128, MH/128), 256, HS_TOTAL, s3>>>(pRES1H + o1h, pWTIN,
                                                              0, pVBUFH + o1h,
                                                              MH, Dn, Dn, 0, 1);
    growth_fused<<<NBH*16, 512, 0, s3>>>(gsw, z0, gv0, NBH);
    hgemm_kernel<<<dim3(Dn/128, (MH2+127)/128), 256, HS_TOTAL, s3>>>(pGBUFH + o2h, pWTOUT,
                                                                     out + OFF_GROWTH + o2h, 0,
                                                                     MH2, Dn, Dn, 0, 0);
    cudaEventRecord(evC1, s3);
    res2_kernel<<<MH, 128, 0, s3>>>(out, n1g, n1b, MH);
    hgemm_kernel<<<dim3(LATENTn/128, MH/128), 256, HS_TOTAL, s3>>>(pR2H + o1h, pWT1,
                                                                   0, pFBUFH + o3h,
                                                                   MH, LATENTn, Dn, 1, 1);
    hgemm_kernel<<<dim3(Dn/128, MH/128), 256, HS_TOTAL, s3>>>(pFBUFH + o3h, pWT2,
                                                              0, pFOUTH + o1h,
                                                              MH, Dn, LATENTn, 0, 1);
    res3_kernel<<<MH, 128, 0, s3>>>(out, n2g, n2b, MH);
    cudaEventRecord(evE, s3);

    // ---- level paths on s2 (after each half's growth) ----
    cudaStreamWaitEvent(s2, evC0, 0);
    levelproj_kernel<<<(NBH*Tn*32)/256, 256, 0, s2>>>(out, gpw, spw, 0);
    level_fused<<<(NBH*COUTn + 15)/16, 256, 0, s2>>>(level, lsw, lv0, out, 0);
    cudaStreamWaitEvent(s2, evC1, 0);
    levelproj_kernel<<<(NBH*Tn*32)/256, 256, 0, s2>>>(out, gpw, spw, NBH);
    level_fused<<<(NBH*COUTn + 15)/16, 256, 0, s2>>>(level, lsw, lv0, out, NBH);
    cudaEventRecord(evL, s2);

    // join everything on stream 0
    cudaStreamWaitEvent(0, evE, 0);
    cudaStreamWaitEvent(0, evL, 0);
}